// round 9
// baseline (speedup 1.0000x reference)
#include <cuda_runtime.h>
#include <cuda_bf16.h>
#include <cstdint>
#include <cstddef>

#define N_NODES 50000
#define N_EDGES 800000
#define N_GRAPHS 64
#define IN_C 256
#define HID 256
#define HID2 128
#define N_DCS 64

// ---------------- static device scratch ----------------
__device__ float g_h1[(size_t)N_NODES * HID];
__device__ float g_bx[(size_t)N_NODES * HID];
__device__ float g_h2[(size_t)N_NODES * HID2];
__device__ float g_cx[(size_t)N_NODES * HID2];
__device__ __nv_bfloat16 g_w1h[HID * IN_C];
__device__ __nv_bfloat16 g_w1l[HID * IN_C];
__device__ __nv_bfloat16 g_w2h[HID2 * HID];
__device__ __nv_bfloat16 g_w2l[HID2 * HID];
__device__ float g_dis[N_NODES];
__device__ int   g_deg[N_NODES];
__device__ int   g_off[N_NODES + 1];
__device__ int   g_pos[N_NODES];
__device__ int   g_csr[N_EDGES];
__device__ int   g_bsum[64];
__device__ int   g_boff[64];
__device__ int   g_gs[N_GRAPHS + 1];
__device__ float g_px[N_GRAPHS * HID2];

// ---------------- helpers ----------------
__device__ __forceinline__ uint32_t smem_u32(const void* p) {
    uint32_t a;
    asm("{ .reg .u64 t; cvta.to.shared.u64 t, %1; cvt.u32.u64 %0, t; }" : "=r"(a) : "l"(p));
    return a;
}
#define SWZ(o) ((uint32_t)(o) ^ ((((uint32_t)(o)) >> 3) & 0x70u))

#define MMA_BF16(d, a, b) \
    asm volatile("mma.sync.aligned.m16n8k16.row.col.f32.bf16.bf16.f32 " \
        "{%0,%1,%2,%3}, {%4,%5,%6,%7}, {%8,%9}, {%0,%1,%2,%3};" \
        : "+f"((d)[0]), "+f"((d)[1]), "+f"((d)[2]), "+f"((d)[3]) \
        : "r"((a)[0]), "r"((a)[1]), "r"((a)[2]), "r"((a)[3]), \
          "r"((b)[0]), "r"((b)[1]))

#define LDSM4(r, addr) \
    asm volatile("ldmatrix.sync.aligned.m8n8.x4.shared.b16 {%0,%1,%2,%3}, [%4];" \
        : "=r"((r)[0]), "=r"((r)[1]), "=r"((r)[2]), "=r"((r)[3]) : "r"(addr))

#define CPASYNC16(dst, src) \
    asm volatile("cp.async.cg.shared.global [%0], [%1], 16;" :: "r"(dst), "l"(src))
#define CPCOMMIT() asm volatile("cp.async.commit_group;" ::: "memory")
#define CPWAIT0()  asm volatile("cp.async.wait_group 0;" ::: "memory")

__device__ __forceinline__ void split2(float f0, float f1, uint32_t& h, uint32_t& l) {
    __nv_bfloat162 hp = __floats2bfloat162_rn(f0, f1);
    float2 hf = __bfloat1622float2(hp);
    __nv_bfloat162 lp = __floats2bfloat162_rn(f0 - hf.x, f1 - hf.y);
    h = *reinterpret_cast<uint32_t*>(&hp);
    l = *reinterpret_cast<uint32_t*>(&lp);
}

// ---------------- fused prep: zero g_deg + pack W1/W2 transposed bf16 hi/lo ----------------
#define ZB ((N_NODES + 255) / 256)
__global__ void prep_kernel(const float* __restrict__ W1, const float* __restrict__ W2) {
    int b = blockIdx.x;
    int t = threadIdx.x;                 // 256
    if (b < ZB) {
        int i = b * 256 + t;
        if (i < N_NODES) g_deg[i] = 0;
    } else if (b < ZB + HID) {
        int n = b - ZB;
        float v = W1[(size_t)t * HID + n];
        __nv_bfloat16 h = __float2bfloat16(v);
        g_w1h[(size_t)n * 256 + t] = h;
        g_w1l[(size_t)n * 256 + t] = __float2bfloat16(v - __bfloat162float(h));
    } else {
        int n = b - ZB - HID;
        float v = W2[(size_t)t * HID2 + n];
        __nv_bfloat16 h = __float2bfloat16(v);
        g_w2h[(size_t)n * 256 + t] = h;
        g_w2l[(size_t)n * 256 + t] = __float2bfloat16(v - __bfloat162float(h));
    }
}

__global__ void hist_kernel(const int* __restrict__ dst, int e) {
    int i = blockIdx.x * blockDim.x + threadIdx.x;
    if (i < e) atomicAdd(&g_deg[dst[i]], 1);
}
__global__ void dis_kernel(int n) {
    int i = blockIdx.x * blockDim.x + threadIdx.x;
    if (i < n) g_dis[i] = rsqrtf((float)g_deg[i] + 1.0f);
}
__global__ void scan_block_kernel(int n) {
    __shared__ int sh[1024];
    int tid = threadIdx.x;
    int i = blockIdx.x * 1024 + tid;
    int v = (i < n) ? g_deg[i] : 0;
    sh[tid] = v;
    __syncthreads();
    #pragma unroll
    for (int s = 1; s < 1024; s <<= 1) {
        int t = (tid >= s) ? sh[tid - s] : 0;
        __syncthreads();
        sh[tid] += t;
        __syncthreads();
    }
    if (i < n) g_off[i] = sh[tid] - v;
    if (tid == 1023) g_bsum[blockIdx.x] = sh[1023];
}
__global__ void scan_sums_kernel(int nb, int n) {
    __shared__ int sh[64];
    int tid = threadIdx.x;
    int v = (tid < nb) ? g_bsum[tid] : 0;
    sh[tid] = v;
    __syncthreads();
    #pragma unroll
    for (int s = 1; s < 64; s <<= 1) {
        int t = (tid >= s) ? sh[tid - s] : 0;
        __syncthreads();
        sh[tid] += t;
        __syncthreads();
    }
    if (tid < nb) g_boff[tid] = sh[tid] - v;
    if (tid == nb - 1) g_off[n] = sh[tid];
}
__global__ void scan_add_kernel(int n) {
    int i = blockIdx.x * blockDim.x + threadIdx.x;
    if (i < n) {
        int o = g_off[i] + g_boff[i >> 10];
        g_off[i] = o;
        g_pos[i] = o;
    }
}
__global__ void scatter_kernel(const int* __restrict__ src, const int* __restrict__ dst, int e) {
    int i = blockIdx.x * blockDim.x + threadIdx.x;
    if (i < e) {
        int d = dst[i];
        int p = atomicAdd(&g_pos[d], 1);
        g_csr[p] = src[i];
    }
}
__global__ void bounds_kernel(const int* __restrict__ batch, int n) {
    int i = blockIdx.x * blockDim.x + threadIdx.x;
    if (i == 0) g_gs[N_GRAPHS] = n;
    if (i < n) {
        if (i == 0 || batch[i] != batch[i - 1]) g_gs[batch[i]] = i;
    }
}

// ================ pipelined HMMA bf16x3 GEMM: C[r][c] = (A[r,:]@B[c,:]^T) * g_dis[r] ================
// A fp32 [M,256] row-major, split to bf16 hi/lo in-kernel (register prefetch, STS at boundary).
// B = Bh+Bl bf16 [NTOT,256] row-major (weights, cp.async). Double-buffered SMEM, 1 CTA/SM.
// CTA tile 128x128, K=256 in 4 chunks of 64. 8 warps (2x4), warp tile 64x32, ldmatrix fragments.
template <int NTOT>
__global__ __launch_bounds__(256, 1) void mma_gemm_kernel(
    const float* __restrict__ A,
    const __nv_bfloat16* __restrict__ Bh, const __nv_bfloat16* __restrict__ Bl,
    float* __restrict__ C, int M)
{
    constexpr int K = 256;
    constexpr int TERM = 16384;            // 128 rows x 128 bytes
    constexpr int BUF = 4 * TERM;          // Ah,Al,Bh,Bl per buffer
    extern __shared__ char sm[];
    const uint32_t sb = smem_u32(sm);

    const int tid = threadIdx.x;
    const int wid = tid >> 5;
    const int lane = tid & 31;
    const int wm = wid >> 2;               // 0..1
    const int wn = wid & 3;                // 0..3
    const int m0 = blockIdx.x * 128;
    const int n0 = blockIdx.y * 128;

    // ldmatrix per-lane base byte offsets (within a term tile)
    uint32_t abase[4], bbase[2];
    {
        int arow = (lane & 7) + ((lane >> 3) & 1) * 8;
        int akb  = (lane >> 4) * 16;
        #pragma unroll
        for (int mi = 0; mi < 4; mi++)
            abase[mi] = (uint32_t)(wm * 64 + mi * 16 + arow) * 128 + akb;
        int brow = (lane & 7) + (lane >> 4) * 8;
        int bkb  = ((lane >> 3) & 1) * 16;
        #pragma unroll
        for (int p = 0; p < 2; p++)
            bbase[p] = (uint32_t)(wn * 32 + p * 16 + brow) * 128 + bkb;
    }

    float acc[4][4][4];
    #pragma unroll
    for (int i = 0; i < 4; i++)
        #pragma unroll
        for (int j = 0; j < 4; j++)
            #pragma unroll
            for (int q = 0; q < 4; q++) acc[i][j][q] = 0.f;

    // A register prefetch: thread covers row = tid/2, elements [(tid&1)*32, +32)
    const int arow_ld = tid >> 1;
    const int au = (tid & 1) * 4;                      // 16B-slot base within row
    const bool aok = (m0 + arow_ld) < M;
    const float* aptr = A + (size_t)(m0 + arow_ld) * K + au * 8;
    float4 pf[8];

    auto prefA = [&](int c) {
        #pragma unroll
        for (int i = 0; i < 4; i++) {
            if (aok) {
                pf[2 * i]     = *(const float4*)(aptr + c * 64 + i * 8);
                pf[2 * i + 1] = *(const float4*)(aptr + c * 64 + i * 8 + 4);
            } else {
                pf[2 * i] = pf[2 * i + 1] = make_float4(0.f, 0.f, 0.f, 0.f);
            }
        }
    };
    auto storeA = [&](int b) {
        char* dst = sm + b * BUF;
        #pragma unroll
        for (int i = 0; i < 4; i++) {
            uint4 hv, lv;
            split2(pf[2 * i].x,     pf[2 * i].y,     hv.x, lv.x);
            split2(pf[2 * i].z,     pf[2 * i].w,     hv.y, lv.y);
            split2(pf[2 * i + 1].x, pf[2 * i + 1].y, hv.z, lv.z);
            split2(pf[2 * i + 1].z, pf[2 * i + 1].w, hv.w, lv.w);
            uint32_t so = SWZ((uint32_t)(arow_ld * 128 + (au + i) * 16));
            *(uint4*)(dst + so)        = hv;
            *(uint4*)(dst + TERM + so) = lv;
        }
    };
    auto cpB = [&](int c, int b) {
        uint32_t d = sb + b * BUF;
        #pragma unroll
        for (int i = 0; i < 4; i++) {
            int v = tid + 256 * i;
            int row = v >> 3, u = v & 7;
            uint32_t so = SWZ((uint32_t)(row * 128 + u * 16));
            size_t gi = (size_t)(n0 + row) * K + c * 64 + u * 8;
            CPASYNC16(d + 2 * TERM + so, Bh + gi);
            CPASYNC16(d + 3 * TERM + so, Bl + gi);
        }
    };
    auto compute = [&](int b) {
        uint32_t sAh = sb + b * BUF;
        uint32_t sAl = sAh + TERM;
        uint32_t sBH = sAh + 2 * TERM;
        uint32_t sBL = sAh + 3 * TERM;
        #pragma unroll
        for (int ks = 0; ks < 4; ks++) {
            const uint32_t ko = (uint32_t)(ks * 32);
            uint32_t bh[8], bl[8], af[16];
            LDSM4(&bh[0], sBH + SWZ(bbase[0] + ko));
            LDSM4(&bh[4], sBH + SWZ(bbase[1] + ko));
            LDSM4(&bl[0], sBL + SWZ(bbase[0] + ko));
            LDSM4(&bl[4], sBL + SWZ(bbase[1] + ko));
            #pragma unroll
            for (int mi = 0; mi < 4; mi++)
                LDSM4(&af[mi * 4], sAh + SWZ(abase[mi] + ko));
            #pragma unroll
            for (int mi = 0; mi < 4; mi++)
                #pragma unroll
                for (int ni = 0; ni < 4; ni++)
                    MMA_BF16(acc[mi][ni], &af[mi * 4], &bh[ni * 2]);
            #pragma unroll
            for (int mi = 0; mi < 4; mi++)
                #pragma unroll
                for (int ni = 0; ni < 4; ni++)
                    MMA_BF16(acc[mi][ni], &af[mi * 4], &bl[ni * 2]);
            #pragma unroll
            for (int mi = 0; mi < 4; mi++)
                LDSM4(&af[mi * 4], sAl + SWZ(abase[mi] + ko));
            #pragma unroll
            for (int mi = 0; mi < 4; mi++)
                #pragma unroll
                for (int ni = 0; ni < 4; ni++)
                    MMA_BF16(acc[mi][ni], &af[mi * 4], &bh[ni * 2]);
        }
    };

    // prologue: fill buffer 0 with chunk 0
    prefA(0);
    cpB(0, 0);
    CPCOMMIT();
    storeA(0);
    CPWAIT0();
    __syncthreads();

    #pragma unroll
    for (int c = 0; c < 4; c++) {
        int nb = (c + 1) & 1;
        if (c < 3) {
            cpB(c + 1, nb);
            CPCOMMIT();
            prefA(c + 1);
        }
        compute(c & 1);
        if (c < 3) {
            storeA(nb);
            CPWAIT0();
        }
        __syncthreads();
    }

    // epilogue: scale by dis[row] and store
    const int g = lane >> 2;
    const int t = lane & 3;
    #pragma unroll
    for (int mi = 0; mi < 4; mi++) {
        int r0 = m0 + wm * 64 + mi * 16 + g;
        int r1 = r0 + 8;
        float s0 = (r0 < M) ? g_dis[r0] : 0.f;
        float s1 = (r1 < M) ? g_dis[r1] : 0.f;
        #pragma unroll
        for (int ni = 0; ni < 4; ni++) {
            int col = n0 + wn * 32 + ni * 8 + t * 2;
            if (r0 < M)
                *(float2*)(C + (size_t)r0 * NTOT + col) =
                    make_float2(acc[mi][ni][0] * s0, acc[mi][ni][1] * s0);
            if (r1 < M)
                *(float2*)(C + (size_t)r1 * NTOT + col) =
                    make_float2(acc[mi][ni][2] * s1, acc[mi][ni][3] * s1);
        }
    }
}

// ---------------- gather aggregation: out = relu(dis[n]*(self+sum) + bias), float4, MLP=4 ----------------
template <int C4>
__global__ __launch_bounds__(128) void agg_kernel(
    const float* __restrict__ hs_, const float* __restrict__ bias_,
    float* __restrict__ out_, int N)
{
    constexpr int NPB = 128 / C4;
    int node = blockIdx.x * NPB + threadIdx.x / C4;
    int c = threadIdx.x % C4;
    if (node >= N) return;
    const float4* hs = (const float4*)hs_;
    float dn = g_dis[node];
    int s0 = g_off[node], s1 = g_off[node + 1];
    float4 a0 = hs[(size_t)node * C4 + c];     // self-loop (already *dis[node])
    float4 a1 = make_float4(0.f, 0.f, 0.f, 0.f);
    float4 a2 = make_float4(0.f, 0.f, 0.f, 0.f);
    float4 a3 = make_float4(0.f, 0.f, 0.f, 0.f);
    int j = s0;
    for (; j + 3 < s1; j += 4) {
        int i0 = g_csr[j], i1 = g_csr[j + 1], i2 = g_csr[j + 2], i3 = g_csr[j + 3];
        float4 v0 = hs[(size_t)i0 * C4 + c];
        float4 v1 = hs[(size_t)i1 * C4 + c];
        float4 v2 = hs[(size_t)i2 * C4 + c];
        float4 v3 = hs[(size_t)i3 * C4 + c];
        a0.x += v0.x; a0.y += v0.y; a0.z += v0.z; a0.w += v0.w;
        a1.x += v1.x; a1.y += v1.y; a1.z += v1.z; a1.w += v1.w;
        a2.x += v2.x; a2.y += v2.y; a2.z += v2.z; a2.w += v2.w;
        a3.x += v3.x; a3.y += v3.y; a3.z += v3.z; a3.w += v3.w;
    }
    for (; j < s1; j++) {
        float4 v = hs[(size_t)g_csr[j] * C4 + c];
        a0.x += v.x; a0.y += v.y; a0.z += v.z; a0.w += v.w;
    }
    float4 bv = ((const float4*)bias_)[c];
    float4 r;
    r.x = fmaxf(fmaf(a0.x + a1.x + a2.x + a3.x, dn, bv.x), 0.f);
    r.y = fmaxf(fmaf(a0.y + a1.y + a2.y + a3.y, dn, bv.y), 0.f);
    r.z = fmaxf(fmaf(a0.z + a1.z + a2.z + a3.z, dn, bv.z), 0.f);
    r.w = fmaxf(fmaf(a0.w + a1.w + a2.w + a3.w, dn, bv.w), 0.f);
    ((float4*)out_)[(size_t)node * C4 + c] = r;
}

// ---------------- global max pool per graph ----------------
__global__ void pool_kernel() {
    int g = blockIdx.x;
    int c = threadIdx.x;          // 0..127
    int a = g_gs[g], b = g_gs[g + 1];
    float m = -3.402823466e38f;
    int n = a;
    for (; n + 3 < b; n += 4) {
        float v0 = g_cx[(size_t)(n + 0) * HID2 + c];
        float v1 = g_cx[(size_t)(n + 1) * HID2 + c];
        float v2 = g_cx[(size_t)(n + 2) * HID2 + c];
        float v3 = g_cx[(size_t)(n + 3) * HID2 + c];
        m = fmaxf(m, fmaxf(fmaxf(v0, v1), fmaxf(v2, v3)));
    }
    for (; n < b; n++) m = fmaxf(m, g_cx[(size_t)n * HID2 + c]);
    g_px[g * HID2 + c] = m;
}

// ---------------- head ----------------
__global__ void head_kernel(const float* __restrict__ Wm, const float* __restrict__ bm,
                            float* __restrict__ out)
{
    int g = blockIdx.x;
    int d = threadIdx.x;          // 0..63
    float acc = bm[d];
    #pragma unroll 8
    for (int k = 0; k < HID2; k++)
        acc = fmaf(g_px[g * HID2 + k], Wm[k * N_DCS + d], acc);
    out[g * N_DCS + d] = acc;
}

// ---------------- launch ----------------
extern "C" void kernel_launch(void* const* d_in, const int* in_sizes, int n_in,
                              void* d_out, int out_size)
{
    const float* x     = (const float*)d_in[0];
    const int*   ei    = (const int*)  d_in[1];
    const int*   batch = (const int*)  d_in[2];
    const float* W1    = (const float*)d_in[3];
    const float* b1    = (const float*)d_in[4];
    const float* W2    = (const float*)d_in[5];
    const float* b2    = (const float*)d_in[6];
    const float* Wm    = (const float*)d_in[7];
    const float* bm    = (const float*)d_in[8];
    float* out = (float*)d_out;

    const int N = in_sizes[2];          // 50000
    const int E = in_sizes[1] / 2;      // 800000
    const int* src = ei;
    const int* dst = ei + E;

    float *h1, *bx, *h2, *cx;
    __nv_bfloat16 *w1h, *w1l, *w2h, *w2l;
    cudaGetSymbolAddress((void**)&h1, g_h1);
    cudaGetSymbolAddress((void**)&bx, g_bx);
    cudaGetSymbolAddress((void**)&h2, g_h2);
    cudaGetSymbolAddress((void**)&cx, g_cx);
    cudaGetSymbolAddress((void**)&w1h, g_w1h);
    cudaGetSymbolAddress((void**)&w1l, g_w1l);
    cudaGetSymbolAddress((void**)&w2h, g_w2h);
    cudaGetSymbolAddress((void**)&w2l, g_w2l);

    const int TB = 256;
    int gn = (N + TB - 1) / TB;
    int ge = (E + TB - 1) / TB;
    int nb = (N + 1023) / 1024;

    const int SMEM = 2 * 4 * 16384;     // 131072 bytes (double-buffered)
    int mtiles = (N + 127) / 128;
    cudaFuncSetAttribute(mma_gemm_kernel<HID>,
                         cudaFuncAttributeMaxDynamicSharedMemorySize, SMEM);
    cudaFuncSetAttribute(mma_gemm_kernel<HID2>,
                         cudaFuncAttributeMaxDynamicSharedMemorySize, SMEM);

    // L1: prep (zero deg + pack weights)
    prep_kernel<<<ZB + HID + HID2, 256>>>(W1, W2);
    // L2: degree histogram
    hist_kernel<<<ge, TB>>>(dst, E);
    // L3: dis = rsqrt(deg+1)
    dis_kernel<<<gn, TB>>>(N);
    // L4: layer-1 GEMM (profiled position)
    {
        dim3 grid(mtiles, HID / 128);
        mma_gemm_kernel<HID><<<grid, 256, SMEM>>>(x, w1h, w1l, h1, N);
    }
    // L5-L8: CSR build
    scan_block_kernel<<<nb, 1024>>>(N);
    scan_sums_kernel<<<1, 64>>>(nb, N);
    scan_add_kernel<<<gn, TB>>>(N);
    scatter_kernel<<<ge, TB>>>(src, dst, E);
    // L9: graph boundaries
    bounds_kernel<<<gn, TB>>>(batch, N);
    // L10: layer-1 aggregation -> bx
    agg_kernel<64><<<(N + 1) / 2, 128>>>(h1, b1, bx, N);
    // L11: layer-2 GEMM
    {
        dim3 grid(mtiles, HID2 / 128);
        mma_gemm_kernel<HID2><<<grid, 256, SMEM>>>(bx, w2h, w2l, h2, N);
    }
    // L12: layer-2 aggregation -> cx
    agg_kernel<32><<<(N + 3) / 4, 128>>>(h2, b2, cx, N);
    // L13-L14: pool + head
    pool_kernel<<<N_GRAPHS, HID2>>>();
    head_kernel<<<N_GRAPHS, N_DCS>>>(Wm, bm, out);
}

// round 10
// speedup vs baseline: 1.3772x; 1.3772x over previous
#include <cuda_runtime.h>
#include <cuda_bf16.h>
#include <cstdint>
#include <cstddef>

#define N_NODES 50000
#define N_EDGES 800000
#define N_GRAPHS 64
#define IN_C 256
#define HID 256
#define HID2 128
#define N_DCS 64

// ---------------- static device scratch ----------------
__device__ float g_h1[(size_t)N_NODES * HID];
__device__ float g_bx[(size_t)N_NODES * HID];
__device__ float g_h2[(size_t)N_NODES * HID2];
__device__ float g_cx[(size_t)N_NODES * HID2];
__device__ __nv_bfloat16 g_w1h[HID * IN_C];
__device__ __nv_bfloat16 g_w1l[HID * IN_C];
__device__ __nv_bfloat16 g_w2h[HID2 * HID];
__device__ __nv_bfloat16 g_w2l[HID2 * HID];
__device__ float g_dis[N_NODES];
__device__ int   g_deg[N_NODES];
__device__ int   g_off[N_NODES + 1];
__device__ int   g_pos[N_NODES];
__device__ int   g_csr[N_EDGES];
__device__ int   g_bsum[64];
__device__ int   g_boff[64];
__device__ int   g_gs[N_GRAPHS + 1];
__device__ float g_px[N_GRAPHS * HID2];

// ---------------- helpers ----------------
__device__ __forceinline__ uint32_t smem_u32(const void* p) {
    uint32_t a;
    asm("{ .reg .u64 t; cvta.to.shared.u64 t, %1; cvt.u32.u64 %0, t; }" : "=r"(a) : "l"(p));
    return a;
}
#define SWZ(o) ((uint32_t)(o) ^ ((((uint32_t)(o)) >> 3) & 0x70u))

#define MMA_BF16(d, a, b) \
    asm volatile("mma.sync.aligned.m16n8k16.row.col.f32.bf16.bf16.f32 " \
        "{%0,%1,%2,%3}, {%4,%5,%6,%7}, {%8,%9}, {%0,%1,%2,%3};" \
        : "+f"((d)[0]), "+f"((d)[1]), "+f"((d)[2]), "+f"((d)[3]) \
        : "r"((a)[0]), "r"((a)[1]), "r"((a)[2]), "r"((a)[3]), \
          "r"((b)[0]), "r"((b)[1]))

#define LDSM4(r, addr) \
    asm volatile("ldmatrix.sync.aligned.m8n8.x4.shared.b16 {%0,%1,%2,%3}, [%4];" \
        : "=r"((r)[0]), "=r"((r)[1]), "=r"((r)[2]), "=r"((r)[3]) : "r"(addr))

__device__ __forceinline__ void split2(float f0, float f1, uint32_t& h, uint32_t& l) {
    __nv_bfloat162 hp = __floats2bfloat162_rn(f0, f1);
    float2 hf = __bfloat1622float2(hp);
    __nv_bfloat162 lp = __floats2bfloat162_rn(f0 - hf.x, f1 - hf.y);
    h = *reinterpret_cast<uint32_t*>(&hp);
    l = *reinterpret_cast<uint32_t*>(&lp);
}

// ---------------- fused prep: zero g_deg + pack W1/W2 transposed bf16 hi/lo ----------------
#define ZB ((N_NODES + 255) / 256)
__global__ void prep_kernel(const float* __restrict__ W1, const float* __restrict__ W2) {
    int b = blockIdx.x;
    int t = threadIdx.x;                 // 256
    if (b < ZB) {
        int i = b * 256 + t;
        if (i < N_NODES) g_deg[i] = 0;
    } else if (b < ZB + HID) {
        int n = b - ZB;
        float v = W1[(size_t)t * HID + n];
        __nv_bfloat16 h = __float2bfloat16(v);
        g_w1h[(size_t)n * 256 + t] = h;
        g_w1l[(size_t)n * 256 + t] = __float2bfloat16(v - __bfloat162float(h));
    } else {
        int n = b - ZB - HID;
        float v = W2[(size_t)t * HID2 + n];
        __nv_bfloat16 h = __float2bfloat16(v);
        g_w2h[(size_t)n * 256 + t] = h;
        g_w2l[(size_t)n * 256 + t] = __float2bfloat16(v - __bfloat162float(h));
    }
}

__global__ void hist_kernel(const int* __restrict__ dst, int e) {
    int i = blockIdx.x * blockDim.x + threadIdx.x;
    if (i < e) atomicAdd(&g_deg[dst[i]], 1);
}
__global__ void dis_kernel(int n) {
    int i = blockIdx.x * blockDim.x + threadIdx.x;
    if (i < n) g_dis[i] = rsqrtf((float)g_deg[i] + 1.0f);
}
__global__ void scan_block_kernel(int n) {
    __shared__ int sh[1024];
    int tid = threadIdx.x;
    int i = blockIdx.x * 1024 + tid;
    int v = (i < n) ? g_deg[i] : 0;
    sh[tid] = v;
    __syncthreads();
    #pragma unroll
    for (int s = 1; s < 1024; s <<= 1) {
        int t = (tid >= s) ? sh[tid - s] : 0;
        __syncthreads();
        sh[tid] += t;
        __syncthreads();
    }
    if (i < n) g_off[i] = sh[tid] - v;
    if (tid == 1023) g_bsum[blockIdx.x] = sh[1023];
}
__global__ void scan_sums_kernel(int nb, int n) {
    __shared__ int sh[64];
    int tid = threadIdx.x;
    int v = (tid < nb) ? g_bsum[tid] : 0;
    sh[tid] = v;
    __syncthreads();
    #pragma unroll
    for (int s = 1; s < 64; s <<= 1) {
        int t = (tid >= s) ? sh[tid - s] : 0;
        __syncthreads();
        sh[tid] += t;
        __syncthreads();
    }
    if (tid < nb) g_boff[tid] = sh[tid] - v;
    if (tid == nb - 1) g_off[n] = sh[tid];
}
__global__ void scan_add_kernel(int n) {
    int i = blockIdx.x * blockDim.x + threadIdx.x;
    if (i < n) {
        int o = g_off[i] + g_boff[i >> 10];
        g_off[i] = o;
        g_pos[i] = o;
    }
}
__global__ void scatter_kernel(const int* __restrict__ src, const int* __restrict__ dst, int e) {
    int i = blockIdx.x * blockDim.x + threadIdx.x;
    if (i < e) {
        int d = dst[i];
        int p = atomicAdd(&g_pos[d], 1);
        g_csr[p] = src[i];
    }
}
__global__ void bounds_kernel(const int* __restrict__ batch, int n) {
    int i = blockIdx.x * blockDim.x + threadIdx.x;
    if (i == 0) g_gs[N_GRAPHS] = n;
    if (i < n) {
        if (i == 0 || batch[i] != batch[i - 1]) g_gs[batch[i]] = i;
    }
}

// ================ HMMA bf16x3 GEMM (round-8 structure + ldmatrix compute) ================
// C[r][c] = (A[r,:]@B[c,:]^T) * g_dis[r]
// A fp32 [M,256] row-major (split to bf16 hi/lo in-kernel).
// B = Bh+Bl bf16 [NTOT,256] row-major (pre-transposed weights).
// CTA tile 128x128, K=256 in 4 chunks of 64 (SW128 swizzled 128B rows), single buffer,
// 2 CTAs/SM. 8 warps (2x4), warp tile 64x32, m16n8k16, fragments via ldmatrix.x4.
template <int NTOT>
__global__ __launch_bounds__(256, 2) void mma_gemm_kernel(
    const float* __restrict__ A,
    const __nv_bfloat16* __restrict__ Bh, const __nv_bfloat16* __restrict__ Bl,
    float* __restrict__ C, int M)
{
    constexpr int K = 256;
    constexpr int TERM = 16384;            // 128 rows x 128 bytes
    extern __shared__ char sm[];
    const uint32_t sb = smem_u32(sm);
    const uint32_t sAh = sb, sAl = sb + TERM, sBH = sb + 2 * TERM, sBL = sb + 3 * TERM;

    const int tid = threadIdx.x;
    const int wid = tid >> 5;
    const int lane = tid & 31;
    const int wm = wid >> 2;               // 0..1
    const int wn = wid & 3;                // 0..3
    const int m0 = blockIdx.x * 128;
    const int n0 = blockIdx.y * 128;

    // ldmatrix per-lane base byte offsets (within a term tile)
    uint32_t abase[4], bbase[2];
    {
        int arow = (lane & 7) + ((lane >> 3) & 1) * 8;
        int akb  = (lane >> 4) * 16;
        #pragma unroll
        for (int mi = 0; mi < 4; mi++)
            abase[mi] = (uint32_t)(wm * 64 + mi * 16 + arow) * 128 + akb;
        int brow = (lane & 7) + (lane >> 4) * 8;
        int bkb  = ((lane >> 3) & 1) * 16;
        #pragma unroll
        for (int p = 0; p < 2; p++)
            bbase[p] = (uint32_t)(wn * 32 + p * 16 + brow) * 128 + bkb;
    }

    float acc[4][4][4];
    #pragma unroll
    for (int i = 0; i < 4; i++)
        #pragma unroll
        for (int j = 0; j < 4; j++)
            #pragma unroll
            for (int q = 0; q < 4; q++) acc[i][j][q] = 0.f;

    for (int c = 0; c < 4; c++) {
        const int k0 = c * 64;
        // cooperative load: 128 rows x {Ah,Al,Bh,Bl}, 8 x 16B slots per row
        #pragma unroll
        for (int v = tid; v < 1024; v += 256) {
            int row = v >> 3, u = v & 7;
            uint32_t so = SWZ((uint32_t)(row * 128 + u * 16));
            uint4 hv = make_uint4(0, 0, 0, 0), lv = make_uint4(0, 0, 0, 0);
            if (m0 + row < M) {
                size_t gi = (size_t)(m0 + row) * K + k0 + u * 8;
                float4 fa = *(const float4*)(A + gi);
                float4 fb = *(const float4*)(A + gi + 4);
                split2(fa.x, fa.y, hv.x, lv.x);
                split2(fa.z, fa.w, hv.y, lv.y);
                split2(fb.x, fb.y, hv.z, lv.z);
                split2(fb.z, fb.w, hv.w, lv.w);
            }
            *(uint4*)(sm + so)            = hv;
            *(uint4*)(sm + TERM + so)     = lv;
            size_t gb = (size_t)(n0 + row) * K + k0 + u * 8;
            *(uint4*)(sm + 2 * TERM + so) = *(const uint4*)(Bh + gb);
            *(uint4*)(sm + 3 * TERM + so) = *(const uint4*)(Bl + gb);
        }
        __syncthreads();

        #pragma unroll
        for (int ks = 0; ks < 4; ks++) {
            const uint32_t ko = (uint32_t)(ks * 32);
            uint32_t bh[8], bl[8], af[16];
            LDSM4(&bh[0], sBH + SWZ(bbase[0] + ko));
            LDSM4(&bh[4], sBH + SWZ(bbase[1] + ko));
            LDSM4(&bl[0], sBL + SWZ(bbase[0] + ko));
            LDSM4(&bl[4], sBL + SWZ(bbase[1] + ko));
            #pragma unroll
            for (int mi = 0; mi < 4; mi++)
                LDSM4(&af[mi * 4], sAh + SWZ(abase[mi] + ko));
            #pragma unroll
            for (int mi = 0; mi < 4; mi++)
                #pragma unroll
                for (int ni = 0; ni < 4; ni++)
                    MMA_BF16(acc[mi][ni], &af[mi * 4], &bh[ni * 2]);
            #pragma unroll
            for (int mi = 0; mi < 4; mi++)
                #pragma unroll
                for (int ni = 0; ni < 4; ni++)
                    MMA_BF16(acc[mi][ni], &af[mi * 4], &bl[ni * 2]);
            #pragma unroll
            for (int mi = 0; mi < 4; mi++)
                LDSM4(&af[mi * 4], sAl + SWZ(abase[mi] + ko));
            #pragma unroll
            for (int mi = 0; mi < 4; mi++)
                #pragma unroll
                for (int ni = 0; ni < 4; ni++)
                    MMA_BF16(acc[mi][ni], &af[mi * 4], &bh[ni * 2]);
        }
        __syncthreads();
    }

    // epilogue: scale by dis[row] and store
    const int g = lane >> 2;
    const int t = lane & 3;
    #pragma unroll
    for (int mi = 0; mi < 4; mi++) {
        int r0 = m0 + wm * 64 + mi * 16 + g;
        int r1 = r0 + 8;
        float s0 = (r0 < M) ? g_dis[r0] : 0.f;
        float s1 = (r1 < M) ? g_dis[r1] : 0.f;
        #pragma unroll
        for (int ni = 0; ni < 4; ni++) {
            int col = n0 + wn * 32 + ni * 8 + t * 2;
            if (r0 < M)
                *(float2*)(C + (size_t)r0 * NTOT + col) =
                    make_float2(acc[mi][ni][0] * s0, acc[mi][ni][1] * s0);
            if (r1 < M)
                *(float2*)(C + (size_t)r1 * NTOT + col) =
                    make_float2(acc[mi][ni][2] * s1, acc[mi][ni][3] * s1);
        }
    }
}

// ---------------- gather aggregation: out = relu(dis[n]*(self+sum) + bias), float4, MLP=4 ----------------
template <int C4>
__global__ __launch_bounds__(128) void agg_kernel(
    const float* __restrict__ hs_, const float* __restrict__ bias_,
    float* __restrict__ out_, int N)
{
    constexpr int NPB = 128 / C4;
    int node = blockIdx.x * NPB + threadIdx.x / C4;
    int c = threadIdx.x % C4;
    if (node >= N) return;
    const float4* hs = (const float4*)hs_;
    float dn = g_dis[node];
    int s0 = g_off[node], s1 = g_off[node + 1];
    float4 a0 = hs[(size_t)node * C4 + c];     // self-loop (already *dis[node])
    float4 a1 = make_float4(0.f, 0.f, 0.f, 0.f);
    float4 a2 = make_float4(0.f, 0.f, 0.f, 0.f);
    float4 a3 = make_float4(0.f, 0.f, 0.f, 0.f);
    int j = s0;
    for (; j + 3 < s1; j += 4) {
        int i0 = g_csr[j], i1 = g_csr[j + 1], i2 = g_csr[j + 2], i3 = g_csr[j + 3];
        float4 v0 = hs[(size_t)i0 * C4 + c];
        float4 v1 = hs[(size_t)i1 * C4 + c];
        float4 v2 = hs[(size_t)i2 * C4 + c];
        float4 v3 = hs[(size_t)i3 * C4 + c];
        a0.x += v0.x; a0.y += v0.y; a0.z += v0.z; a0.w += v0.w;
        a1.x += v1.x; a1.y += v1.y; a1.z += v1.z; a1.w += v1.w;
        a2.x += v2.x; a2.y += v2.y; a2.z += v2.z; a2.w += v2.w;
        a3.x += v3.x; a3.y += v3.y; a3.z += v3.z; a3.w += v3.w;
    }
    for (; j < s1; j++) {
        float4 v = hs[(size_t)g_csr[j] * C4 + c];
        a0.x += v.x; a0.y += v.y; a0.z += v.z; a0.w += v.w;
    }
    float4 bv = ((const float4*)bias_)[c];
    float4 r;
    r.x = fmaxf(fmaf(a0.x + a1.x + a2.x + a3.x, dn, bv.x), 0.f);
    r.y = fmaxf(fmaf(a0.y + a1.y + a2.y + a3.y, dn, bv.y), 0.f);
    r.z = fmaxf(fmaf(a0.z + a1.z + a2.z + a3.z, dn, bv.z), 0.f);
    r.w = fmaxf(fmaf(a0.w + a1.w + a2.w + a3.w, dn, bv.w), 0.f);
    ((float4*)out_)[(size_t)node * C4 + c] = r;
}

// ---------------- global max pool per graph ----------------
__global__ void pool_kernel() {
    int g = blockIdx.x;
    int c = threadIdx.x;          // 0..127
    int a = g_gs[g], b = g_gs[g + 1];
    float m = -3.402823466e38f;
    int n = a;
    for (; n + 3 < b; n += 4) {
        float v0 = g_cx[(size_t)(n + 0) * HID2 + c];
        float v1 = g_cx[(size_t)(n + 1) * HID2 + c];
        float v2 = g_cx[(size_t)(n + 2) * HID2 + c];
        float v3 = g_cx[(size_t)(n + 3) * HID2 + c];
        m = fmaxf(m, fmaxf(fmaxf(v0, v1), fmaxf(v2, v3)));
    }
    for (; n < b; n++) m = fmaxf(m, g_cx[(size_t)n * HID2 + c]);
    g_px[g * HID2 + c] = m;
}

// ---------------- head ----------------
__global__ void head_kernel(const float* __restrict__ Wm, const float* __restrict__ bm,
                            float* __restrict__ out)
{
    int g = blockIdx.x;
    int d = threadIdx.x;          // 0..63
    float acc = bm[d];
    #pragma unroll 8
    for (int k = 0; k < HID2; k++)
        acc = fmaf(g_px[g * HID2 + k], Wm[k * N_DCS + d], acc);
    out[g * N_DCS + d] = acc;
}

// ---------------- launch ----------------
extern "C" void kernel_launch(void* const* d_in, const int* in_sizes, int n_in,
                              void* d_out, int out_size)
{
    const float* x     = (const float*)d_in[0];
    const int*   ei    = (const int*)  d_in[1];
    const int*   batch = (const int*)  d_in[2];
    const float* W1    = (const float*)d_in[3];
    const float* b1    = (const float*)d_in[4];
    const float* W2    = (const float*)d_in[5];
    const float* b2    = (const float*)d_in[6];
    const float* Wm    = (const float*)d_in[7];
    const float* bm    = (const float*)d_in[8];
    float* out = (float*)d_out;

    const int N = in_sizes[2];          // 50000
    const int E = in_sizes[1] / 2;      // 800000
    const int* src = ei;
    const int* dst = ei + E;

    float *h1, *bx, *h2, *cx;
    __nv_bfloat16 *w1h, *w1l, *w2h, *w2l;
    cudaGetSymbolAddress((void**)&h1, g_h1);
    cudaGetSymbolAddress((void**)&bx, g_bx);
    cudaGetSymbolAddress((void**)&h2, g_h2);
    cudaGetSymbolAddress((void**)&cx, g_cx);
    cudaGetSymbolAddress((void**)&w1h, g_w1h);
    cudaGetSymbolAddress((void**)&w1l, g_w1l);
    cudaGetSymbolAddress((void**)&w2h, g_w2h);
    cudaGetSymbolAddress((void**)&w2l, g_w2l);

    const int TB = 256;
    int gn = (N + TB - 1) / TB;
    int ge = (E + TB - 1) / TB;
    int nb = (N + 1023) / 1024;

    const int SMEM = 4 * 16384;         // 65536 bytes, single buffer (2 CTAs/SM)
    int mtiles = (N + 127) / 128;
    cudaFuncSetAttribute(mma_gemm_kernel<HID>,
                         cudaFuncAttributeMaxDynamicSharedMemorySize, SMEM);
    cudaFuncSetAttribute(mma_gemm_kernel<HID2>,
                         cudaFuncAttributeMaxDynamicSharedMemorySize, SMEM);

    // L1: prep (zero deg + pack weights)
    prep_kernel<<<ZB + HID + HID2, 256>>>(W1, W2);
    // L2: degree histogram
    hist_kernel<<<ge, TB>>>(dst, E);
    // L3: dis = rsqrt(deg+1)
    dis_kernel<<<gn, TB>>>(N);
    // L4: layer-1 GEMM (profiled position)
    {
        dim3 grid(mtiles, HID / 128);
        mma_gemm_kernel<HID><<<grid, 256, SMEM>>>(x, w1h, w1l, h1, N);
    }
    // L5-L8: CSR build
    scan_block_kernel<<<nb, 1024>>>(N);
    scan_sums_kernel<<<1, 64>>>(nb, N);
    scan_add_kernel<<<gn, TB>>>(N);
    scatter_kernel<<<ge, TB>>>(src, dst, E);
    // L9: graph boundaries
    bounds_kernel<<<gn, TB>>>(batch, N);
    // L10: layer-1 aggregation -> bx
    agg_kernel<64><<<(N + 1) / 2, 128>>>(h1, b1, bx, N);
    // L11: layer-2 GEMM
    {
        dim3 grid(mtiles, HID2 / 128);
        mma_gemm_kernel<HID2><<<grid, 256, SMEM>>>(bx, w2h, w2l, h2, N);
    }
    // L12: layer-2 aggregation -> cx
    agg_kernel<32><<<(N + 3) / 4, 128>>>(h2, b2, cx, N);
    // L13-L14: pool + head
    pool_kernel<<<N_GRAPHS, HID2>>>();
    head_kernel<<<N_GRAPHS, N_DCS>>>(Wm, bm, out);
}

// round 11
// speedup vs baseline: 1.4702x; 1.0675x over previous
#include <cuda_runtime.h>
#include <cuda_bf16.h>
#include <cstdint>
#include <cstddef>

#define N_NODES 50000
#define N_EDGES 800000
#define N_GRAPHS 64
#define IN_C 256
#define HID 256
#define HID2 128
#define N_DCS 64

// ---------------- static device scratch ----------------
__device__ float g_h1[(size_t)N_NODES * HID];
__device__ float g_bx[(size_t)N_NODES * HID];
__device__ float g_h2[(size_t)N_NODES * HID2];
__device__ float g_cx[(size_t)N_NODES * HID2];
__device__ __nv_bfloat16 g_w1h[HID * IN_C];
__device__ __nv_bfloat16 g_w1l[HID * IN_C];
__device__ __nv_bfloat16 g_w2h[HID2 * HID];
__device__ __nv_bfloat16 g_w2l[HID2 * HID];
__device__ float g_dis[N_NODES];
__device__ int   g_deg[N_NODES];
__device__ int   g_off[N_NODES + 1];
__device__ int   g_pos[N_NODES];
__device__ int   g_csr[N_EDGES];
__device__ int   g_bsum[64];
__device__ int   g_boff[64];
__device__ int   g_gs[N_GRAPHS + 1];
__device__ float g_px[N_GRAPHS * HID2];

// ---------------- helpers ----------------
__device__ __forceinline__ uint32_t smem_u32(const void* p) {
    uint32_t a;
    asm("{ .reg .u64 t; cvta.to.shared.u64 t, %1; cvt.u32.u64 %0, t; }" : "=r"(a) : "l"(p));
    return a;
}
// SW64 swizzle for 64-byte rows
#define SWZ64(o) ((uint32_t)(o) ^ ((((uint32_t)(o)) >> 3) & 0x30u))

#define MMA_BF16(d, a, b) \
    asm volatile("mma.sync.aligned.m16n8k16.row.col.f32.bf16.bf16.f32 " \
        "{%0,%1,%2,%3}, {%4,%5,%6,%7}, {%8,%9}, {%0,%1,%2,%3};" \
        : "+f"((d)[0]), "+f"((d)[1]), "+f"((d)[2]), "+f"((d)[3]) \
        : "r"((a)[0]), "r"((a)[1]), "r"((a)[2]), "r"((a)[3]), \
          "r"((b)[0]), "r"((b)[1]))

#define LDSM4(r, addr) \
    asm volatile("ldmatrix.sync.aligned.m8n8.x4.shared.b16 {%0,%1,%2,%3}, [%4];" \
        : "=r"((r)[0]), "=r"((r)[1]), "=r"((r)[2]), "=r"((r)[3]) : "r"(addr))

#define CPASYNC16(dst, src) \
    asm volatile("cp.async.cg.shared.global [%0], [%1], 16;" :: "r"(dst), "l"(src))
#define CPCOMMIT() asm volatile("cp.async.commit_group;" ::: "memory")
#define CPWAIT0()  asm volatile("cp.async.wait_group 0;" ::: "memory")

__device__ __forceinline__ void split2(float f0, float f1, uint32_t& h, uint32_t& l) {
    __nv_bfloat162 hp = __floats2bfloat162_rn(f0, f1);
    float2 hf = __bfloat1622float2(hp);
    __nv_bfloat162 lp = __floats2bfloat162_rn(f0 - hf.x, f1 - hf.y);
    h = *reinterpret_cast<uint32_t*>(&hp);
    l = *reinterpret_cast<uint32_t*>(&lp);
}

// ---------------- fused prep: zero g_deg + pack W1/W2 transposed bf16 hi/lo ----------------
#define ZB ((N_NODES + 255) / 256)
__global__ void prep_kernel(const float* __restrict__ W1, const float* __restrict__ W2) {
    int b = blockIdx.x;
    int t = threadIdx.x;                 // 256
    if (b < ZB) {
        int i = b * 256 + t;
        if (i < N_NODES) g_deg[i] = 0;
    } else if (b < ZB + HID) {
        int n = b - ZB;
        float v = W1[(size_t)t * HID + n];
        __nv_bfloat16 h = __float2bfloat16(v);
        g_w1h[(size_t)n * 256 + t] = h;
        g_w1l[(size_t)n * 256 + t] = __float2bfloat16(v - __bfloat162float(h));
    } else {
        int n = b - ZB - HID;
        float v = W2[(size_t)t * HID2 + n];
        __nv_bfloat16 h = __float2bfloat16(v);
        g_w2h[(size_t)n * 256 + t] = h;
        g_w2l[(size_t)n * 256 + t] = __float2bfloat16(v - __bfloat162float(h));
    }
}

__global__ void hist_kernel(const int* __restrict__ dst, int e) {
    int i = blockIdx.x * blockDim.x + threadIdx.x;
    if (i < e) atomicAdd(&g_deg[dst[i]], 1);
}
__global__ void dis_kernel(int n) {
    int i = blockIdx.x * blockDim.x + threadIdx.x;
    if (i < n) g_dis[i] = rsqrtf((float)g_deg[i] + 1.0f);
}
__global__ void scan_block_kernel(int n) {
    __shared__ int sh[1024];
    int tid = threadIdx.x;
    int i = blockIdx.x * 1024 + tid;
    int v = (i < n) ? g_deg[i] : 0;
    sh[tid] = v;
    __syncthreads();
    #pragma unroll
    for (int s = 1; s < 1024; s <<= 1) {
        int t = (tid >= s) ? sh[tid - s] : 0;
        __syncthreads();
        sh[tid] += t;
        __syncthreads();
    }
    if (i < n) g_off[i] = sh[tid] - v;
    if (tid == 1023) g_bsum[blockIdx.x] = sh[1023];
}
__global__ void scan_sums_kernel(int nb, int n) {
    __shared__ int sh[64];
    int tid = threadIdx.x;
    int v = (tid < nb) ? g_bsum[tid] : 0;
    sh[tid] = v;
    __syncthreads();
    #pragma unroll
    for (int s = 1; s < 64; s <<= 1) {
        int t = (tid >= s) ? sh[tid - s] : 0;
        __syncthreads();
        sh[tid] += t;
        __syncthreads();
    }
    if (tid < nb) g_boff[tid] = sh[tid] - v;
    if (tid == nb - 1) g_off[n] = sh[tid];
}
__global__ void scan_add_kernel(int n) {
    int i = blockIdx.x * blockDim.x + threadIdx.x;
    if (i < n) {
        int o = g_off[i] + g_boff[i >> 10];
        g_off[i] = o;
        g_pos[i] = o;
    }
}
__global__ void scatter_kernel(const int* __restrict__ src, const int* __restrict__ dst, int e) {
    int i = blockIdx.x * blockDim.x + threadIdx.x;
    if (i < e) {
        int d = dst[i];
        int p = atomicAdd(&g_pos[d], 1);
        g_csr[p] = src[i];
    }
}
__global__ void bounds_kernel(const int* __restrict__ batch, int n) {
    int i = blockIdx.x * blockDim.x + threadIdx.x;
    if (i == 0) g_gs[N_GRAPHS] = n;
    if (i < n) {
        if (i == 0 || batch[i] != batch[i - 1]) g_gs[batch[i]] = i;
    }
}

// ================ pipelined HMMA bf16x3 GEMM, chunk-32 double buffer, 2 CTAs/SM ================
// C[r][c] = (A[r,:]@B[c,:]^T) * g_dis[r]
// A fp32 [M,256] row-major (split to bf16 hi/lo in-kernel, register-staged).
// B = Bh+Bl bf16 [NTOT,256] row-major (pre-transposed weights, cp.async).
// CTA tile 128x128, K=256 in 8 chunks of 32 (SW64-swizzled 64B SMEM rows).
// 8 warps (2x4), warp tile 64x32, m16n8k16, ldmatrix.x4 fragments.
template <int NTOT>
__global__ __launch_bounds__(256, 2) void mma_gemm_kernel(
    const float* __restrict__ A,
    const __nv_bfloat16* __restrict__ Bh, const __nv_bfloat16* __restrict__ Bl,
    float* __restrict__ C, int M)
{
    constexpr int K = 256;
    constexpr int TERM = 128 * 64;         // 8192 bytes: 128 rows x 64B (32 bf16)
    constexpr int BUF = 4 * TERM;          // Ah,Al,Bh,Bl per buffer = 32KB
    extern __shared__ char sm[];
    const uint32_t sb = smem_u32(sm);

    const int tid = threadIdx.x;
    const int wid = tid >> 5;
    const int lane = tid & 31;
    const int wm = wid >> 2;               // 0..1
    const int wn = wid & 3;                // 0..3
    const int m0 = blockIdx.x * 128;
    const int n0 = blockIdx.y * 128;

    // ldmatrix per-lane base byte offsets within a term tile (64B rows)
    uint32_t abase[4], bbase[2];
    {
        int arow = (lane & 7) + ((lane >> 3) & 1) * 8;
        int akb  = (lane >> 4) * 16;
        #pragma unroll
        for (int mi = 0; mi < 4; mi++)
            abase[mi] = (uint32_t)(wm * 64 + mi * 16 + arow) * 64 + akb;
        int brow = (lane & 7) + (lane >> 4) * 8;
        int bkb  = ((lane >> 3) & 1) * 16;
        #pragma unroll
        for (int p = 0; p < 2; p++)
            bbase[p] = (uint32_t)(wn * 32 + p * 16 + brow) * 64 + bkb;
    }

    float acc[4][4][4];
    #pragma unroll
    for (int i = 0; i < 4; i++)
        #pragma unroll
        for (int j = 0; j < 4; j++)
            #pragma unroll
            for (int q = 0; q < 4; q++) acc[i][j][q] = 0.f;

    // A staging: thread covers row = tid/2, 16 floats at half*16 within each 32-col chunk
    const int arow_ld = tid >> 1;
    const int half = tid & 1;
    const bool aok = (m0 + arow_ld) < M;
    const float* aptr = A + (size_t)(m0 + arow_ld) * K + half * 16;
    float4 pf[4];

    auto prefA = [&](int c) {
        if (aok) {
            #pragma unroll
            for (int i = 0; i < 4; i++)
                pf[i] = *(const float4*)(aptr + c * 32 + i * 4);
        } else {
            #pragma unroll
            for (int i = 0; i < 4; i++) pf[i] = make_float4(0.f, 0.f, 0.f, 0.f);
        }
    };
    auto storeA = [&](int b) {
        char* dst = sm + b * BUF;
        #pragma unroll
        for (int i = 0; i < 2; i++) {
            uint4 hv, lv;
            split2(pf[2 * i].x,     pf[2 * i].y,     hv.x, lv.x);
            split2(pf[2 * i].z,     pf[2 * i].w,     hv.y, lv.y);
            split2(pf[2 * i + 1].x, pf[2 * i + 1].y, hv.z, lv.z);
            split2(pf[2 * i + 1].z, pf[2 * i + 1].w, hv.w, lv.w);
            uint32_t so = SWZ64((uint32_t)(arow_ld * 64 + half * 32 + i * 16));
            *(uint4*)(dst + so)        = hv;
            *(uint4*)(dst + TERM + so) = lv;
        }
    };
    auto cpB = [&](int c, int b) {
        uint32_t d = sb + b * BUF;
        #pragma unroll
        for (int i = 0; i < 2; i++) {
            int v = tid + 256 * i;
            int row = v >> 2, u = v & 3;
            uint32_t so = SWZ64((uint32_t)(row * 64 + u * 16));
            size_t gi = (size_t)(n0 + row) * K + c * 32 + u * 8;
            CPASYNC16(d + 2 * TERM + so, Bh + gi);
            CPASYNC16(d + 3 * TERM + so, Bl + gi);
        }
    };
    auto compute = [&](int b) {
        uint32_t sAh = sb + b * BUF;
        uint32_t sAl = sAh + TERM;
        uint32_t sBH = sAh + 2 * TERM;
        uint32_t sBL = sAh + 3 * TERM;
        #pragma unroll
        for (int ks = 0; ks < 2; ks++) {
            const uint32_t ko = (uint32_t)(ks * 32);
            uint32_t bh[8], bl[8], af[16];
            LDSM4(&bh[0], sBH + SWZ64(bbase[0] + ko));
            LDSM4(&bh[4], sBH + SWZ64(bbase[1] + ko));
            LDSM4(&bl[0], sBL + SWZ64(bbase[0] + ko));
            LDSM4(&bl[4], sBL + SWZ64(bbase[1] + ko));
            #pragma unroll
            for (int mi = 0; mi < 4; mi++)
                LDSM4(&af[mi * 4], sAh + SWZ64(abase[mi] + ko));
            #pragma unroll
            for (int mi = 0; mi < 4; mi++)
                #pragma unroll
                for (int ni = 0; ni < 4; ni++)
                    MMA_BF16(acc[mi][ni], &af[mi * 4], &bh[ni * 2]);
            #pragma unroll
            for (int mi = 0; mi < 4; mi++)
                #pragma unroll
                for (int ni = 0; ni < 4; ni++)
                    MMA_BF16(acc[mi][ni], &af[mi * 4], &bl[ni * 2]);
            #pragma unroll
            for (int mi = 0; mi < 4; mi++)
                LDSM4(&af[mi * 4], sAl + SWZ64(abase[mi] + ko));
            #pragma unroll
            for (int mi = 0; mi < 4; mi++)
                #pragma unroll
                for (int ni = 0; ni < 4; ni++)
                    MMA_BF16(acc[mi][ni], &af[mi * 4], &bh[ni * 2]);
        }
    };

    // prologue: fill buffer 0 with chunk 0
    prefA(0);
    cpB(0, 0);
    CPCOMMIT();
    storeA(0);
    CPWAIT0();
    __syncthreads();

    #pragma unroll
    for (int c = 0; c < 8; c++) {
        int nb = (c + 1) & 1;
        if (c < 7) {
            cpB(c + 1, nb);
            CPCOMMIT();
            prefA(c + 1);
        }
        compute(c & 1);
        if (c < 7) {
            storeA(nb);
            CPWAIT0();
        }
        __syncthreads();
    }

    // epilogue: scale by dis[row] and store
    const int g = lane >> 2;
    const int t = lane & 3;
    #pragma unroll
    for (int mi = 0; mi < 4; mi++) {
        int r0 = m0 + wm * 64 + mi * 16 + g;
        int r1 = r0 + 8;
        float s0 = (r0 < M) ? g_dis[r0] : 0.f;
        float s1 = (r1 < M) ? g_dis[r1] : 0.f;
        #pragma unroll
        for (int ni = 0; ni < 4; ni++) {
            int col = n0 + wn * 32 + ni * 8 + t * 2;
            if (r0 < M)
                *(float2*)(C + (size_t)r0 * NTOT + col) =
                    make_float2(acc[mi][ni][0] * s0, acc[mi][ni][1] * s0);
            if (r1 < M)
                *(float2*)(C + (size_t)r1 * NTOT + col) =
                    make_float2(acc[mi][ni][2] * s1, acc[mi][ni][3] * s1);
        }
    }
}

// ---------------- gather aggregation: out = relu(dis[n]*(self+sum) + bias), float4, MLP=4 ----------------
template <int C4>
__global__ __launch_bounds__(128) void agg_kernel(
    const float* __restrict__ hs_, const float* __restrict__ bias_,
    float* __restrict__ out_, int N)
{
    constexpr int NPB = 128 / C4;
    int node = blockIdx.x * NPB + threadIdx.x / C4;
    int c = threadIdx.x % C4;
    if (node >= N) return;
    const float4* hs = (const float4*)hs_;
    float dn = g_dis[node];
    int s0 = g_off[node], s1 = g_off[node + 1];
    float4 a0 = hs[(size_t)node * C4 + c];     // self-loop (already *dis[node])
    float4 a1 = make_float4(0.f, 0.f, 0.f, 0.f);
    float4 a2 = make_float4(0.f, 0.f, 0.f, 0.f);
    float4 a3 = make_float4(0.f, 0.f, 0.f, 0.f);
    int j = s0;
    for (; j + 3 < s1; j += 4) {
        int i0 = g_csr[j], i1 = g_csr[j + 1], i2 = g_csr[j + 2], i3 = g_csr[j + 3];
        float4 v0 = hs[(size_t)i0 * C4 + c];
        float4 v1 = hs[(size_t)i1 * C4 + c];
        float4 v2 = hs[(size_t)i2 * C4 + c];
        float4 v3 = hs[(size_t)i3 * C4 + c];
        a0.x += v0.x; a0.y += v0.y; a0.z += v0.z; a0.w += v0.w;
        a1.x += v1.x; a1.y += v1.y; a1.z += v1.z; a1.w += v1.w;
        a2.x += v2.x; a2.y += v2.y; a2.z += v2.z; a2.w += v2.w;
        a3.x += v3.x; a3.y += v3.y; a3.z += v3.z; a3.w += v3.w;
    }
    for (; j < s1; j++) {
        float4 v = hs[(size_t)g_csr[j] * C4 + c];
        a0.x += v.x; a0.y += v.y; a0.z += v.z; a0.w += v.w;
    }
    float4 bv = ((const float4*)bias_)[c];
    float4 r;
    r.x = fmaxf(fmaf(a0.x + a1.x + a2.x + a3.x, dn, bv.x), 0.f);
    r.y = fmaxf(fmaf(a0.y + a1.y + a2.y + a3.y, dn, bv.y), 0.f);
    r.z = fmaxf(fmaf(a0.z + a1.z + a2.z + a3.z, dn, bv.z), 0.f);
    r.w = fmaxf(fmaf(a0.w + a1.w + a2.w + a3.w, dn, bv.w), 0.f);
    ((float4*)out_)[(size_t)node * C4 + c] = r;
}

// ---------------- global max pool per graph ----------------
__global__ void pool_kernel() {
    int g = blockIdx.x;
    int c = threadIdx.x;          // 0..127
    int a = g_gs[g], b = g_gs[g + 1];
    float m = -3.402823466e38f;
    int n = a;
    for (; n + 3 < b; n += 4) {
        float v0 = g_cx[(size_t)(n + 0) * HID2 + c];
        float v1 = g_cx[(size_t)(n + 1) * HID2 + c];
        float v2 = g_cx[(size_t)(n + 2) * HID2 + c];
        float v3 = g_cx[(size_t)(n + 3) * HID2 + c];
        m = fmaxf(m, fmaxf(fmaxf(v0, v1), fmaxf(v2, v3)));
    }
    for (; n < b; n++) m = fmaxf(m, g_cx[(size_t)n * HID2 + c]);
    g_px[g * HID2 + c] = m;
}

// ---------------- head ----------------
__global__ void head_kernel(const float* __restrict__ Wm, const float* __restrict__ bm,
                            float* __restrict__ out)
{
    int g = blockIdx.x;
    int d = threadIdx.x;          // 0..63
    float acc = bm[d];
    #pragma unroll 8
    for (int k = 0; k < HID2; k++)
        acc = fmaf(g_px[g * HID2 + k], Wm[k * N_DCS + d], acc);
    out[g * N_DCS + d] = acc;
}

// ---------------- launch ----------------
extern "C" void kernel_launch(void* const* d_in, const int* in_sizes, int n_in,
                              void* d_out, int out_size)
{
    const float* x     = (const float*)d_in[0];
    const int*   ei    = (const int*)  d_in[1];
    const int*   batch = (const int*)  d_in[2];
    const float* W1    = (const float*)d_in[3];
    const float* b1    = (const float*)d_in[4];
    const float* W2    = (const float*)d_in[5];
    const float* b2    = (const float*)d_in[6];
    const float* Wm    = (const float*)d_in[7];
    const float* bm    = (const float*)d_in[8];
    float* out = (float*)d_out;

    const int N = in_sizes[2];          // 50000
    const int E = in_sizes[1] / 2;      // 800000
    const int* src = ei;
    const int* dst = ei + E;

    float *h1, *bx, *h2, *cx;
    __nv_bfloat16 *w1h, *w1l, *w2h, *w2l;
    cudaGetSymbolAddress((void**)&h1, g_h1);
    cudaGetSymbolAddress((void**)&bx, g_bx);
    cudaGetSymbolAddress((void**)&h2, g_h2);
    cudaGetSymbolAddress((void**)&cx, g_cx);
    cudaGetSymbolAddress((void**)&w1h, g_w1h);
    cudaGetSymbolAddress((void**)&w1l, g_w1l);
    cudaGetSymbolAddress((void**)&w2h, g_w2h);
    cudaGetSymbolAddress((void**)&w2l, g_w2l);

    const int TB = 256;
    int gn = (N + TB - 1) / TB;
    int ge = (E + TB - 1) / TB;
    int nb = (N + 1023) / 1024;

    const int SMEM = 2 * 4 * 8192;      // 65536 bytes: double-buffered chunk-32, 2 CTAs/SM
    int mtiles = (N + 127) / 128;
    cudaFuncSetAttribute(mma_gemm_kernel<HID>,
                         cudaFuncAttributeMaxDynamicSharedMemorySize, SMEM);
    cudaFuncSetAttribute(mma_gemm_kernel<HID2>,
                         cudaFuncAttributeMaxDynamicSharedMemorySize, SMEM);

    // L1: prep (zero deg + pack weights)
    prep_kernel<<<ZB + HID + HID2, 256>>>(W1, W2);
    // L2: degree histogram
    hist_kernel<<<ge, TB>>>(dst, E);
    // L3: dis = rsqrt(deg+1)
    dis_kernel<<<gn, TB>>>(N);
    // L4: layer-1 GEMM (profiled position)
    {
        dim3 grid(mtiles, HID / 128);
        mma_gemm_kernel<HID><<<grid, 256, SMEM>>>(x, w1h, w1l, h1, N);
    }
    // L5-L8: CSR build
    scan_block_kernel<<<nb, 1024>>>(N);
    scan_sums_kernel<<<1, 64>>>(nb, N);
    scan_add_kernel<<<gn, TB>>>(N);
    scatter_kernel<<<ge, TB>>>(src, dst, E);
    // L9: graph boundaries
    bounds_kernel<<<gn, TB>>>(batch, N);
    // L10: layer-1 aggregation -> bx
    agg_kernel<64><<<(N + 1) / 2, 128>>>(h1, b1, bx, N);
    // L11: layer-2 GEMM
    {
        dim3 grid(mtiles, HID2 / 128);
        mma_gemm_kernel<HID2><<<grid, 256, SMEM>>>(bx, w2h, w2l, h2, N);
    }
    // L12: layer-2 aggregation -> cx
    agg_kernel<32><<<(N + 3) / 4, 128>>>(h2, b2, cx, N);
    // L13-L14: pool + head
    pool_kernel<<<N_GRAPHS, HID2>>>();
    head_kernel<<<N_GRAPHS, N_DCS>>>(Wm, bm, out);
}

// round 12
// speedup vs baseline: 1.6889x; 1.1488x over previous
#include <cuda_runtime.h>
#include <cuda_bf16.h>
#include <cuda_fp16.h>
#include <cstdint>
#include <cstddef>

#define N_NODES 50000
#define N_EDGES 800000
#define N_GRAPHS 64
#define IN_C 256
#define HID 256
#define HID2 128
#define N_DCS 64

// ---------------- static device scratch ----------------
__device__ __half g_h1[(size_t)N_NODES * HID];          // (x@W1)*dis, fp16
__device__ float  g_bx[(size_t)N_NODES * HID];          // relu layer1 output fp32
__device__ __half g_h2[(size_t)N_NODES * HID2];         // (bx@W2)*dis, fp16
__device__ float  g_cx[(size_t)N_NODES * HID2];         // relu layer2 output
__device__ __nv_bfloat16 g_w1h[HID * IN_C];
__device__ __nv_bfloat16 g_w1l[HID * IN_C];
__device__ __nv_bfloat16 g_w2h[HID2 * HID];
__device__ __nv_bfloat16 g_w2l[HID2 * HID];
__device__ float g_dis[N_NODES];
__device__ int   g_deg[N_NODES];
__device__ int   g_off[N_NODES + 1];
__device__ int   g_pos[N_NODES];
__device__ int   g_csr[N_EDGES];
__device__ int   g_bsum[64];
__device__ int   g_boff[64];
__device__ int   g_gs[N_GRAPHS + 1];
__device__ float g_px[N_GRAPHS * HID2];

// ---------------- helpers ----------------
__device__ __forceinline__ uint32_t smem_u32(const void* p) {
    uint32_t a;
    asm("{ .reg .u64 t; cvta.to.shared.u64 t, %1; cvt.u32.u64 %0, t; }" : "=r"(a) : "l"(p));
    return a;
}
// SW64 swizzle for 64-byte rows
#define SWZ64(o) ((uint32_t)(o) ^ ((((uint32_t)(o)) >> 3) & 0x30u))

#define MMA_BF16(d, a, b) \
    asm volatile("mma.sync.aligned.m16n8k16.row.col.f32.bf16.bf16.f32 " \
        "{%0,%1,%2,%3}, {%4,%5,%6,%7}, {%8,%9}, {%0,%1,%2,%3};" \
        : "+f"((d)[0]), "+f"((d)[1]), "+f"((d)[2]), "+f"((d)[3]) \
        : "r"((a)[0]), "r"((a)[1]), "r"((a)[2]), "r"((a)[3]), \
          "r"((b)[0]), "r"((b)[1]))

#define LDSM4(r, addr) \
    asm volatile("ldmatrix.sync.aligned.m8n8.x4.shared.b16 {%0,%1,%2,%3}, [%4];" \
        : "=r"((r)[0]), "=r"((r)[1]), "=r"((r)[2]), "=r"((r)[3]) : "r"(addr))

#define CPASYNC16(dst, src) \
    asm volatile("cp.async.cg.shared.global [%0], [%1], 16;" :: "r"(dst), "l"(src))
#define CPCOMMIT() asm volatile("cp.async.commit_group;" ::: "memory")
#define CPWAIT0()  asm volatile("cp.async.wait_group 0;" ::: "memory")

__device__ __forceinline__ void split2(float f0, float f1, uint32_t& h, uint32_t& l) {
    __nv_bfloat162 hp = __floats2bfloat162_rn(f0, f1);
    float2 hf = __bfloat1622float2(hp);
    __nv_bfloat162 lp = __floats2bfloat162_rn(f0 - hf.x, f1 - hf.y);
    h = *reinterpret_cast<uint32_t*>(&hp);
    l = *reinterpret_cast<uint32_t*>(&lp);
}

// ---------------- fused prep: zero g_deg + pack W1/W2 transposed bf16 hi/lo ----------------
#define ZB ((N_NODES + 255) / 256)
__global__ void prep_kernel(const float* __restrict__ W1, const float* __restrict__ W2) {
    int b = blockIdx.x;
    int t = threadIdx.x;                 // 256
    if (b < ZB) {
        int i = b * 256 + t;
        if (i < N_NODES) g_deg[i] = 0;
    } else if (b < ZB + HID) {
        int n = b - ZB;
        float v = W1[(size_t)t * HID + n];
        __nv_bfloat16 h = __float2bfloat16(v);
        g_w1h[(size_t)n * 256 + t] = h;
        g_w1l[(size_t)n * 256 + t] = __float2bfloat16(v - __bfloat162float(h));
    } else {
        int n = b - ZB - HID;
        float v = W2[(size_t)t * HID2 + n];
        __nv_bfloat16 h = __float2bfloat16(v);
        g_w2h[(size_t)n * 256 + t] = h;
        g_w2l[(size_t)n * 256 + t] = __float2bfloat16(v - __bfloat162float(h));
    }
}

__global__ void hist_kernel(const int* __restrict__ dst, int e) {
    int i = blockIdx.x * blockDim.x + threadIdx.x;
    if (i < e) atomicAdd(&g_deg[dst[i]], 1);
}
__global__ void dis_kernel(int n) {
    int i = blockIdx.x * blockDim.x + threadIdx.x;
    if (i < n) g_dis[i] = rsqrtf((float)g_deg[i] + 1.0f);
}
__global__ void scan_block_kernel(int n) {
    __shared__ int sh[1024];
    int tid = threadIdx.x;
    int i = blockIdx.x * 1024 + tid;
    int v = (i < n) ? g_deg[i] : 0;
    sh[tid] = v;
    __syncthreads();
    #pragma unroll
    for (int s = 1; s < 1024; s <<= 1) {
        int t = (tid >= s) ? sh[tid - s] : 0;
        __syncthreads();
        sh[tid] += t;
        __syncthreads();
    }
    if (i < n) g_off[i] = sh[tid] - v;
    if (tid == 1023) g_bsum[blockIdx.x] = sh[1023];
}
__global__ void scan_sums_kernel(int nb, int n) {
    __shared__ int sh[64];
    int tid = threadIdx.x;
    int v = (tid < nb) ? g_bsum[tid] : 0;
    sh[tid] = v;
    __syncthreads();
    #pragma unroll
    for (int s = 1; s < 64; s <<= 1) {
        int t = (tid >= s) ? sh[tid - s] : 0;
        __syncthreads();
        sh[tid] += t;
        __syncthreads();
    }
    if (tid < nb) g_boff[tid] = sh[tid] - v;
    if (tid == nb - 1) g_off[n] = sh[tid];
}
__global__ void scan_add_kernel(int n) {
    int i = blockIdx.x * blockDim.x + threadIdx.x;
    if (i < n) {
        int o = g_off[i] + g_boff[i >> 10];
        g_off[i] = o;
        g_pos[i] = o;
    }
}
__global__ void scatter_kernel(const int* __restrict__ src, const int* __restrict__ dst, int e) {
    int i = blockIdx.x * blockDim.x + threadIdx.x;
    if (i < e) {
        int d = dst[i];
        int p = atomicAdd(&g_pos[d], 1);
        g_csr[p] = src[i];
    }
}
__global__ void bounds_kernel(const int* __restrict__ batch, int n) {
    int i = blockIdx.x * blockDim.x + threadIdx.x;
    if (i == 0) g_gs[N_GRAPHS] = n;
    if (i < n) {
        if (i == 0 || batch[i] != batch[i - 1]) g_gs[batch[i]] = i;
    }
}

// ================ pipelined HMMA bf16x3 GEMM, chunk-32 double buffer, 2 CTAs/SM ================
// C[r][c] = (A[r,:]@B[c,:]^T) * g_dis[r], stored as fp16.
// A fp32 [M,256] row-major (split to bf16 hi/lo in-kernel, register-staged).
// B = Bh+Bl bf16 [NTOT,256] row-major (pre-transposed weights, cp.async).
template <int NTOT>
__global__ __launch_bounds__(256, 2) void mma_gemm_kernel(
    const float* __restrict__ A,
    const __nv_bfloat16* __restrict__ Bh, const __nv_bfloat16* __restrict__ Bl,
    __half* __restrict__ C, int M)
{
    constexpr int K = 256;
    constexpr int TERM = 128 * 64;         // 8192 bytes: 128 rows x 64B (32 bf16)
    constexpr int BUF = 4 * TERM;          // Ah,Al,Bh,Bl per buffer = 32KB
    extern __shared__ char sm[];
    const uint32_t sb = smem_u32(sm);

    const int tid = threadIdx.x;
    const int wid = tid >> 5;
    const int lane = tid & 31;
    const int wm = wid >> 2;               // 0..1
    const int wn = wid & 3;                // 0..3
    const int m0 = blockIdx.x * 128;
    const int n0 = blockIdx.y * 128;

    uint32_t abase[4], bbase[2];
    {
        int arow = (lane & 7) + ((lane >> 3) & 1) * 8;
        int akb  = (lane >> 4) * 16;
        #pragma unroll
        for (int mi = 0; mi < 4; mi++)
            abase[mi] = (uint32_t)(wm * 64 + mi * 16 + arow) * 64 + akb;
        int brow = (lane & 7) + (lane >> 4) * 8;
        int bkb  = ((lane >> 3) & 1) * 16;
        #pragma unroll
        for (int p = 0; p < 2; p++)
            bbase[p] = (uint32_t)(wn * 32 + p * 16 + brow) * 64 + bkb;
    }

    float acc[4][4][4];
    #pragma unroll
    for (int i = 0; i < 4; i++)
        #pragma unroll
        for (int j = 0; j < 4; j++)
            #pragma unroll
            for (int q = 0; q < 4; q++) acc[i][j][q] = 0.f;

    const int arow_ld = tid >> 1;
    const int half_ = tid & 1;
    const bool aok = (m0 + arow_ld) < M;
    const float* aptr = A + (size_t)(m0 + arow_ld) * K + half_ * 16;
    float4 pf[4];

    auto prefA = [&](int c) {
        if (aok) {
            #pragma unroll
            for (int i = 0; i < 4; i++)
                pf[i] = *(const float4*)(aptr + c * 32 + i * 4);
        } else {
            #pragma unroll
            for (int i = 0; i < 4; i++) pf[i] = make_float4(0.f, 0.f, 0.f, 0.f);
        }
    };
    auto storeA = [&](int b) {
        char* dst = sm + b * BUF;
        #pragma unroll
        for (int i = 0; i < 2; i++) {
            uint4 hv, lv;
            split2(pf[2 * i].x,     pf[2 * i].y,     hv.x, lv.x);
            split2(pf[2 * i].z,     pf[2 * i].w,     hv.y, lv.y);
            split2(pf[2 * i + 1].x, pf[2 * i + 1].y, hv.z, lv.z);
            split2(pf[2 * i + 1].z, pf[2 * i + 1].w, hv.w, lv.w);
            uint32_t so = SWZ64((uint32_t)(arow_ld * 64 + half_ * 32 + i * 16));
            *(uint4*)(dst + so)        = hv;
            *(uint4*)(dst + TERM + so) = lv;
        }
    };
    auto cpB = [&](int c, int b) {
        uint32_t d = sb + b * BUF;
        #pragma unroll
        for (int i = 0; i < 2; i++) {
            int v = tid + 256 * i;
            int row = v >> 2, u = v & 3;
            uint32_t so = SWZ64((uint32_t)(row * 64 + u * 16));
            size_t gi = (size_t)(n0 + row) * K + c * 32 + u * 8;
            CPASYNC16(d + 2 * TERM + so, Bh + gi);
            CPASYNC16(d + 3 * TERM + so, Bl + gi);
        }
    };
    auto compute = [&](int b) {
        uint32_t sAh = sb + b * BUF;
        uint32_t sAl = sAh + TERM;
        uint32_t sBH = sAh + 2 * TERM;
        uint32_t sBL = sAh + 3 * TERM;
        #pragma unroll
        for (int ks = 0; ks < 2; ks++) {
            const uint32_t ko = (uint32_t)(ks * 32);
            uint32_t bh[8], bl[8], af[16];
            LDSM4(&bh[0], sBH + SWZ64(bbase[0] + ko));
            LDSM4(&bh[4], sBH + SWZ64(bbase[1] + ko));
            LDSM4(&bl[0], sBL + SWZ64(bbase[0] + ko));
            LDSM4(&bl[4], sBL + SWZ64(bbase[1] + ko));
            #pragma unroll
            for (int mi = 0; mi < 4; mi++)
                LDSM4(&af[mi * 4], sAh + SWZ64(abase[mi] + ko));
            #pragma unroll
            for (int mi = 0; mi < 4; mi++)
                #pragma unroll
                for (int ni = 0; ni < 4; ni++)
                    MMA_BF16(acc[mi][ni], &af[mi * 4], &bh[ni * 2]);
            #pragma unroll
            for (int mi = 0; mi < 4; mi++)
                #pragma unroll
                for (int ni = 0; ni < 4; ni++)
                    MMA_BF16(acc[mi][ni], &af[mi * 4], &bl[ni * 2]);
            #pragma unroll
            for (int mi = 0; mi < 4; mi++)
                LDSM4(&af[mi * 4], sAl + SWZ64(abase[mi] + ko));
            #pragma unroll
            for (int mi = 0; mi < 4; mi++)
                #pragma unroll
                for (int ni = 0; ni < 4; ni++)
                    MMA_BF16(acc[mi][ni], &af[mi * 4], &bh[ni * 2]);
        }
    };

    prefA(0);
    cpB(0, 0);
    CPCOMMIT();
    storeA(0);
    CPWAIT0();
    __syncthreads();

    #pragma unroll
    for (int c = 0; c < 8; c++) {
        int nb = (c + 1) & 1;
        if (c < 7) {
            cpB(c + 1, nb);
            CPCOMMIT();
            prefA(c + 1);
        }
        compute(c & 1);
        if (c < 7) {
            storeA(nb);
            CPWAIT0();
        }
        __syncthreads();
    }

    // epilogue: scale by dis[row], convert to fp16, store
    const int g = lane >> 2;
    const int t = lane & 3;
    #pragma unroll
    for (int mi = 0; mi < 4; mi++) {
        int r0 = m0 + wm * 64 + mi * 16 + g;
        int r1 = r0 + 8;
        float s0 = (r0 < M) ? g_dis[r0] : 0.f;
        float s1 = (r1 < M) ? g_dis[r1] : 0.f;
        #pragma unroll
        for (int ni = 0; ni < 4; ni++) {
            int col = n0 + wn * 32 + ni * 8 + t * 2;
            if (r0 < M)
                *(__half2*)(C + (size_t)r0 * NTOT + col) =
                    __floats2half2_rn(acc[mi][ni][0] * s0, acc[mi][ni][1] * s0);
            if (r1 < M)
                *(__half2*)(C + (size_t)r1 * NTOT + col) =
                    __floats2half2_rn(acc[mi][ni][2] * s1, acc[mi][ni][3] * s1);
        }
    }
}

// ---------------- gather aggregation (fp16 input, fp32 accum/output) ----------------
// out = relu(dis[n]*(self + sum_src) + bias). C8 = channels/8 (32 for HID, 16 for HID2).
// Thread handles 8 halves (16B). 128 threads/block -> 128/C8 nodes per block.
template <int C8>
__global__ __launch_bounds__(128) void agg_kernel_h(
    const __half* __restrict__ hs_, const float* __restrict__ bias_,
    float* __restrict__ out_, int N)
{
    constexpr int NPB = 128 / C8;
    int node = blockIdx.x * NPB + threadIdx.x / C8;
    int c = threadIdx.x % C8;
    if (node >= N) return;
    const uint4* hs = (const uint4*)hs_;
    float dn = g_dis[node];
    int s0 = g_off[node], s1 = g_off[node + 1];

    float acc[8];
    {
        uint4 sv = hs[(size_t)node * C8 + c];          // self-loop
        const __half2* p = (const __half2*)&sv;
        #pragma unroll
        for (int q = 0; q < 4; q++) {
            float2 f = __half22float2(p[q]);
            acc[2 * q] = f.x; acc[2 * q + 1] = f.y;
        }
    }
    int j = s0;
    for (; j + 3 < s1; j += 4) {
        uint4 v0 = hs[(size_t)g_csr[j]     * C8 + c];
        uint4 v1 = hs[(size_t)g_csr[j + 1] * C8 + c];
        uint4 v2 = hs[(size_t)g_csr[j + 2] * C8 + c];
        uint4 v3 = hs[(size_t)g_csr[j + 3] * C8 + c];
        const __half2* p0 = (const __half2*)&v0;
        const __half2* p1 = (const __half2*)&v1;
        const __half2* p2 = (const __half2*)&v2;
        const __half2* p3 = (const __half2*)&v3;
        #pragma unroll
        for (int q = 0; q < 4; q++) {
            float2 f0 = __half22float2(p0[q]);
            float2 f1 = __half22float2(p1[q]);
            float2 f2 = __half22float2(p2[q]);
            float2 f3 = __half22float2(p3[q]);
            acc[2 * q]     += (f0.x + f1.x) + (f2.x + f3.x);
            acc[2 * q + 1] += (f0.y + f1.y) + (f2.y + f3.y);
        }
    }
    for (; j < s1; j++) {
        uint4 v = hs[(size_t)g_csr[j] * C8 + c];
        const __half2* p = (const __half2*)&v;
        #pragma unroll
        for (int q = 0; q < 4; q++) {
            float2 f = __half22float2(p[q]);
            acc[2 * q] += f.x; acc[2 * q + 1] += f.y;
        }
    }
    float4 b0 = ((const float4*)bias_)[c * 2];
    float4 b1 = ((const float4*)bias_)[c * 2 + 1];
    float4 r0, r1;
    r0.x = fmaxf(fmaf(acc[0], dn, b0.x), 0.f);
    r0.y = fmaxf(fmaf(acc[1], dn, b0.y), 0.f);
    r0.z = fmaxf(fmaf(acc[2], dn, b0.z), 0.f);
    r0.w = fmaxf(fmaf(acc[3], dn, b0.w), 0.f);
    r1.x = fmaxf(fmaf(acc[4], dn, b1.x), 0.f);
    r1.y = fmaxf(fmaf(acc[5], dn, b1.y), 0.f);
    r1.z = fmaxf(fmaf(acc[6], dn, b1.z), 0.f);
    r1.w = fmaxf(fmaf(acc[7], dn, b1.w), 0.f);
    ((float4*)out_)[(size_t)node * C8 * 2 + c * 2]     = r0;
    ((float4*)out_)[(size_t)node * C8 * 2 + c * 2 + 1] = r1;
}

// ---------------- global max pool per graph ----------------
__global__ void pool_kernel() {
    int g = blockIdx.x;
    int c = threadIdx.x;          // 0..127
    int a = g_gs[g], b = g_gs[g + 1];
    float m = -3.402823466e38f;
    int n = a;
    for (; n + 3 < b; n += 4) {
        float v0 = g_cx[(size_t)(n + 0) * HID2 + c];
        float v1 = g_cx[(size_t)(n + 1) * HID2 + c];
        float v2 = g_cx[(size_t)(n + 2) * HID2 + c];
        float v3 = g_cx[(size_t)(n + 3) * HID2 + c];
        m = fmaxf(m, fmaxf(fmaxf(v0, v1), fmaxf(v2, v3)));
    }
    for (; n < b; n++) m = fmaxf(m, g_cx[(size_t)n * HID2 + c]);
    g_px[g * HID2 + c] = m;
}

// ---------------- head ----------------
__global__ void head_kernel(const float* __restrict__ Wm, const float* __restrict__ bm,
                            float* __restrict__ out)
{
    int g = blockIdx.x;
    int d = threadIdx.x;          // 0..63
    float acc = bm[d];
    #pragma unroll 8
    for (int k = 0; k < HID2; k++)
        acc = fmaf(g_px[g * HID2 + k], Wm[k * N_DCS + d], acc);
    out[g * N_DCS + d] = acc;
}

// ---------------- launch ----------------
extern "C" void kernel_launch(void* const* d_in, const int* in_sizes, int n_in,
                              void* d_out, int out_size)
{
    const float* x     = (const float*)d_in[0];
    const int*   ei    = (const int*)  d_in[1];
    const int*   batch = (const int*)  d_in[2];
    const float* W1    = (const float*)d_in[3];
    const float* b1    = (const float*)d_in[4];
    const float* W2    = (const float*)d_in[5];
    const float* b2    = (const float*)d_in[6];
    const float* Wm    = (const float*)d_in[7];
    const float* bm    = (const float*)d_in[8];
    float* out = (float*)d_out;

    const int N = in_sizes[2];          // 50000
    const int E = in_sizes[1] / 2;      // 800000
    const int* src = ei;
    const int* dst = ei + E;

    __half *h1, *h2;
    float *bx, *cx;
    __nv_bfloat16 *w1h, *w1l, *w2h, *w2l;
    cudaGetSymbolAddress((void**)&h1, g_h1);
    cudaGetSymbolAddress((void**)&bx, g_bx);
    cudaGetSymbolAddress((void**)&h2, g_h2);
    cudaGetSymbolAddress((void**)&cx, g_cx);
    cudaGetSymbolAddress((void**)&w1h, g_w1h);
    cudaGetSymbolAddress((void**)&w1l, g_w1l);
    cudaGetSymbolAddress((void**)&w2h, g_w2h);
    cudaGetSymbolAddress((void**)&w2l, g_w2l);

    const int TB = 256;
    int gn = (N + TB - 1) / TB;
    int ge = (E + TB - 1) / TB;
    int nb = (N + 1023) / 1024;

    const int SMEM = 2 * 4 * 8192;      // 65536 bytes: double-buffered chunk-32, 2 CTAs/SM
    int mtiles = (N + 127) / 128;
    cudaFuncSetAttribute(mma_gemm_kernel<HID>,
                         cudaFuncAttributeMaxDynamicSharedMemorySize, SMEM);
    cudaFuncSetAttribute(mma_gemm_kernel<HID2>,
                         cudaFuncAttributeMaxDynamicSharedMemorySize, SMEM);

    // L1: prep (zero deg + pack weights)
    prep_kernel<<<ZB + HID + HID2, 256>>>(W1, W2);
    // L2: degree histogram
    hist_kernel<<<ge, TB>>>(dst, E);
    // L3: dis = rsqrt(deg+1)
    dis_kernel<<<gn, TB>>>(N);
    // L4: layer-1 GEMM (profiled position)
    {
        dim3 grid(mtiles, HID / 128);
        mma_gemm_kernel<HID><<<grid, 256, SMEM>>>(x, w1h, w1l, h1, N);
    }
    // L5-L8: CSR build
    scan_block_kernel<<<nb, 1024>>>(N);
    scan_sums_kernel<<<1, 64>>>(nb, N);
    scan_add_kernel<<<gn, TB>>>(N);
    scatter_kernel<<<ge, TB>>>(src, dst, E);
    // L9: graph boundaries
    bounds_kernel<<<gn, TB>>>(batch, N);
    // L10: layer-1 aggregation -> bx (fp32)
    agg_kernel_h<HID / 8><<<(N * (HID / 8) + 127) / 128, 128>>>(h1, b1, bx, N);
    // L11: layer-2 GEMM
    {
        dim3 grid(mtiles, HID2 / 128);
        mma_gemm_kernel<HID2><<<grid, 256, SMEM>>>(bx, w2h, w2l, h2, N);
    }
    // L12: layer-2 aggregation -> cx
    agg_kernel_h<HID2 / 8><<<(N * (HID2 / 8) + 127) / 128, 128>>>(h2, b2, cx, N);
    // L13-L14: pool + head
    pool_kernel<<<N_GRAPHS, HID2>>>();
    head_kernel<<<N_GRAPHS, N_DCS>>>(Wm, bm, out);
}

// round 13
// speedup vs baseline: 1.7654x; 1.0453x over previous
#include <cuda_runtime.h>
#include <cuda_bf16.h>
#include <cuda_fp16.h>
#include <cstdint>
#include <cstddef>

#define N_NODES 50000
#define N_EDGES 800000
#define N_GRAPHS 64
#define IN_C 256
#define HID 256
#define HID2 128
#define N_DCS 64

// ---------------- static device scratch ----------------
__device__ __half g_h1[(size_t)N_NODES * HID];          // (x@W1)*dis, fp16
__device__ __half g_bx[(size_t)N_NODES * HID];          // relu layer1 output fp16
__device__ __half g_h2[(size_t)N_NODES * HID2];         // (bx@W2)*dis, fp16
__device__ float  g_cx[(size_t)N_NODES * HID2];         // relu layer2 output fp32
__device__ __nv_bfloat16 g_w1h[HID * IN_C];
__device__ __nv_bfloat16 g_w1l[HID * IN_C];
__device__ __nv_bfloat16 g_w2h[HID2 * HID];
__device__ __nv_bfloat16 g_w2l[HID2 * HID];
__device__ float g_dis[N_NODES];
__device__ int   g_deg[N_NODES];
__device__ int   g_off[N_NODES + 1];
__device__ int   g_pos[N_NODES];
__device__ int   g_csr[N_EDGES];
__device__ int   g_bsum[64];
__device__ int   g_boff[64];
__device__ int   g_gs[N_GRAPHS + 1];
__device__ float g_px[N_GRAPHS * HID2];

// ---------------- helpers ----------------
__device__ __forceinline__ uint32_t smem_u32(const void* p) {
    uint32_t a;
    asm("{ .reg .u64 t; cvta.to.shared.u64 t, %1; cvt.u32.u64 %0, t; }" : "=r"(a) : "l"(p));
    return a;
}
// SW64 swizzle for 64-byte rows
#define SWZ64(o) ((uint32_t)(o) ^ ((((uint32_t)(o)) >> 3) & 0x30u))

#define MMA_BF16(d, a, b) \
    asm volatile("mma.sync.aligned.m16n8k16.row.col.f32.bf16.bf16.f32 " \
        "{%0,%1,%2,%3}, {%4,%5,%6,%7}, {%8,%9}, {%0,%1,%2,%3};" \
        : "+f"((d)[0]), "+f"((d)[1]), "+f"((d)[2]), "+f"((d)[3]) \
        : "r"((a)[0]), "r"((a)[1]), "r"((a)[2]), "r"((a)[3]), \
          "r"((b)[0]), "r"((b)[1]))

#define LDSM4(r, addr) \
    asm volatile("ldmatrix.sync.aligned.m8n8.x4.shared.b16 {%0,%1,%2,%3}, [%4];" \
        : "=r"((r)[0]), "=r"((r)[1]), "=r"((r)[2]), "=r"((r)[3]) : "r"(addr))

#define CPASYNC16(dst, src) \
    asm volatile("cp.async.cg.shared.global [%0], [%1], 16;" :: "r"(dst), "l"(src))
#define CPCOMMIT() asm volatile("cp.async.commit_group;" ::: "memory")
#define CPWAIT0()  asm volatile("cp.async.wait_group 0;" ::: "memory")

__device__ __forceinline__ void split2(float f0, float f1, uint32_t& h, uint32_t& l) {
    __nv_bfloat162 hp = __floats2bfloat162_rn(f0, f1);
    float2 hf = __bfloat1622float2(hp);
    __nv_bfloat162 lp = __floats2bfloat162_rn(f0 - hf.x, f1 - hf.y);
    h = *reinterpret_cast<uint32_t*>(&hp);
    l = *reinterpret_cast<uint32_t*>(&lp);
}

// ---------------- fused prep: zero g_deg + pack W1/W2 transposed bf16 hi/lo ----------------
#define ZB ((N_NODES + 255) / 256)
__global__ void prep_kernel(const float* __restrict__ W1, const float* __restrict__ W2) {
    int b = blockIdx.x;
    int t = threadIdx.x;                 // 256
    if (b < ZB) {
        int i = b * 256 + t;
        if (i < N_NODES) g_deg[i] = 0;
    } else if (b < ZB + HID) {
        int n = b - ZB;
        float v = W1[(size_t)t * HID + n];
        __nv_bfloat16 h = __float2bfloat16(v);
        g_w1h[(size_t)n * 256 + t] = h;
        g_w1l[(size_t)n * 256 + t] = __float2bfloat16(v - __bfloat162float(h));
    } else {
        int n = b - ZB - HID;
        float v = W2[(size_t)t * HID2 + n];
        __nv_bfloat16 h = __float2bfloat16(v);
        g_w2h[(size_t)n * 256 + t] = h;
        g_w2l[(size_t)n * 256 + t] = __float2bfloat16(v - __bfloat162float(h));
    }
}

__global__ void hist_kernel(const int* __restrict__ dst, int e) {
    int i = blockIdx.x * blockDim.x + threadIdx.x;
    if (i < e) atomicAdd(&g_deg[dst[i]], 1);
}
__global__ void dis_kernel(int n) {
    int i = blockIdx.x * blockDim.x + threadIdx.x;
    if (i < n) g_dis[i] = rsqrtf((float)g_deg[i] + 1.0f);
}
__global__ void scan_block_kernel(int n) {
    __shared__ int sh[1024];
    int tid = threadIdx.x;
    int i = blockIdx.x * 1024 + tid;
    int v = (i < n) ? g_deg[i] : 0;
    sh[tid] = v;
    __syncthreads();
    #pragma unroll
    for (int s = 1; s < 1024; s <<= 1) {
        int t = (tid >= s) ? sh[tid - s] : 0;
        __syncthreads();
        sh[tid] += t;
        __syncthreads();
    }
    if (i < n) g_off[i] = sh[tid] - v;
    if (tid == 1023) g_bsum[blockIdx.x] = sh[1023];
}
__global__ void scan_sums_kernel(int nb, int n) {
    __shared__ int sh[64];
    int tid = threadIdx.x;
    int v = (tid < nb) ? g_bsum[tid] : 0;
    sh[tid] = v;
    __syncthreads();
    #pragma unroll
    for (int s = 1; s < 64; s <<= 1) {
        int t = (tid >= s) ? sh[tid - s] : 0;
        __syncthreads();
        sh[tid] += t;
        __syncthreads();
    }
    if (tid < nb) g_boff[tid] = sh[tid] - v;
    if (tid == nb - 1) g_off[n] = sh[tid];
}
// stage 3 + graph-bounds fused
__global__ void scan_add_kernel(const int* __restrict__ batch, int n) {
    int i = blockIdx.x * blockDim.x + threadIdx.x;
    if (i < n) {
        int o = g_off[i] + g_boff[i >> 10];
        g_off[i] = o;
        g_pos[i] = o;
        if (i == 0) {
            g_gs[N_GRAPHS] = n;
            g_gs[batch[0]] = 0;
        } else if (batch[i] != batch[i - 1]) {
            g_gs[batch[i]] = i;
        }
    }
}
__global__ void scatter_kernel(const int* __restrict__ src, const int* __restrict__ dst, int e) {
    int i = blockIdx.x * blockDim.x + threadIdx.x;
    if (i < e) {
        int d = dst[i];
        int p = atomicAdd(&g_pos[d], 1);
        g_csr[p] = src[i];
    }
}

// ================ pipelined HMMA bf16x3 GEMM, chunk-32 double buffer, 2 CTAs/SM ================
// C[r][c] = (A[r,:]@B[c,:]^T) * g_dis[r], stored fp16.
// A [M,256] row-major, fp32 or fp16 (split to bf16 hi/lo in-kernel, register-staged).
// B = Bh+Bl bf16 [NTOT,256] row-major (pre-transposed weights, cp.async).
// CTA tile MTILE x 128, K=256 in 8 chunks of 32 (SW64-swizzled 64B SMEM rows).
// 8 warps (2 x 4); warp tile (MTILE/2) x 32; m16n8k16; ldmatrix.x4 fragments.
template <int NTOT, int MTILE, typename AT>
__global__ __launch_bounds__(256, 2) void mma_gemm_kernel(
    const AT* __restrict__ A,
    const __nv_bfloat16* __restrict__ Bh, const __nv_bfloat16* __restrict__ Bl,
    __half* __restrict__ C, int M)
{
    constexpr int K = 256;
    constexpr int MI    = MTILE / 32;        // m-fragments per warp (4 or 2)
    constexpr int ATERM = MTILE * 64;        // bytes per A term tile
    constexpr int BTERM = 128 * 64;          // 8192
    constexpr int BUF   = 2 * ATERM + 2 * BTERM;
    constexpr int TPR   = 256 / MTILE;       // threads per A row (2 or 4)
    constexpr int CPT   = 32 / TPR;          // A cols per thread per chunk (16 or 8)

    extern __shared__ char sm[];
    const uint32_t sb = smem_u32(sm);

    const int tid = threadIdx.x;
    const int wid = tid >> 5;
    const int lane = tid & 31;
    const int wm = wid >> 2;               // 0..1
    const int wn = wid & 3;                // 0..3
    const int m0 = blockIdx.x * MTILE;
    const int n0 = blockIdx.y * 128;

    uint32_t abase[MI], bbase[2];
    {
        int arow = (lane & 7) + ((lane >> 3) & 1) * 8;
        int akb  = (lane >> 4) * 16;
        #pragma unroll
        for (int mi = 0; mi < MI; mi++)
            abase[mi] = (uint32_t)(wm * (MTILE / 2) + mi * 16 + arow) * 64 + akb;
        int brow = (lane & 7) + (lane >> 4) * 8;
        int bkb  = ((lane >> 3) & 1) * 16;
        #pragma unroll
        for (int p = 0; p < 2; p++)
            bbase[p] = (uint32_t)(wn * 32 + p * 16 + brow) * 64 + bkb;
    }

    float acc[MI][4][4];
    #pragma unroll
    for (int i = 0; i < MI; i++)
        #pragma unroll
        for (int j = 0; j < 4; j++)
            #pragma unroll
            for (int q = 0; q < 4; q++) acc[i][j][q] = 0.f;

    const int arow_ld = tid / TPR;
    const int part = tid % TPR;
    const bool aok = (m0 + arow_ld) < M;
    const AT* aptr = A + (size_t)(m0 + arow_ld) * K + part * CPT;
    float pfv[CPT];

    auto prefA = [&](int c) {
        if (aok) {
            if constexpr (sizeof(AT) == 4) {
                #pragma unroll
                for (int i = 0; i < CPT / 4; i++) {
                    float4 v = *(const float4*)((const float*)aptr + c * 32 + i * 4);
                    pfv[4 * i] = v.x; pfv[4 * i + 1] = v.y;
                    pfv[4 * i + 2] = v.z; pfv[4 * i + 3] = v.w;
                }
            } else {
                #pragma unroll
                for (int i = 0; i < CPT / 8; i++) {
                    uint4 raw = *(const uint4*)((const __half*)aptr + c * 32 + i * 8);
                    const __half2* hp = (const __half2*)&raw;
                    #pragma unroll
                    for (int q = 0; q < 4; q++) {
                        float2 f = __half22float2(hp[q]);
                        pfv[8 * i + 2 * q] = f.x;
                        pfv[8 * i + 2 * q + 1] = f.y;
                    }
                }
            }
        } else {
            #pragma unroll
            for (int i = 0; i < CPT; i++) pfv[i] = 0.f;
        }
    };
    auto storeA = [&](int b) {
        char* dst = sm + b * BUF;
        #pragma unroll
        for (int i = 0; i < CPT / 8; i++) {
            uint4 hv, lv;
            split2(pfv[8 * i],     pfv[8 * i + 1], hv.x, lv.x);
            split2(pfv[8 * i + 2], pfv[8 * i + 3], hv.y, lv.y);
            split2(pfv[8 * i + 4], pfv[8 * i + 5], hv.z, lv.z);
            split2(pfv[8 * i + 6], pfv[8 * i + 7], hv.w, lv.w);
            uint32_t so = SWZ64((uint32_t)(arow_ld * 64 + part * CPT * 2 + i * 16));
            *(uint4*)(dst + so)         = hv;
            *(uint4*)(dst + ATERM + so) = lv;
        }
    };
    auto cpB = [&](int c, int b) {
        uint32_t d = sb + b * BUF + 2 * ATERM;
        #pragma unroll
        for (int i = 0; i < 2; i++) {
            int v = tid + 256 * i;
            int row = v >> 2, u = v & 3;
            uint32_t so = SWZ64((uint32_t)(row * 64 + u * 16));
            size_t gi = (size_t)(n0 + row) * K + c * 32 + u * 8;
            CPASYNC16(d + so, Bh + gi);
            CPASYNC16(d + BTERM + so, Bl + gi);
        }
    };
    auto compute = [&](int b) {
        uint32_t sAh = sb + b * BUF;
        uint32_t sAl = sAh + ATERM;
        uint32_t sBH = sAh + 2 * ATERM;
        uint32_t sBL = sBH + BTERM;
        #pragma unroll
        for (int ks = 0; ks < 2; ks++) {
            const uint32_t ko = (uint32_t)(ks * 32);
            uint32_t bh[8], bl[8], af[MI * 4];
            LDSM4(&bh[0], sBH + SWZ64(bbase[0] + ko));
            LDSM4(&bh[4], sBH + SWZ64(bbase[1] + ko));
            LDSM4(&bl[0], sBL + SWZ64(bbase[0] + ko));
            LDSM4(&bl[4], sBL + SWZ64(bbase[1] + ko));
            #pragma unroll
            for (int mi = 0; mi < MI; mi++)
                LDSM4(&af[mi * 4], sAh + SWZ64(abase[mi] + ko));
            #pragma unroll
            for (int mi = 0; mi < MI; mi++)
                #pragma unroll
                for (int ni = 0; ni < 4; ni++)
                    MMA_BF16(acc[mi][ni], &af[mi * 4], &bh[ni * 2]);
            #pragma unroll
            for (int mi = 0; mi < MI; mi++)
                #pragma unroll
                for (int ni = 0; ni < 4; ni++)
                    MMA_BF16(acc[mi][ni], &af[mi * 4], &bl[ni * 2]);
            #pragma unroll
            for (int mi = 0; mi < MI; mi++)
                LDSM4(&af[mi * 4], sAl + SWZ64(abase[mi] + ko));
            #pragma unroll
            for (int mi = 0; mi < MI; mi++)
                #pragma unroll
                for (int ni = 0; ni < 4; ni++)
                    MMA_BF16(acc[mi][ni], &af[mi * 4], &bh[ni * 2]);
        }
    };

    prefA(0);
    cpB(0, 0);
    CPCOMMIT();
    storeA(0);
    CPWAIT0();
    __syncthreads();

    #pragma unroll
    for (int c = 0; c < 8; c++) {
        int nb = (c + 1) & 1;
        if (c < 7) {
            cpB(c + 1, nb);
            CPCOMMIT();
            prefA(c + 1);
        }
        compute(c & 1);
        if (c < 7) {
            storeA(nb);
            CPWAIT0();
        }
        __syncthreads();
    }

    // epilogue: scale by dis[row], convert to fp16, store
    const int g = lane >> 2;
    const int t = lane & 3;
    #pragma unroll
    for (int mi = 0; mi < MI; mi++) {
        int r0 = m0 + wm * (MTILE / 2) + mi * 16 + g;
        int r1 = r0 + 8;
        float s0 = (r0 < M) ? g_dis[r0] : 0.f;
        float s1 = (r1 < M) ? g_dis[r1] : 0.f;
        #pragma unroll
        for (int ni = 0; ni < 4; ni++) {
            int col = n0 + wn * 32 + ni * 8 + t * 2;
            if (r0 < M)
                *(__half2*)(C + (size_t)r0 * NTOT + col) =
                    __floats2half2_rn(acc[mi][ni][0] * s0, acc[mi][ni][1] * s0);
            if (r1 < M)
                *(__half2*)(C + (size_t)r1 * NTOT + col) =
                    __floats2half2_rn(acc[mi][ni][2] * s1, acc[mi][ni][3] * s1);
        }
    }
}

// ---------------- gather aggregation (fp16 input, fp32 accum, OT output) ----------------
// out = relu(dis[n]*(self + sum_src) + bias). C8 = channels/8. 128 thr/block.
template <int C8, typename OT>
__global__ __launch_bounds__(128) void agg_kernel_h(
    const __half* __restrict__ hs_, const float* __restrict__ bias_,
    OT* __restrict__ out_, int N)
{
    constexpr int NPB = 128 / C8;
    int node = blockIdx.x * NPB + threadIdx.x / C8;
    int c = threadIdx.x % C8;
    if (node >= N) return;
    const uint4* hs = (const uint4*)hs_;
    float dn = g_dis[node];
    int s0 = g_off[node], s1 = g_off[node + 1];

    float acc[8];
    {
        uint4 sv = hs[(size_t)node * C8 + c];          // self-loop
        const __half2* p = (const __half2*)&sv;
        #pragma unroll
        for (int q = 0; q < 4; q++) {
            float2 f = __half22float2(p[q]);
            acc[2 * q] = f.x; acc[2 * q + 1] = f.y;
        }
    }
    int j = s0;
    for (; j + 3 < s1; j += 4) {
        uint4 v0 = hs[(size_t)g_csr[j]     * C8 + c];
        uint4 v1 = hs[(size_t)g_csr[j + 1] * C8 + c];
        uint4 v2 = hs[(size_t)g_csr[j + 2] * C8 + c];
        uint4 v3 = hs[(size_t)g_csr[j + 3] * C8 + c];
        const __half2* p0 = (const __half2*)&v0;
        const __half2* p1 = (const __half2*)&v1;
        const __half2* p2 = (const __half2*)&v2;
        const __half2* p3 = (const __half2*)&v3;
        #pragma unroll
        for (int q = 0; q < 4; q++) {
            float2 f0 = __half22float2(p0[q]);
            float2 f1 = __half22float2(p1[q]);
            float2 f2 = __half22float2(p2[q]);
            float2 f3 = __half22float2(p3[q]);
            acc[2 * q]     += (f0.x + f1.x) + (f2.x + f3.x);
            acc[2 * q + 1] += (f0.y + f1.y) + (f2.y + f3.y);
        }
    }
    for (; j < s1; j++) {
        uint4 v = hs[(size_t)g_csr[j] * C8 + c];
        const __half2* p = (const __half2*)&v;
        #pragma unroll
        for (int q = 0; q < 4; q++) {
            float2 f = __half22float2(p[q]);
            acc[2 * q] += f.x; acc[2 * q + 1] += f.y;
        }
    }
    float4 b0 = ((const float4*)bias_)[c * 2];
    float4 b1 = ((const float4*)bias_)[c * 2 + 1];
    float o[8];
    o[0] = fmaxf(fmaf(acc[0], dn, b0.x), 0.f);
    o[1] = fmaxf(fmaf(acc[1], dn, b0.y), 0.f);
    o[2] = fmaxf(fmaf(acc[2], dn, b0.z), 0.f);
    o[3] = fmaxf(fmaf(acc[3], dn, b0.w), 0.f);
    o[4] = fmaxf(fmaf(acc[4], dn, b1.x), 0.f);
    o[5] = fmaxf(fmaf(acc[5], dn, b1.y), 0.f);
    o[6] = fmaxf(fmaf(acc[6], dn, b1.z), 0.f);
    o[7] = fmaxf(fmaf(acc[7], dn, b1.w), 0.f);
    if constexpr (sizeof(OT) == 2) {
        uint4 st;
        __half2* hp = (__half2*)&st;
        hp[0] = __floats2half2_rn(o[0], o[1]);
        hp[1] = __floats2half2_rn(o[2], o[3]);
        hp[2] = __floats2half2_rn(o[4], o[5]);
        hp[3] = __floats2half2_rn(o[6], o[7]);
        ((uint4*)out_)[(size_t)node * C8 + c] = st;
    } else {
        ((float4*)out_)[(size_t)node * C8 * 2 + c * 2]     = make_float4(o[0], o[1], o[2], o[3]);
        ((float4*)out_)[(size_t)node * C8 * 2 + c * 2 + 1] = make_float4(o[4], o[5], o[6], o[7]);
    }
}

// ---------------- global max pool per graph ----------------
__global__ void pool_kernel() {
    int g = blockIdx.x;
    int c = threadIdx.x;          // 0..127
    int a = g_gs[g], b = g_gs[g + 1];
    float m = -3.402823466e38f;
    int n = a;
    for (; n + 3 < b; n += 4) {
        float v0 = g_cx[(size_t)(n + 0) * HID2 + c];
        float v1 = g_cx[(size_t)(n + 1) * HID2 + c];
        float v2 = g_cx[(size_t)(n + 2) * HID2 + c];
        float v3 = g_cx[(size_t)(n + 3) * HID2 + c];
        m = fmaxf(m, fmaxf(fmaxf(v0, v1), fmaxf(v2, v3)));
    }
    for (; n < b; n++) m = fmaxf(m, g_cx[(size_t)n * HID2 + c]);
    g_px[g * HID2 + c] = m;
}

// ---------------- head ----------------
__global__ void head_kernel(const float* __restrict__ Wm, const float* __restrict__ bm,
                            float* __restrict__ out)
{
    int g = blockIdx.x;
    int d = threadIdx.x;          // 0..63
    float acc = bm[d];
    #pragma unroll 8
    for (int k = 0; k < HID2; k++)
        acc = fmaf(g_px[g * HID2 + k], Wm[k * N_DCS + d], acc);
    out[g * N_DCS + d] = acc;
}

// ---------------- launch ----------------
extern "C" void kernel_launch(void* const* d_in, const int* in_sizes, int n_in,
                              void* d_out, int out_size)
{
    const float* x     = (const float*)d_in[0];
    const int*   ei    = (const int*)  d_in[1];
    const int*   batch = (const int*)  d_in[2];
    const float* W1    = (const float*)d_in[3];
    const float* b1    = (const float*)d_in[4];
    const float* W2    = (const float*)d_in[5];
    const float* b2    = (const float*)d_in[6];
    const float* Wm    = (const float*)d_in[7];
    const float* bm    = (const float*)d_in[8];
    float* out = (float*)d_out;

    const int N = in_sizes[2];          // 50000
    const int E = in_sizes[1] / 2;      // 800000
    const int* src = ei;
    const int* dst = ei + E;

    __half *h1, *bx, *h2;
    float *cx;
    __nv_bfloat16 *w1h, *w1l, *w2h, *w2l;
    cudaGetSymbolAddress((void**)&h1, g_h1);
    cudaGetSymbolAddress((void**)&bx, g_bx);
    cudaGetSymbolAddress((void**)&h2, g_h2);
    cudaGetSymbolAddress((void**)&cx, g_cx);
    cudaGetSymbolAddress((void**)&w1h, g_w1h);
    cudaGetSymbolAddress((void**)&w1l, g_w1l);
    cudaGetSymbolAddress((void**)&w2h, g_w2h);
    cudaGetSymbolAddress((void**)&w2l, g_w2l);

    const int TB = 256;
    int gn = (N + TB - 1) / TB;
    int ge = (E + TB - 1) / TB;
    int nb = (N + 1023) / 1024;

    // GEMM1: CTA 128x128, double-buffered chunk-32, 2 CTAs/SM
    const int SMEM1 = 2 * (2 * 128 * 64 + 2 * 128 * 64);   // 65536
    // GEMM2: CTA 64x128 (tail-friendly: 782 CTAs)
    const int SMEM2 = 2 * (2 * 64 * 64 + 2 * 128 * 64);    // 49152
    cudaFuncSetAttribute((const void*)mma_gemm_kernel<HID, 128, float>,
                         cudaFuncAttributeMaxDynamicSharedMemorySize, SMEM1);
    cudaFuncSetAttribute((const void*)mma_gemm_kernel<HID2, 64, __half>,
                         cudaFuncAttributeMaxDynamicSharedMemorySize, SMEM2);

    // L1: prep (zero deg + pack weights)
    prep_kernel<<<ZB + HID + HID2, 256>>>(W1, W2);
    // L2: degree histogram
    hist_kernel<<<ge, TB>>>(dst, E);
    // L3: dis = rsqrt(deg+1)
    dis_kernel<<<gn, TB>>>(N);
    // L4: layer-1 GEMM (profiled position)
    {
        dim3 grid((N + 127) / 128, HID / 128);
        mma_gemm_kernel<HID, 128, float><<<grid, 256, SMEM1>>>(x, w1h, w1l, h1, N);
    }
    // L5-L8: CSR build (+ graph bounds fused into scan_add)
    scan_block_kernel<<<nb, 1024>>>(N);
    scan_sums_kernel<<<1, 64>>>(nb, N);
    scan_add_kernel<<<gn, TB>>>(batch, N);
    scatter_kernel<<<ge, TB>>>(src, dst, E);
    // L9: layer-1 aggregation -> bx (fp16)
    agg_kernel_h<HID / 8, __half><<<(N * (HID / 8) + 127) / 128, 128>>>(h1, b1, bx, N);
    // L10: layer-2 GEMM (M-tile 64: 782 CTAs, no 1.3-wave tail)
    {
        dim3 grid((N + 63) / 64, 1);
        mma_gemm_kernel<HID2, 64, __half><<<grid, 256, SMEM2>>>(bx, w2h, w2l, h2, N);
    }
    // L11: layer-2 aggregation -> cx (fp32)
    agg_kernel_h<HID2 / 8, float><<<(N * (HID2 / 8) + 127) / 128, 128>>>(h2, b2, cx, N);
    // L12-L13: pool + head
    pool_kernel<<<N_GRAPHS, HID2>>>();
    head_kernel<<<N_GRAPHS, N_DCS>>>(Wm, bm, out);
}

// round 14
// speedup vs baseline: 1.8282x; 1.0356x over previous
#include <cuda_runtime.h>
#include <cuda_bf16.h>
#include <cuda_fp16.h>
#include <cstdint>
#include <cstddef>

#define N_NODES 50000
#define N_EDGES 800000
#define N_GRAPHS 64
#define IN_C 256
#define HID 256
#define HID2 128
#define N_DCS 64

// ---------------- static device scratch ----------------
__device__ __half g_h1[(size_t)N_NODES * HID];          // (x@W1)*dis, fp16
__device__ __half g_bx[(size_t)N_NODES * HID];          // relu layer1 output fp16
__device__ __half g_h2[(size_t)N_NODES * HID2];         // (bx@W2)*dis, fp16
__device__ float  g_cx[(size_t)N_NODES * HID2];         // relu layer2 output fp32
__device__ __nv_bfloat16 g_w1h[HID * IN_C];
__device__ __nv_bfloat16 g_w1l[HID * IN_C];
__device__ __half g_w2f[HID2 * HID];                    // W2^T packed fp16
__device__ float g_dis[N_NODES];
__device__ int   g_deg[N_NODES];
__device__ int   g_off[N_NODES + 1];
__device__ int   g_pos[N_NODES];
__device__ int   g_csr[N_EDGES];
__device__ int   g_bsum[64];
__device__ int   g_boff[64];
__device__ int   g_gs[N_GRAPHS + 1];
__device__ float g_px[N_GRAPHS * HID2];

// ---------------- helpers ----------------
__device__ __forceinline__ uint32_t smem_u32(const void* p) {
    uint32_t a;
    asm("{ .reg .u64 t; cvta.to.shared.u64 t, %1; cvt.u32.u64 %0, t; }" : "=r"(a) : "l"(p));
    return a;
}
// SW64 swizzle for 64-byte rows
#define SWZ64(o) ((uint32_t)(o) ^ ((((uint32_t)(o)) >> 3) & 0x30u))

#define MMA_BF16(d, a, b) \
    asm volatile("mma.sync.aligned.m16n8k16.row.col.f32.bf16.bf16.f32 " \
        "{%0,%1,%2,%3}, {%4,%5,%6,%7}, {%8,%9}, {%0,%1,%2,%3};" \
        : "+f"((d)[0]), "+f"((d)[1]), "+f"((d)[2]), "+f"((d)[3]) \
        : "r"((a)[0]), "r"((a)[1]), "r"((a)[2]), "r"((a)[3]), \
          "r"((b)[0]), "r"((b)[1]))

#define MMA_F16(d, a, b) \
    asm volatile("mma.sync.aligned.m16n8k16.row.col.f32.f16.f16.f32 " \
        "{%0,%1,%2,%3}, {%4,%5,%6,%7}, {%8,%9}, {%0,%1,%2,%3};" \
        : "+f"((d)[0]), "+f"((d)[1]), "+f"((d)[2]), "+f"((d)[3]) \
        : "r"((a)[0]), "r"((a)[1]), "r"((a)[2]), "r"((a)[3]), \
          "r"((b)[0]), "r"((b)[1]))

#define LDSM4(r, addr) \
    asm volatile("ldmatrix.sync.aligned.m8n8.x4.shared.b16 {%0,%1,%2,%3}, [%4];" \
        : "=r"((r)[0]), "=r"((r)[1]), "=r"((r)[2]), "=r"((r)[3]) : "r"(addr))

#define CPASYNC16(dst, src) \
    asm volatile("cp.async.cg.shared.global [%0], [%1], 16;" :: "r"(dst), "l"(src))
#define CPASYNC16Z(dst, src, sz) \
    asm volatile("cp.async.cg.shared.global [%0], [%1], 16, %2;" :: "r"(dst), "l"(src), "r"(sz))
#define CPCOMMIT() asm volatile("cp.async.commit_group;" ::: "memory")
#define CPWAIT0()  asm volatile("cp.async.wait_group 0;" ::: "memory")

__device__ __forceinline__ void split2(float f0, float f1, uint32_t& h, uint32_t& l) {
    __nv_bfloat162 hp = __floats2bfloat162_rn(f0, f1);
    float2 hf = __bfloat1622float2(hp);
    __nv_bfloat162 lp = __floats2bfloat162_rn(f0 - hf.x, f1 - hf.y);
    h = *reinterpret_cast<uint32_t*>(&hp);
    l = *reinterpret_cast<uint32_t*>(&lp);
}

// ---------------- fused prep: zero g_deg + pack W1 bf16 hi/lo + pack W2 fp16 ----------------
#define ZB ((N_NODES + 255) / 256)
__global__ void prep_kernel(const float* __restrict__ W1, const float* __restrict__ W2) {
    int b = blockIdx.x;
    int t = threadIdx.x;                 // 256
    if (b < ZB) {
        int i = b * 256 + t;
        if (i < N_NODES) g_deg[i] = 0;
    } else if (b < ZB + HID) {
        int n = b - ZB;
        float v = W1[(size_t)t * HID + n];
        __nv_bfloat16 h = __float2bfloat16(v);
        g_w1h[(size_t)n * 256 + t] = h;
        g_w1l[(size_t)n * 256 + t] = __float2bfloat16(v - __bfloat162float(h));
    } else {
        int n = b - ZB - HID;
        g_w2f[(size_t)n * 256 + t] = __float2half(W2[(size_t)t * HID2 + n]);
    }
}

__global__ void hist_kernel(const int* __restrict__ dst, int e) {
    int i = blockIdx.x * blockDim.x + threadIdx.x;
    if (i < e) atomicAdd(&g_deg[dst[i]], 1);
}
// stage 1: local scan + block sum; also computes dis = rsqrt(deg+1)
__global__ void scan_block_kernel(int n) {
    __shared__ int sh[1024];
    int tid = threadIdx.x;
    int i = blockIdx.x * 1024 + tid;
    int v = (i < n) ? g_deg[i] : 0;
    if (i < n) g_dis[i] = rsqrtf((float)v + 1.0f);
    sh[tid] = v;
    __syncthreads();
    #pragma unroll
    for (int s = 1; s < 1024; s <<= 1) {
        int t = (tid >= s) ? sh[tid - s] : 0;
        __syncthreads();
        sh[tid] += t;
        __syncthreads();
    }
    if (i < n) g_off[i] = sh[tid] - v;
    if (tid == 1023) g_bsum[blockIdx.x] = sh[1023];
}
__global__ void scan_sums_kernel(int nb, int n) {
    __shared__ int sh[64];
    int tid = threadIdx.x;
    int v = (tid < nb) ? g_bsum[tid] : 0;
    sh[tid] = v;
    __syncthreads();
    #pragma unroll
    for (int s = 1; s < 64; s <<= 1) {
        int t = (tid >= s) ? sh[tid - s] : 0;
        __syncthreads();
        sh[tid] += t;
        __syncthreads();
    }
    if (tid < nb) g_boff[tid] = sh[tid] - v;
    if (tid == nb - 1) g_off[n] = sh[tid];
}
// stage 3 + graph-bounds fused
__global__ void scan_add_kernel(const int* __restrict__ batch, int n) {
    int i = blockIdx.x * blockDim.x + threadIdx.x;
    if (i < n) {
        int o = g_off[i] + g_boff[i >> 10];
        g_off[i] = o;
        g_pos[i] = o;
        if (i == 0) {
            g_gs[N_GRAPHS] = n;
            g_gs[batch[0]] = 0;
        } else if (batch[i] != batch[i - 1]) {
            g_gs[batch[i]] = i;
        }
    }
}
__global__ void scatter_kernel(const int* __restrict__ src, const int* __restrict__ dst, int e) {
    int i = blockIdx.x * blockDim.x + threadIdx.x;
    if (i < e) {
        int d = dst[i];
        int p = atomicAdd(&g_pos[d], 1);
        g_csr[p] = src[i];
    }
}

// ================ GEMM1: pipelined HMMA bf16x3, chunk-32 double buffer, 2 CTAs/SM ================
// C[r][c] = (A[r,:]@B[c,:]^T) * g_dis[r], stored fp16. A fp32 [M,256] (in-kernel hi/lo split).
template <int NTOT>
__global__ __launch_bounds__(256, 2) void mma_gemm_kernel(
    const float* __restrict__ A,
    const __nv_bfloat16* __restrict__ Bh, const __nv_bfloat16* __restrict__ Bl,
    __half* __restrict__ C, int M)
{
    constexpr int K = 256;
    constexpr int TERM = 128 * 64;         // 8192 bytes
    constexpr int BUF = 4 * TERM;          // 32KB per buffer
    extern __shared__ char sm[];
    const uint32_t sb = smem_u32(sm);

    const int tid = threadIdx.x;
    const int wid = tid >> 5;
    const int lane = tid & 31;
    const int wm = wid >> 2;
    const int wn = wid & 3;
    const int m0 = blockIdx.x * 128;
    const int n0 = blockIdx.y * 128;

    uint32_t abase[4], bbase[2];
    {
        int arow = (lane & 7) + ((lane >> 3) & 1) * 8;
        int akb  = (lane >> 4) * 16;
        #pragma unroll
        for (int mi = 0; mi < 4; mi++)
            abase[mi] = (uint32_t)(wm * 64 + mi * 16 + arow) * 64 + akb;
        int brow = (lane & 7) + (lane >> 4) * 8;
        int bkb  = ((lane >> 3) & 1) * 16;
        #pragma unroll
        for (int p = 0; p < 2; p++)
            bbase[p] = (uint32_t)(wn * 32 + p * 16 + brow) * 64 + bkb;
    }

    float acc[4][4][4];
    #pragma unroll
    for (int i = 0; i < 4; i++)
        #pragma unroll
        for (int j = 0; j < 4; j++)
            #pragma unroll
            for (int q = 0; q < 4; q++) acc[i][j][q] = 0.f;

    const int arow_ld = tid >> 1;
    const int half_ = tid & 1;
    const bool aok = (m0 + arow_ld) < M;
    const float* aptr = A + (size_t)(m0 + arow_ld) * K + half_ * 16;
    float4 pf[4];

    auto prefA = [&](int c) {
        if (aok) {
            #pragma unroll
            for (int i = 0; i < 4; i++)
                pf[i] = *(const float4*)(aptr + c * 32 + i * 4);
        } else {
            #pragma unroll
            for (int i = 0; i < 4; i++) pf[i] = make_float4(0.f, 0.f, 0.f, 0.f);
        }
    };
    auto storeA = [&](int b) {
        char* dst = sm + b * BUF;
        #pragma unroll
        for (int i = 0; i < 2; i++) {
            uint4 hv, lv;
            split2(pf[2 * i].x,     pf[2 * i].y,     hv.x, lv.x);
            split2(pf[2 * i].z,     pf[2 * i].w,     hv.y, lv.y);
            split2(pf[2 * i + 1].x, pf[2 * i + 1].y, hv.z, lv.z);
            split2(pf[2 * i + 1].z, pf[2 * i + 1].w, hv.w, lv.w);
            uint32_t so = SWZ64((uint32_t)(arow_ld * 64 + half_ * 32 + i * 16));
            *(uint4*)(dst + so)        = hv;
            *(uint4*)(dst + TERM + so) = lv;
        }
    };
    auto cpB = [&](int c, int b) {
        uint32_t d = sb + b * BUF;
        #pragma unroll
        for (int i = 0; i < 2; i++) {
            int v = tid + 256 * i;
            int row = v >> 2, u = v & 3;
            uint32_t so = SWZ64((uint32_t)(row * 64 + u * 16));
            size_t gi = (size_t)(n0 + row) * K + c * 32 + u * 8;
            CPASYNC16(d + 2 * TERM + so, Bh + gi);
            CPASYNC16(d + 3 * TERM + so, Bl + gi);
        }
    };
    auto compute = [&](int b) {
        uint32_t sAh = sb + b * BUF;
        uint32_t sAl = sAh + TERM;
        uint32_t sBH = sAh + 2 * TERM;
        uint32_t sBL = sAh + 3 * TERM;
        #pragma unroll
        for (int ks = 0; ks < 2; ks++) {
            const uint32_t ko = (uint32_t)(ks * 32);
            uint32_t bh[8], bl[8], af[16];
            LDSM4(&bh[0], sBH + SWZ64(bbase[0] + ko));
            LDSM4(&bh[4], sBH + SWZ64(bbase[1] + ko));
            LDSM4(&bl[0], sBL + SWZ64(bbase[0] + ko));
            LDSM4(&bl[4], sBL + SWZ64(bbase[1] + ko));
            #pragma unroll
            for (int mi = 0; mi < 4; mi++)
                LDSM4(&af[mi * 4], sAh + SWZ64(abase[mi] + ko));
            #pragma unroll
            for (int mi = 0; mi < 4; mi++)
                #pragma unroll
                for (int ni = 0; ni < 4; ni++)
                    MMA_BF16(acc[mi][ni], &af[mi * 4], &bh[ni * 2]);
            #pragma unroll
            for (int mi = 0; mi < 4; mi++)
                #pragma unroll
                for (int ni = 0; ni < 4; ni++)
                    MMA_BF16(acc[mi][ni], &af[mi * 4], &bl[ni * 2]);
            #pragma unroll
            for (int mi = 0; mi < 4; mi++)
                LDSM4(&af[mi * 4], sAl + SWZ64(abase[mi] + ko));
            #pragma unroll
            for (int mi = 0; mi < 4; mi++)
                #pragma unroll
                for (int ni = 0; ni < 4; ni++)
                    MMA_BF16(acc[mi][ni], &af[mi * 4], &bh[ni * 2]);
        }
    };

    prefA(0);
    cpB(0, 0);
    CPCOMMIT();
    storeA(0);
    CPWAIT0();
    __syncthreads();

    #pragma unroll
    for (int c = 0; c < 8; c++) {
        int nb = (c + 1) & 1;
        if (c < 7) {
            cpB(c + 1, nb);
            CPCOMMIT();
            prefA(c + 1);
        }
        compute(c & 1);
        if (c < 7) {
            storeA(nb);
            CPWAIT0();
        }
        __syncthreads();
    }

    const int g = lane >> 2;
    const int t = lane & 3;
    #pragma unroll
    for (int mi = 0; mi < 4; mi++) {
        int r0 = m0 + wm * 64 + mi * 16 + g;
        int r1 = r0 + 8;
        float s0 = (r0 < M) ? g_dis[r0] : 0.f;
        float s1 = (r1 < M) ? g_dis[r1] : 0.f;
        #pragma unroll
        for (int ni = 0; ni < 4; ni++) {
            int col = n0 + wn * 32 + ni * 8 + t * 2;
            if (r0 < M)
                *(__half2*)(C + (size_t)r0 * NTOT + col) =
                    __floats2half2_rn(acc[mi][ni][0] * s0, acc[mi][ni][1] * s0);
            if (r1 < M)
                *(__half2*)(C + (size_t)r1 * NTOT + col) =
                    __floats2half2_rn(acc[mi][ni][2] * s1, acc[mi][ni][3] * s1);
        }
    }
}

// ================ GEMM2: single-pass fp16 HMMA, chunk-32 double buffer ================
// C[r][c] = (A[r,:]@B[c,:]^T) * g_dis[r], fp16 out. A fp16 [M,256] (cp.async direct).
// CTA tile 64x128. 8 warps (2x4), warp tile 32x32, MI=2.
template <int NTOT, int MTILE>
__global__ __launch_bounds__(256, 2) void mma_gemm_f16_kernel(
    const __half* __restrict__ A, const __half* __restrict__ Bf,
    __half* __restrict__ C, int M)
{
    constexpr int K = 256;
    constexpr int MI = MTILE / 32;           // 2
    constexpr int ATERM = MTILE * 64;        // 4096
    constexpr int BTERM = NTOT * 64;         // 8192
    constexpr int BUF = ATERM + BTERM;       // 12288
    extern __shared__ char sm[];
    const uint32_t sb = smem_u32(sm);

    const int tid = threadIdx.x;
    const int wid = tid >> 5;
    const int lane = tid & 31;
    const int wm = wid >> 2;
    const int wn = wid & 3;
    const int m0 = blockIdx.x * MTILE;

    uint32_t abase[MI], bbase[2];
    {
        int arow = (lane & 7) + ((lane >> 3) & 1) * 8;
        int akb  = (lane >> 4) * 16;
        #pragma unroll
        for (int mi = 0; mi < MI; mi++)
            abase[mi] = (uint32_t)(wm * (MTILE / 2) + mi * 16 + arow) * 64 + akb;
        int brow = (lane & 7) + (lane >> 4) * 8;
        int bkb  = ((lane >> 3) & 1) * 16;
        #pragma unroll
        for (int p = 0; p < 2; p++)
            bbase[p] = (uint32_t)(wn * 32 + p * 16 + brow) * 64 + bkb;
    }

    float acc[MI][4][4];
    #pragma unroll
    for (int i = 0; i < MI; i++)
        #pragma unroll
        for (int j = 0; j < 4; j++)
            #pragma unroll
            for (int q = 0; q < 4; q++) acc[i][j][q] = 0.f;

    // A: MTILE rows x 4 x 16B slots = 256 slots -> 1 per thread (MTILE=64)
    auto cpA = [&](int c, int b) {
        uint32_t d = sb + b * BUF;
        int row = tid >> 2, u = tid & 3;
        uint32_t so = SWZ64((uint32_t)(row * 64 + u * 16));
        size_t gi = (size_t)(m0 + row) * K + c * 32 + u * 8;
        uint32_t sz = ((m0 + row) < M) ? 16u : 0u;     // zero-fill OOB rows
        CPASYNC16Z(d + so, A + gi, sz);
    };
    // B: NTOT rows x 4 slots = 512 slots -> 2 per thread
    auto cpB = [&](int c, int b) {
        uint32_t d = sb + b * BUF + ATERM;
        #pragma unroll
        for (int i = 0; i < 2; i++) {
            int v = tid + 256 * i;
            int row = v >> 2, u = v & 3;
            uint32_t so = SWZ64((uint32_t)(row * 64 + u * 16));
            size_t gi = (size_t)row * K + c * 32 + u * 8;
            CPASYNC16(d + so, Bf + gi);
        }
    };
    auto compute = [&](int b) {
        uint32_t sA = sb + b * BUF;
        uint32_t sB = sA + ATERM;
        #pragma unroll
        for (int ks = 0; ks < 2; ks++) {
            const uint32_t ko = (uint32_t)(ks * 32);
            uint32_t bf[8], af[MI * 4];
            LDSM4(&bf[0], sB + SWZ64(bbase[0] + ko));
            LDSM4(&bf[4], sB + SWZ64(bbase[1] + ko));
            #pragma unroll
            for (int mi = 0; mi < MI; mi++)
                LDSM4(&af[mi * 4], sA + SWZ64(abase[mi] + ko));
            #pragma unroll
            for (int mi = 0; mi < MI; mi++)
                #pragma unroll
                for (int ni = 0; ni < 4; ni++)
                    MMA_F16(acc[mi][ni], &af[mi * 4], &bf[ni * 2]);
        }
    };

    cpA(0, 0);
    cpB(0, 0);
    CPCOMMIT();
    CPWAIT0();
    __syncthreads();

    #pragma unroll
    for (int c = 0; c < 8; c++) {
        int nb = (c + 1) & 1;
        if (c < 7) {
            cpA(c + 1, nb);
            cpB(c + 1, nb);
            CPCOMMIT();
        }
        compute(c & 1);
        if (c < 7) CPWAIT0();
        __syncthreads();
    }

    const int g = lane >> 2;
    const int t = lane & 3;
    #pragma unroll
    for (int mi = 0; mi < MI; mi++) {
        int r0 = m0 + wm * (MTILE / 2) + mi * 16 + g;
        int r1 = r0 + 8;
        float s0 = (r0 < M) ? g_dis[r0] : 0.f;
        float s1 = (r1 < M) ? g_dis[r1] : 0.f;
        #pragma unroll
        for (int ni = 0; ni < 4; ni++) {
            int col = wn * 32 + ni * 8 + t * 2;
            if (r0 < M)
                *(__half2*)(C + (size_t)r0 * NTOT + col) =
                    __floats2half2_rn(acc[mi][ni][0] * s0, acc[mi][ni][1] * s0);
            if (r1 < M)
                *(__half2*)(C + (size_t)r1 * NTOT + col) =
                    __floats2half2_rn(acc[mi][ni][2] * s1, acc[mi][ni][3] * s1);
        }
    }
}

// ---------------- gather aggregation (fp16 input, fp32 accum, OT output) ----------------
template <int C8, typename OT>
__global__ __launch_bounds__(128) void agg_kernel_h(
    const __half* __restrict__ hs_, const float* __restrict__ bias_,
    OT* __restrict__ out_, int N)
{
    constexpr int NPB = 128 / C8;
    int node = blockIdx.x * NPB + threadIdx.x / C8;
    int c = threadIdx.x % C8;
    if (node >= N) return;
    const uint4* hs = (const uint4*)hs_;
    float dn = g_dis[node];
    int s0 = g_off[node], s1 = g_off[node + 1];

    float acc[8];
    {
        uint4 sv = hs[(size_t)node * C8 + c];
        const __half2* p = (const __half2*)&sv;
        #pragma unroll
        for (int q = 0; q < 4; q++) {
            float2 f = __half22float2(p[q]);
            acc[2 * q] = f.x; acc[2 * q + 1] = f.y;
        }
    }
    int j = s0;
    for (; j + 3 < s1; j += 4) {
        uint4 v0 = hs[(size_t)g_csr[j]     * C8 + c];
        uint4 v1 = hs[(size_t)g_csr[j + 1] * C8 + c];
        uint4 v2 = hs[(size_t)g_csr[j + 2] * C8 + c];
        uint4 v3 = hs[(size_t)g_csr[j + 3] * C8 + c];
        const __half2* p0 = (const __half2*)&v0;
        const __half2* p1 = (const __half2*)&v1;
        const __half2* p2 = (const __half2*)&v2;
        const __half2* p3 = (const __half2*)&v3;
        #pragma unroll
        for (int q = 0; q < 4; q++) {
            float2 f0 = __half22float2(p0[q]);
            float2 f1 = __half22float2(p1[q]);
            float2 f2 = __half22float2(p2[q]);
            float2 f3 = __half22float2(p3[q]);
            acc[2 * q]     += (f0.x + f1.x) + (f2.x + f3.x);
            acc[2 * q + 1] += (f0.y + f1.y) + (f2.y + f3.y);
        }
    }
    for (; j < s1; j++) {
        uint4 v = hs[(size_t)g_csr[j] * C8 + c];
        const __half2* p = (const __half2*)&v;
        #pragma unroll
        for (int q = 0; q < 4; q++) {
            float2 f = __half22float2(p[q]);
            acc[2 * q] += f.x; acc[2 * q + 1] += f.y;
        }
    }
    float4 b0 = ((const float4*)bias_)[c * 2];
    float4 b1 = ((const float4*)bias_)[c * 2 + 1];
    float o[8];
    o[0] = fmaxf(fmaf(acc[0], dn, b0.x), 0.f);
    o[1] = fmaxf(fmaf(acc[1], dn, b0.y), 0.f);
    o[2] = fmaxf(fmaf(acc[2], dn, b0.z), 0.f);
    o[3] = fmaxf(fmaf(acc[3], dn, b0.w), 0.f);
    o[4] = fmaxf(fmaf(acc[4], dn, b1.x), 0.f);
    o[5] = fmaxf(fmaf(acc[5], dn, b1.y), 0.f);
    o[6] = fmaxf(fmaf(acc[6], dn, b1.z), 0.f);
    o[7] = fmaxf(fmaf(acc[7], dn, b1.w), 0.f);
    if constexpr (sizeof(OT) == 2) {
        uint4 st;
        __half2* hp = (__half2*)&st;
        hp[0] = __floats2half2_rn(o[0], o[1]);
        hp[1] = __floats2half2_rn(o[2], o[3]);
        hp[2] = __floats2half2_rn(o[4], o[5]);
        hp[3] = __floats2half2_rn(o[6], o[7]);
        ((uint4*)out_)[(size_t)node * C8 + c] = st;
    } else {
        ((float4*)out_)[(size_t)node * C8 * 2 + c * 2]     = make_float4(o[0], o[1], o[2], o[3]);
        ((float4*)out_)[(size_t)node * C8 * 2 + c * 2 + 1] = make_float4(o[4], o[5], o[6], o[7]);
    }
}

// ---------------- global max pool per graph ----------------
__global__ void pool_kernel() {
    int g = blockIdx.x;
    int c = threadIdx.x;          // 0..127
    int a = g_gs[g], b = g_gs[g + 1];
    float m = -3.402823466e38f;
    int n = a;
    for (; n + 3 < b; n += 4) {
        float v0 = g_cx[(size_t)(n + 0) * HID2 + c];
        float v1 = g_cx[(size_t)(n + 1) * HID2 + c];
        float v2 = g_cx[(size_t)(n + 2) * HID2 + c];
        float v3 = g_cx[(size_t)(n + 3) * HID2 + c];
        m = fmaxf(m, fmaxf(fmaxf(v0, v1), fmaxf(v2, v3)));
    }
    for (; n < b; n++) m = fmaxf(m, g_cx[(size_t)n * HID2 + c]);
    g_px[g * HID2 + c] = m;
}

// ---------------- head ----------------
__global__ void head_kernel(const float* __restrict__ Wm, const float* __restrict__ bm,
                            float* __restrict__ out)
{
    int g = blockIdx.x;
    int d = threadIdx.x;          // 0..63
    float acc = bm[d];
    #pragma unroll 8
    for (int k = 0; k < HID2; k++)
        acc = fmaf(g_px[g * HID2 + k], Wm[k * N_DCS + d], acc);
    out[g * N_DCS + d] = acc;
}

// ---------------- launch ----------------
extern "C" void kernel_launch(void* const* d_in, const int* in_sizes, int n_in,
                              void* d_out, int out_size)
{
    const float* x     = (const float*)d_in[0];
    const int*   ei    = (const int*)  d_in[1];
    const int*   batch = (const int*)  d_in[2];
    const float* W1    = (const float*)d_in[3];
    const float* b1    = (const float*)d_in[4];
    const float* W2    = (const float*)d_in[5];
    const float* b2    = (const float*)d_in[6];
    const float* Wm    = (const float*)d_in[7];
    const float* bm    = (const float*)d_in[8];
    float* out = (float*)d_out;

    const int N = in_sizes[2];          // 50000
    const int E = in_sizes[1] / 2;      // 800000
    const int* src = ei;
    const int* dst = ei + E;

    __half *h1, *bx, *h2, *w2f;
    float *cx;
    __nv_bfloat16 *w1h, *w1l;
    cudaGetSymbolAddress((void**)&h1, g_h1);
    cudaGetSymbolAddress((void**)&bx, g_bx);
    cudaGetSymbolAddress((void**)&h2, g_h2);
    cudaGetSymbolAddress((void**)&cx, g_cx);
    cudaGetSymbolAddress((void**)&w1h, g_w1h);
    cudaGetSymbolAddress((void**)&w1l, g_w1l);
    cudaGetSymbolAddress((void**)&w2f, g_w2f);

    const int TB = 256;
    int gn = (N + TB - 1) / TB;
    int ge = (E + TB - 1) / TB;
    int nb = (N + 1023) / 1024;

    const int SMEM1 = 2 * 4 * 8192;                    // 65536 (GEMM1)
    const int SMEM2 = 2 * (64 * 64 + 128 * 64);        // 24576 (GEMM2 fp16)
    cudaFuncSetAttribute((const void*)mma_gemm_kernel<HID>,
                         cudaFuncAttributeMaxDynamicSharedMemorySize, SMEM1);
    cudaFuncSetAttribute((const void*)mma_gemm_f16_kernel<HID2, 64>,
                         cudaFuncAttributeMaxDynamicSharedMemorySize, SMEM2);

    // L1: prep (zero deg + pack weights)
    prep_kernel<<<ZB + HID + HID2, 256>>>(W1, W2);
    // L2: degree histogram
    hist_kernel<<<ge, TB>>>(dst, E);
    // L3: block scan (+ dis fused)
    scan_block_kernel<<<nb, 1024>>>(N);
    // L4: layer-1 GEMM (profiled position)
    {
        dim3 grid((N + 127) / 128, HID / 128);
        mma_gemm_kernel<HID><<<grid, 256, SMEM1>>>(x, w1h, w1l, h1, N);
    }
    // L5-L7: CSR build (+ graph bounds fused into scan_add)
    scan_sums_kernel<<<1, 64>>>(nb, N);
    scan_add_kernel<<<gn, TB>>>(batch, N);
    scatter_kernel<<<ge, TB>>>(src, dst, E);
    // L8: layer-1 aggregation -> bx (fp16)
    agg_kernel_h<HID / 8, __half><<<(N * (HID / 8) + 127) / 128, 128>>>(h1, b1, bx, N);
    // L9: layer-2 GEMM (single-pass fp16)
    mma_gemm_f16_kernel<HID2, 64><<<(N + 63) / 64, 256, SMEM2>>>(bx, w2f, h2, N);
    // L10: layer-2 aggregation -> cx (fp32)
    agg_kernel_h<HID2 / 8, float><<<(N * (HID2 / 8) + 127) / 128, 128>>>(h2, b2, cx, N);
    // L11-L12: pool + head
    pool_kernel<<<N_GRAPHS, HID2>>>();
    head_kernel<<<N_GRAPHS, N_DCS>>>(Wm, bm, out);
}

// round 15
// speedup vs baseline: 2.1576x; 1.1801x over previous
#include <cuda_runtime.h>
#include <cuda_fp16.h>
#include <cstdint>
#include <cstddef>

#define N_NODES 50000
#define N_EDGES 800000
#define N_GRAPHS 64
#define IN_C 256
#define HID 256
#define HID2 128
#define N_DCS 64

// ---------------- static device scratch ----------------
__device__ __half g_h1[(size_t)N_NODES * HID];          // (x@W1)*dis, fp16
__device__ __half g_bx[(size_t)N_NODES * HID];          // relu layer1 output fp16
__device__ __half g_h2[(size_t)N_NODES * HID2];         // (bx@W2)*dis, fp16
__device__ float  g_cx[(size_t)N_NODES * HID2];         // relu layer2 output fp32
__device__ __half g_w1f[HID * IN_C];                    // W1^T packed fp16
__device__ __half g_w2f[HID2 * HID];                    // W2^T packed fp16
__device__ float g_dis[N_NODES];
__device__ int   g_deg[N_NODES];
__device__ int   g_off[N_NODES + 1];
__device__ int   g_pos[N_NODES];
__device__ int   g_csr[N_EDGES];
__device__ int   g_bsum[64];
__device__ int   g_boff[64];
__device__ int   g_gs[N_GRAPHS + 1];
__device__ float g_px[N_GRAPHS * HID2];

// ---------------- helpers ----------------
__device__ __forceinline__ uint32_t smem_u32(const void* p) {
    uint32_t a;
    asm("{ .reg .u64 t; cvta.to.shared.u64 t, %1; cvt.u32.u64 %0, t; }" : "=r"(a) : "l"(p));
    return a;
}
// SW64 swizzle for 64-byte rows
#define SWZ64(o) ((uint32_t)(o) ^ ((((uint32_t)(o)) >> 3) & 0x30u))

#define MMA_F16(d, a, b) \
    asm volatile("mma.sync.aligned.m16n8k16.row.col.f32.f16.f16.f32 " \
        "{%0,%1,%2,%3}, {%4,%5,%6,%7}, {%8,%9}, {%0,%1,%2,%3};" \
        : "+f"((d)[0]), "+f"((d)[1]), "+f"((d)[2]), "+f"((d)[3]) \
        : "r"((a)[0]), "r"((a)[1]), "r"((a)[2]), "r"((a)[3]), \
          "r"((b)[0]), "r"((b)[1]))

#define LDSM4(r, addr) \
    asm volatile("ldmatrix.sync.aligned.m8n8.x4.shared.b16 {%0,%1,%2,%3}, [%4];" \
        : "=r"((r)[0]), "=r"((r)[1]), "=r"((r)[2]), "=r"((r)[3]) : "r"(addr))

#define CPASYNC16(dst, src) \
    asm volatile("cp.async.cg.shared.global [%0], [%1], 16;" :: "r"(dst), "l"(src))
#define CPASYNC16Z(dst, src, sz) \
    asm volatile("cp.async.cg.shared.global [%0], [%1], 16, %2;" :: "r"(dst), "l"(src), "r"(sz))
#define CPCOMMIT() asm volatile("cp.async.commit_group;" ::: "memory")
#define CPWAIT0()  asm volatile("cp.async.wait_group 0;" ::: "memory")

// ---------------- fused prep: zero g_deg + pack W1/W2 transposed fp16 ----------------
#define ZB ((N_NODES + 255) / 256)
__global__ void prep_kernel(const float* __restrict__ W1, const float* __restrict__ W2) {
    int b = blockIdx.x;
    int t = threadIdx.x;                 // 256
    if (b < ZB) {
        int i = b * 256 + t;
        if (i < N_NODES) g_deg[i] = 0;
    } else if (b < ZB + HID) {
        int n = b - ZB;
        g_w1f[(size_t)n * 256 + t] = __float2half(W1[(size_t)t * HID + n]);
    } else {
        int n = b - ZB - HID;
        g_w2f[(size_t)n * 256 + t] = __float2half(W2[(size_t)t * HID2 + n]);
    }
}

__global__ void hist_kernel(const int* __restrict__ dst, int e) {
    int i = blockIdx.x * blockDim.x + threadIdx.x;
    if (i < e) atomicAdd(&g_deg[dst[i]], 1);
}
// stage 1: local scan + block sum; also computes dis = rsqrt(deg+1)
__global__ void scan_block_kernel(int n) {
    __shared__ int sh[1024];
    int tid = threadIdx.x;
    int i = blockIdx.x * 1024 + tid;
    int v = (i < n) ? g_deg[i] : 0;
    if (i < n) g_dis[i] = rsqrtf((float)v + 1.0f);
    sh[tid] = v;
    __syncthreads();
    #pragma unroll
    for (int s = 1; s < 1024; s <<= 1) {
        int t = (tid >= s) ? sh[tid - s] : 0;
        __syncthreads();
        sh[tid] += t;
        __syncthreads();
    }
    if (i < n) g_off[i] = sh[tid] - v;
    if (tid == 1023) g_bsum[blockIdx.x] = sh[1023];
}
__global__ void scan_sums_kernel(int nb, int n) {
    __shared__ int sh[64];
    int tid = threadIdx.x;
    int v = (tid < nb) ? g_bsum[tid] : 0;
    sh[tid] = v;
    __syncthreads();
    #pragma unroll
    for (int s = 1; s < 64; s <<= 1) {
        int t = (tid >= s) ? sh[tid - s] : 0;
        __syncthreads();
        sh[tid] += t;
        __syncthreads();
    }
    if (tid < nb) g_boff[tid] = sh[tid] - v;
    if (tid == nb - 1) g_off[n] = sh[tid];
}
// stage 3 + graph-bounds fused
__global__ void scan_add_kernel(const int* __restrict__ batch, int n) {
    int i = blockIdx.x * blockDim.x + threadIdx.x;
    if (i < n) {
        int o = g_off[i] + g_boff[i >> 10];
        g_off[i] = o;
        g_pos[i] = o;
        if (i == 0) {
            g_gs[N_GRAPHS] = n;
            g_gs[batch[0]] = 0;
        } else if (batch[i] != batch[i - 1]) {
            g_gs[batch[i]] = i;
        }
    }
}
__global__ void scatter_kernel(const int* __restrict__ src, const int* __restrict__ dst, int e) {
    int i = blockIdx.x * blockDim.x + threadIdx.x;
    if (i < e) {
        int d = dst[i];
        int p = atomicAdd(&g_pos[d], 1);
        g_csr[p] = src[i];
    }
}

// ================ single-pass fp16 HMMA GEMM, chunk-32 double buffer, 2 CTAs/SM ================
// C[r][c] = (A[r,:]@B[c,:]^T) * g_dis[r], fp16 out.
// A [M,256] row-major: fp32 (LDG + convert + STS, register-staged) or fp16 (cp.async direct).
// Bf fp16 [NTOT,256] row-major (pre-transposed weights, cp.async; tiled by n0 when NTOT>128).
// CTA tile MTILE x 128, K=256 in 8 chunks of 32 (SW64-swizzled 64B SMEM rows).
// 8 warps (2x4); warp tile (MTILE/2) x 32; m16n8k16; ldmatrix.x4 fragments.
template <int NTOT, int MTILE, typename AT>
__global__ __launch_bounds__(256, 2) void gemm_f16_kernel(
    const AT* __restrict__ A, const __half* __restrict__ Bf,
    __half* __restrict__ C, int M)
{
    constexpr int K = 256;
    constexpr int MI    = MTILE / 32;        // 4 (MTILE=128) or 2 (64)
    constexpr int ATERM = MTILE * 64;        // bytes per A chunk tile
    constexpr int BTERM = 128 * 64;          // 8192
    constexpr int BUF   = ATERM + BTERM;
    constexpr int TPR   = 256 / MTILE;       // threads per A row (fp32 path)
    constexpr int CPT   = 32 / TPR;          // A cols per thread per chunk

    extern __shared__ char sm[];
    const uint32_t sb = smem_u32(sm);

    const int tid = threadIdx.x;
    const int wid = tid >> 5;
    const int lane = tid & 31;
    const int wm = wid >> 2;
    const int wn = wid & 3;
    const int m0 = blockIdx.x * MTILE;
    const int n0 = blockIdx.y * 128;

    uint32_t abase[MI], bbase[2];
    {
        int arow = (lane & 7) + ((lane >> 3) & 1) * 8;
        int akb  = (lane >> 4) * 16;
        #pragma unroll
        for (int mi = 0; mi < MI; mi++)
            abase[mi] = (uint32_t)(wm * (MTILE / 2) + mi * 16 + arow) * 64 + akb;
        int brow = (lane & 7) + (lane >> 4) * 8;
        int bkb  = ((lane >> 3) & 1) * 16;
        #pragma unroll
        for (int p = 0; p < 2; p++)
            bbase[p] = (uint32_t)(wn * 32 + p * 16 + brow) * 64 + bkb;
    }

    float acc[MI][4][4];
    #pragma unroll
    for (int i = 0; i < MI; i++)
        #pragma unroll
        for (int j = 0; j < 4; j++)
            #pragma unroll
            for (int q = 0; q < 4; q++) acc[i][j][q] = 0.f;

    // fp32-A path register staging
    const int arow_ld = tid / TPR;
    const int part = tid % TPR;
    const bool aok = (m0 + arow_ld) < M;
    float pfv[CPT];

    auto prefA = [&](int c) {
        if constexpr (sizeof(AT) == 4) {
            if (aok) {
                const float* ap = (const float*)A + (size_t)(m0 + arow_ld) * K + part * CPT;
                #pragma unroll
                for (int i = 0; i < CPT / 4; i++) {
                    float4 v = *(const float4*)(ap + c * 32 + i * 4);
                    pfv[4 * i] = v.x; pfv[4 * i + 1] = v.y;
                    pfv[4 * i + 2] = v.z; pfv[4 * i + 3] = v.w;
                }
            } else {
                #pragma unroll
                for (int i = 0; i < CPT; i++) pfv[i] = 0.f;
            }
        }
    };
    auto storeA = [&](int b) {
        if constexpr (sizeof(AT) == 4) {
            char* dst = sm + b * BUF;
            #pragma unroll
            for (int i = 0; i < CPT / 8; i++) {
                uint4 hv;
                __half2* hp = (__half2*)&hv;
                hp[0] = __floats2half2_rn(pfv[8 * i],     pfv[8 * i + 1]);
                hp[1] = __floats2half2_rn(pfv[8 * i + 2], pfv[8 * i + 3]);
                hp[2] = __floats2half2_rn(pfv[8 * i + 4], pfv[8 * i + 5]);
                hp[3] = __floats2half2_rn(pfv[8 * i + 6], pfv[8 * i + 7]);
                uint32_t so = SWZ64((uint32_t)(arow_ld * 64 + part * CPT * 2 + i * 16));
                *(uint4*)(dst + so) = hv;
            }
        }
    };
    // fp16-A path: cp.async direct (MTILE*4 slots of 16B)
    auto cpA = [&](int c, int b) {
        if constexpr (sizeof(AT) == 2) {
            uint32_t d = sb + b * BUF;
            constexpr int NS = (MTILE * 4) / 256;     // slots per thread
            #pragma unroll
            for (int i = 0; i < NS; i++) {
                int v = tid + 256 * i;
                int row = v >> 2, u = v & 3;
                uint32_t so = SWZ64((uint32_t)(row * 64 + u * 16));
                size_t gi = (size_t)(m0 + row) * K + c * 32 + u * 8;
                uint32_t sz = ((m0 + row) < M) ? 16u : 0u;
                CPASYNC16Z(d + so, (const __half*)A + gi, sz);
            }
        }
    };
    auto cpB = [&](int c, int b) {
        uint32_t d = sb + b * BUF + ATERM;
        #pragma unroll
        for (int i = 0; i < 2; i++) {
            int v = tid + 256 * i;
            int row = v >> 2, u = v & 3;
            uint32_t so = SWZ64((uint32_t)(row * 64 + u * 16));
            size_t gi = (size_t)(n0 + row) * K + c * 32 + u * 8;
            CPASYNC16(d + so, Bf + gi);
        }
    };
    auto compute = [&](int b) {
        uint32_t sA = sb + b * BUF;
        uint32_t sB = sA + ATERM;
        #pragma unroll
        for (int ks = 0; ks < 2; ks++) {
            const uint32_t ko = (uint32_t)(ks * 32);
            uint32_t bf[8], af[MI * 4];
            LDSM4(&bf[0], sB + SWZ64(bbase[0] + ko));
            LDSM4(&bf[4], sB + SWZ64(bbase[1] + ko));
            #pragma unroll
            for (int mi = 0; mi < MI; mi++)
                LDSM4(&af[mi * 4], sA + SWZ64(abase[mi] + ko));
            #pragma unroll
            for (int mi = 0; mi < MI; mi++)
                #pragma unroll
                for (int ni = 0; ni < 4; ni++)
                    MMA_F16(acc[mi][ni], &af[mi * 4], &bf[ni * 2]);
        }
    };

    // prologue
    prefA(0);
    cpA(0, 0);
    cpB(0, 0);
    CPCOMMIT();
    storeA(0);
    CPWAIT0();
    __syncthreads();

    #pragma unroll
    for (int c = 0; c < 8; c++) {
        int nb = (c + 1) & 1;
        if (c < 7) {
            cpA(c + 1, nb);
            cpB(c + 1, nb);
            CPCOMMIT();
            prefA(c + 1);
        }
        compute(c & 1);
        if (c < 7) {
            storeA(nb);
            CPWAIT0();
        }
        __syncthreads();
    }

    // epilogue: scale by dis[row], convert to fp16, store
    const int g = lane >> 2;
    const int t = lane & 3;
    #pragma unroll
    for (int mi = 0; mi < MI; mi++) {
        int r0 = m0 + wm * (MTILE / 2) + mi * 16 + g;
        int r1 = r0 + 8;
        float s0 = (r0 < M) ? g_dis[r0] : 0.f;
        float s1 = (r1 < M) ? g_dis[r1] : 0.f;
        #pragma unroll
        for (int ni = 0; ni < 4; ni++) {
            int col = n0 + wn * 32 + ni * 8 + t * 2;
            if (r0 < M)
                *(__half2*)(C + (size_t)r0 * NTOT + col) =
                    __floats2half2_rn(acc[mi][ni][0] * s0, acc[mi][ni][1] * s0);
            if (r1 < M)
                *(__half2*)(C + (size_t)r1 * NTOT + col) =
                    __floats2half2_rn(acc[mi][ni][2] * s1, acc[mi][ni][3] * s1);
        }
    }
}

// ---------------- gather aggregation (fp16 input, fp32 accum, OT output) ----------------
template <int C8, typename OT>
__global__ __launch_bounds__(128) void agg_kernel_h(
    const __half* __restrict__ hs_, const float* __restrict__ bias_,
    OT* __restrict__ out_, int N)
{
    constexpr int NPB = 128 / C8;
    int node = blockIdx.x * NPB + threadIdx.x / C8;
    int c = threadIdx.x % C8;
    if (node >= N) return;
    const uint4* hs = (const uint4*)hs_;
    float dn = g_dis[node];
    int s0 = g_off[node], s1 = g_off[node + 1];

    float acc[8];
    {
        uint4 sv = hs[(size_t)node * C8 + c];
        const __half2* p = (const __half2*)&sv;
        #pragma unroll
        for (int q = 0; q < 4; q++) {
            float2 f = __half22float2(p[q]);
            acc[2 * q] = f.x; acc[2 * q + 1] = f.y;
        }
    }
    int j = s0;
    for (; j + 3 < s1; j += 4) {
        uint4 v0 = hs[(size_t)g_csr[j]     * C8 + c];
        uint4 v1 = hs[(size_t)g_csr[j + 1] * C8 + c];
        uint4 v2 = hs[(size_t)g_csr[j + 2] * C8 + c];
        uint4 v3 = hs[(size_t)g_csr[j + 3] * C8 + c];
        const __half2* p0 = (const __half2*)&v0;
        const __half2* p1 = (const __half2*)&v1;
        const __half2* p2 = (const __half2*)&v2;
        const __half2* p3 = (const __half2*)&v3;
        #pragma unroll
        for (int q = 0; q < 4; q++) {
            float2 f0 = __half22float2(p0[q]);
            float2 f1 = __half22float2(p1[q]);
            float2 f2 = __half22float2(p2[q]);
            float2 f3 = __half22float2(p3[q]);
            acc[2 * q]     += (f0.x + f1.x) + (f2.x + f3.x);
            acc[2 * q + 1] += (f0.y + f1.y) + (f2.y + f3.y);
        }
    }
    for (; j < s1; j++) {
        uint4 v = hs[(size_t)g_csr[j] * C8 + c];
        const __half2* p = (const __half2*)&v;
        #pragma unroll
        for (int q = 0; q < 4; q++) {
            float2 f = __half22float2(p[q]);
            acc[2 * q] += f.x; acc[2 * q + 1] += f.y;
        }
    }
    float4 b0 = ((const float4*)bias_)[c * 2];
    float4 b1 = ((const float4*)bias_)[c * 2 + 1];
    float o[8];
    o[0] = fmaxf(fmaf(acc[0], dn, b0.x), 0.f);
    o[1] = fmaxf(fmaf(acc[1], dn, b0.y), 0.f);
    o[2] = fmaxf(fmaf(acc[2], dn, b0.z), 0.f);
    o[3] = fmaxf(fmaf(acc[3], dn, b0.w), 0.f);
    o[4] = fmaxf(fmaf(acc[4], dn, b1.x), 0.f);
    o[5] = fmaxf(fmaf(acc[5], dn, b1.y), 0.f);
    o[6] = fmaxf(fmaf(acc[6], dn, b1.z), 0.f);
    o[7] = fmaxf(fmaf(acc[7], dn, b1.w), 0.f);
    if constexpr (sizeof(OT) == 2) {
        uint4 st;
        __half2* hp = (__half2*)&st;
        hp[0] = __floats2half2_rn(o[0], o[1]);
        hp[1] = __floats2half2_rn(o[2], o[3]);
        hp[2] = __floats2half2_rn(o[4], o[5]);
        hp[3] = __floats2half2_rn(o[6], o[7]);
        ((uint4*)out_)[(size_t)node * C8 + c] = st;
    } else {
        ((float4*)out_)[(size_t)node * C8 * 2 + c * 2]     = make_float4(o[0], o[1], o[2], o[3]);
        ((float4*)out_)[(size_t)node * C8 * 2 + c * 2 + 1] = make_float4(o[4], o[5], o[6], o[7]);
    }
}

// ---------------- global max pool per graph ----------------
__global__ void pool_kernel() {
    int g = blockIdx.x;
    int c = threadIdx.x;          // 0..127
    int a = g_gs[g], b = g_gs[g + 1];
    float m = -3.402823466e38f;
    int n = a;
    for (; n + 3 < b; n += 4) {
        float v0 = g_cx[(size_t)(n + 0) * HID2 + c];
        float v1 = g_cx[(size_t)(n + 1) * HID2 + c];
        float v2 = g_cx[(size_t)(n + 2) * HID2 + c];
        float v3 = g_cx[(size_t)(n + 3) * HID2 + c];
        m = fmaxf(m, fmaxf(fmaxf(v0, v1), fmaxf(v2, v3)));
    }
    for (; n < b; n++) m = fmaxf(m, g_cx[(size_t)n * HID2 + c]);
    g_px[g * HID2 + c] = m;
}

// ---------------- head ----------------
__global__ void head_kernel(const float* __restrict__ Wm, const float* __restrict__ bm,
                            float* __restrict__ out)
{
    int g = blockIdx.x;
    int d = threadIdx.x;          // 0..63
    float acc = bm[d];
    #pragma unroll 8
    for (int k = 0; k < HID2; k++)
        acc = fmaf(g_px[g * HID2 + k], Wm[k * N_DCS + d], acc);
    out[g * N_DCS + d] = acc;
}

// ---------------- launch ----------------
extern "C" void kernel_launch(void* const* d_in, const int* in_sizes, int n_in,
                              void* d_out, int out_size)
{
    const float* x     = (const float*)d_in[0];
    const int*   ei    = (const int*)  d_in[1];
    const int*   batch = (const int*)  d_in[2];
    const float* W1    = (const float*)d_in[3];
    const float* b1    = (const float*)d_in[4];
    const float* W2    = (const float*)d_in[5];
    const float* b2    = (const float*)d_in[6];
    const float* Wm    = (const float*)d_in[7];
    const float* bm    = (const float*)d_in[8];
    float* out = (float*)d_out;

    const int N = in_sizes[2];          // 50000
    const int E = in_sizes[1] / 2;      // 800000
    const int* src = ei;
    const int* dst = ei + E;

    __half *h1, *bx, *h2, *w1f, *w2f;
    float *cx;
    cudaGetSymbolAddress((void**)&h1, g_h1);
    cudaGetSymbolAddress((void**)&bx, g_bx);
    cudaGetSymbolAddress((void**)&h2, g_h2);
    cudaGetSymbolAddress((void**)&cx, g_cx);
    cudaGetSymbolAddress((void**)&w1f, g_w1f);
    cudaGetSymbolAddress((void**)&w2f, g_w2f);

    const int TB = 256;
    int gn = (N + TB - 1) / TB;
    int ge = (E + TB - 1) / TB;
    int nb = (N + 1023) / 1024;

    const int SMEM1 = 2 * (128 * 64 + 128 * 64);   // 32768 (GEMM1: fp32 A, MTILE=128)
    const int SMEM2 = 2 * (64 * 64 + 128 * 64);    // 24576 (GEMM2: fp16 A, MTILE=64)
    cudaFuncSetAttribute((const void*)gemm_f16_kernel<HID, 128, float>,
                         cudaFuncAttributeMaxDynamicSharedMemorySize, SMEM1);
    cudaFuncSetAttribute((const void*)gemm_f16_kernel<HID2, 64, __half>,
                         cudaFuncAttributeMaxDynamicSharedMemorySize, SMEM2);

    // L1: prep (zero deg + pack weights fp16)
    prep_kernel<<<ZB + HID + HID2, 256>>>(W1, W2);
    // L2: degree histogram
    hist_kernel<<<ge, TB>>>(dst, E);
    // L3: block scan (+ dis fused)
    scan_block_kernel<<<nb, 1024>>>(N);
    // L4: layer-1 GEMM, single-pass fp16 (profiled position)
    {
        dim3 grid((N + 127) / 128, HID / 128);
        gemm_f16_kernel<HID, 128, float><<<grid, 256, SMEM1>>>(x, w1f, h1, N);
    }
    // L5-L7: CSR build (+ graph bounds fused into scan_add)
    scan_sums_kernel<<<1, 64>>>(nb, N);
    scan_add_kernel<<<gn, TB>>>(batch, N);
    scatter_kernel<<<ge, TB>>>(src, dst, E);
    // L8: layer-1 aggregation -> bx (fp16)
    agg_kernel_h<HID / 8, __half><<<(N * (HID / 8) + 127) / 128, 128>>>(h1, b1, bx, N);
    // L9: layer-2 GEMM (fp16, M-tile 64)
    gemm_f16_kernel<HID2, 64, __half><<<(N + 63) / 64, 256, SMEM2>>>(bx, w2f, h2, N);
    // L10: layer-2 aggregation -> cx (fp32)
    agg_kernel_h<HID2 / 8, float><<<(N * (HID2 / 8) + 127) / 128, 128>>>(h2, b2, cx, N);
    // L11-L12: pool + head
    pool_kernel<<<N_GRAPHS, HID2>>>();
    head_kernel<<<N_GRAPHS, N_DCS>>>(Wm, bm, out);
}

// round 16
// speedup vs baseline: 2.2786x; 1.0561x over previous
#include <cuda_runtime.h>
#include <cuda_fp16.h>
#include <cstdint>
#include <cstddef>

#define N_NODES 50000
#define N_EDGES 800000
#define N_GRAPHS 64
#define IN_C 256
#define HID 256
#define HID2 128
#define N_DCS 64

// ---------------- static device scratch ----------------
__device__ __half g_h1[(size_t)N_NODES * HID];          // (x@W1)*dis, fp16
__device__ __half g_bx[(size_t)N_NODES * HID];          // relu layer1 output fp16
__device__ __half g_h2[(size_t)N_NODES * HID2];         // (bx@W2)*dis, fp16
__device__ float  g_cx[(size_t)N_NODES * HID2];         // relu layer2 output fp32
__device__ __half g_w1f[HID * IN_C];                    // W1^T packed fp16
__device__ __half g_w2f[HID2 * HID];                    // W2^T packed fp16
__device__ float g_dis[N_NODES];
__device__ int   g_deg[N_NODES];
__device__ int   g_off[N_NODES + 1];
__device__ int   g_pos[N_NODES];
__device__ int   g_csr[N_EDGES];
__device__ int   g_bsum[64];
__device__ int   g_boff[64];
__device__ int   g_gs[N_GRAPHS + 1];
__device__ float g_px[N_GRAPHS * HID2];

// ---------------- helpers ----------------
__device__ __forceinline__ uint32_t smem_u32(const void* p) {
    uint32_t a;
    asm("{ .reg .u64 t; cvta.to.shared.u64 t, %1; cvt.u32.u64 %0, t; }" : "=r"(a) : "l"(p));
    return a;
}
// SW64 swizzle for 64-byte rows
#define SWZ64(o) ((uint32_t)(o) ^ ((((uint32_t)(o)) >> 3) & 0x30u))

#define MMA_F16(d, a, b) \
    asm volatile("mma.sync.aligned.m16n8k16.row.col.f32.f16.f16.f32 " \
        "{%0,%1,%2,%3}, {%4,%5,%6,%7}, {%8,%9}, {%0,%1,%2,%3};" \
        : "+f"((d)[0]), "+f"((d)[1]), "+f"((d)[2]), "+f"((d)[3]) \
        : "r"((a)[0]), "r"((a)[1]), "r"((a)[2]), "r"((a)[3]), \
          "r"((b)[0]), "r"((b)[1]))

#define LDSM4(r, addr) \
    asm volatile("ldmatrix.sync.aligned.m8n8.x4.shared.b16 {%0,%1,%2,%3}, [%4];" \
        : "=r"((r)[0]), "=r"((r)[1]), "=r"((r)[2]), "=r"((r)[3]) : "r"(addr))

#define CPASYNC16(dst, src) \
    asm volatile("cp.async.cg.shared.global [%0], [%1], 16;" :: "r"(dst), "l"(src))
#define CPASYNC16Z(dst, src, sz) \
    asm volatile("cp.async.cg.shared.global [%0], [%1], 16, %2;" :: "r"(dst), "l"(src), "r"(sz))
#define CPCOMMIT() asm volatile("cp.async.commit_group;" ::: "memory")
#define CPWAIT0()  asm volatile("cp.async.wait_group 0;" ::: "memory")

// ---------------- fused prep: zero g_deg + pack W1/W2 transposed fp16 ----------------
#define ZB ((N_NODES + 255) / 256)
__global__ void prep_kernel(const float* __restrict__ W1, const float* __restrict__ W2) {
    int b = blockIdx.x;
    int t = threadIdx.x;                 // 256
    if (b < ZB) {
        int i = b * 256 + t;
        if (i < N_NODES) g_deg[i] = 0;
    } else if (b < ZB + HID) {
        int n = b - ZB;
        g_w1f[(size_t)n * 256 + t] = __float2half(W1[(size_t)t * HID + n]);
    } else {
        int n = b - ZB - HID;
        g_w2f[(size_t)n * 256 + t] = __float2half(W2[(size_t)t * HID2 + n]);
    }
}

__global__ void hist_kernel(const int* __restrict__ dst, int e) {
    int i = blockIdx.x * blockDim.x + threadIdx.x;
    if (i < e) atomicAdd(&g_deg[dst[i]], 1);
}
// stage 1: local scan + block sum; also computes dis = rsqrt(deg+1)
__global__ void scan_block_kernel(int n) {
    __shared__ int sh[1024];
    int tid = threadIdx.x;
    int i = blockIdx.x * 1024 + tid;
    int v = (i < n) ? g_deg[i] : 0;
    if (i < n) g_dis[i] = rsqrtf((float)v + 1.0f);
    sh[tid] = v;
    __syncthreads();
    #pragma unroll
    for (int s = 1; s < 1024; s <<= 1) {
        int t = (tid >= s) ? sh[tid - s] : 0;
        __syncthreads();
        sh[tid] += t;
        __syncthreads();
    }
    if (i < n) g_off[i] = sh[tid] - v;
    if (tid == 1023) g_bsum[blockIdx.x] = sh[1023];
}
__global__ void scan_sums_kernel(int nb, int n) {
    __shared__ int sh[64];
    int tid = threadIdx.x;
    int v = (tid < nb) ? g_bsum[tid] : 0;
    sh[tid] = v;
    __syncthreads();
    #pragma unroll
    for (int s = 1; s < 64; s <<= 1) {
        int t = (tid >= s) ? sh[tid - s] : 0;
        __syncthreads();
        sh[tid] += t;
        __syncthreads();
    }
    if (tid < nb) g_boff[tid] = sh[tid] - v;
    if (tid == nb - 1) g_off[n] = sh[tid];
}
// stage 3 + graph-bounds fused
__global__ void scan_add_kernel(const int* __restrict__ batch, int n) {
    int i = blockIdx.x * blockDim.x + threadIdx.x;
    if (i < n) {
        int o = g_off[i] + g_boff[i >> 10];
        g_off[i] = o;
        g_pos[i] = o;
        if (i == 0) {
            g_gs[N_GRAPHS] = n;
            g_gs[batch[0]] = 0;
        } else if (batch[i] != batch[i - 1]) {
            g_gs[batch[i]] = i;
        }
    }
}
__global__ void scatter_kernel(const int* __restrict__ src, const int* __restrict__ dst, int e) {
    int i = blockIdx.x * blockDim.x + threadIdx.x;
    if (i < e) {
        int d = dst[i];
        int p = atomicAdd(&g_pos[d], 1);
        g_csr[p] = src[i];
    }
}

// ================ single-pass fp16 HMMA GEMM, full-N CTA tile, chunk-32 double buffer ================
// C[r][c] = (A[r,:]@B[c,:]^T) * g_dis[r], fp16 out.
// A [M,256] row-major: fp32 (LDG + convert + STS, register-staged) or fp16 (cp.async direct).
// Bf fp16 [NTOT,256] row-major (pre-transposed weights, cp.async; full NTOT per CTA -> A read ONCE).
// CTA tile MTILE x NTOT, K=256 in 8 chunks of 32 (SW64-swizzled 64B SMEM rows).
// 8 warps (2 x 4); warp tile (MTILE/2) x (NTOT/4); m16n8k16; ldmatrix.x4 fragments.
template <int NTOT, int MTILE, typename AT>
__global__ __launch_bounds__(256, 2) void gemm_f16_kernel(
    const AT* __restrict__ A, const __half* __restrict__ Bf,
    __half* __restrict__ C, int M)
{
    constexpr int K = 256;
    constexpr int MI    = MTILE / 32;        // m-fragments per warp
    constexpr int NI    = NTOT / 32;         // n-fragments per warp (8 for 256, 4 for 128)
    constexpr int NB    = NI / 2;            // B ldmatrix.x4 per ks-step
    constexpr int ATERM = MTILE * 64;        // bytes per A chunk tile (fp16)
    constexpr int BTERM = NTOT * 64;
    constexpr int BUF   = ATERM + BTERM;
    constexpr int TPR   = 256 / MTILE;       // threads per A row (fp32 path)
    constexpr int CPT   = 32 / TPR;          // A cols per thread per chunk

    extern __shared__ char sm[];
    const uint32_t sb = smem_u32(sm);

    const int tid = threadIdx.x;
    const int wid = tid >> 5;
    const int lane = tid & 31;
    const int wm = wid >> 2;                 // 0..1
    const int wn = wid & 3;                  // 0..3
    const int m0 = blockIdx.x * MTILE;

    uint32_t abase[MI], bbase[NB];
    {
        int arow = (lane & 7) + ((lane >> 3) & 1) * 8;
        int akb  = (lane >> 4) * 16;
        #pragma unroll
        for (int mi = 0; mi < MI; mi++)
            abase[mi] = (uint32_t)(wm * (MTILE / 2) + mi * 16 + arow) * 64 + akb;
        int brow = (lane & 7) + (lane >> 4) * 8;
        int bkb  = ((lane >> 3) & 1) * 16;
        #pragma unroll
        for (int p = 0; p < NB; p++)
            bbase[p] = (uint32_t)(wn * (NTOT / 4) + p * 16 + brow) * 64 + bkb;
    }

    float acc[MI][NI][4];
    #pragma unroll
    for (int i = 0; i < MI; i++)
        #pragma unroll
        for (int j = 0; j < NI; j++)
            #pragma unroll
            for (int q = 0; q < 4; q++) acc[i][j][q] = 0.f;

    // fp32-A path register staging
    const int arow_ld = tid / TPR;
    const int part = tid % TPR;
    const bool aok = (m0 + arow_ld) < M;
    float pfv[CPT];

    auto prefA = [&](int c) {
        if constexpr (sizeof(AT) == 4) {
            if (aok) {
                const float* ap = (const float*)A + (size_t)(m0 + arow_ld) * K + part * CPT;
                #pragma unroll
                for (int i = 0; i < CPT / 4; i++) {
                    float4 v = *(const float4*)(ap + c * 32 + i * 4);
                    pfv[4 * i] = v.x; pfv[4 * i + 1] = v.y;
                    pfv[4 * i + 2] = v.z; pfv[4 * i + 3] = v.w;
                }
            } else {
                #pragma unroll
                for (int i = 0; i < CPT; i++) pfv[i] = 0.f;
            }
        }
    };
    auto storeA = [&](int b) {
        if constexpr (sizeof(AT) == 4) {
            char* dst = sm + b * BUF;
            #pragma unroll
            for (int i = 0; i < CPT / 8; i++) {
                uint4 hv;
                __half2* hp = (__half2*)&hv;
                hp[0] = __floats2half2_rn(pfv[8 * i],     pfv[8 * i + 1]);
                hp[1] = __floats2half2_rn(pfv[8 * i + 2], pfv[8 * i + 3]);
                hp[2] = __floats2half2_rn(pfv[8 * i + 4], pfv[8 * i + 5]);
                hp[3] = __floats2half2_rn(pfv[8 * i + 6], pfv[8 * i + 7]);
                uint32_t so = SWZ64((uint32_t)(arow_ld * 64 + part * CPT * 2 + i * 16));
                *(uint4*)(dst + so) = hv;
            }
        }
    };
    // fp16-A path: cp.async direct (MTILE*4 slots of 16B)
    auto cpA = [&](int c, int b) {
        if constexpr (sizeof(AT) == 2) {
            uint32_t d = sb + b * BUF;
            constexpr int NS = (MTILE * 4) / 256;
            #pragma unroll
            for (int i = 0; i < NS; i++) {
                int v = tid + 256 * i;
                int row = v >> 2, u = v & 3;
                uint32_t so = SWZ64((uint32_t)(row * 64 + u * 16));
                size_t gi = (size_t)(m0 + row) * K + c * 32 + u * 8;
                uint32_t sz = ((m0 + row) < M) ? 16u : 0u;
                CPASYNC16Z(d + so, (const __half*)A + gi, sz);
            }
        }
    };
    auto cpB = [&](int c, int b) {
        uint32_t d = sb + b * BUF + ATERM;
        constexpr int NS = (NTOT * 4) / 256;
        #pragma unroll
        for (int i = 0; i < NS; i++) {
            int v = tid + 256 * i;
            int row = v >> 2, u = v & 3;
            uint32_t so = SWZ64((uint32_t)(row * 64 + u * 16));
            size_t gi = (size_t)row * K + c * 32 + u * 8;
            CPASYNC16(d + so, Bf + gi);
        }
    };
    auto compute = [&](int b) {
        uint32_t sA = sb + b * BUF;
        uint32_t sB = sA + ATERM;
        #pragma unroll
        for (int ks = 0; ks < 2; ks++) {
            const uint32_t ko = (uint32_t)(ks * 32);
            uint32_t bf[NI * 2], af[MI * 4];
            #pragma unroll
            for (int p = 0; p < NB; p++)
                LDSM4(&bf[p * 4], sB + SWZ64(bbase[p] + ko));
            #pragma unroll
            for (int mi = 0; mi < MI; mi++)
                LDSM4(&af[mi * 4], sA + SWZ64(abase[mi] + ko));
            #pragma unroll
            for (int mi = 0; mi < MI; mi++)
                #pragma unroll
                for (int ni = 0; ni < NI; ni++)
                    MMA_F16(acc[mi][ni], &af[mi * 4], &bf[ni * 2]);
        }
    };

    // prologue
    prefA(0);
    cpA(0, 0);
    cpB(0, 0);
    CPCOMMIT();
    storeA(0);
    CPWAIT0();
    __syncthreads();

    #pragma unroll
    for (int c = 0; c < 8; c++) {
        int nb = (c + 1) & 1;
        if (c < 7) {
            cpA(c + 1, nb);
            cpB(c + 1, nb);
            CPCOMMIT();
            prefA(c + 1);
        }
        compute(c & 1);
        if (c < 7) {
            storeA(nb);
            CPWAIT0();
        }
        __syncthreads();
    }

    // epilogue: scale by dis[row], convert to fp16, store
    const int g = lane >> 2;
    const int t = lane & 3;
    #pragma unroll
    for (int mi = 0; mi < MI; mi++) {
        int r0 = m0 + wm * (MTILE / 2) + mi * 16 + g;
        int r1 = r0 + 8;
        float s0 = (r0 < M) ? g_dis[r0] : 0.f;
        float s1 = (r1 < M) ? g_dis[r1] : 0.f;
        #pragma unroll
        for (int ni = 0; ni < NI; ni++) {
            int col = wn * (NTOT / 4) + ni * 8 + t * 2;
            if (r0 < M)
                *(__half2*)(C + (size_t)r0 * NTOT + col) =
                    __floats2half2_rn(acc[mi][ni][0] * s0, acc[mi][ni][1] * s0);
            if (r1 < M)
                *(__half2*)(C + (size_t)r1 * NTOT + col) =
                    __floats2half2_rn(acc[mi][ni][2] * s1, acc[mi][ni][3] * s1);
        }
    }
}

// ---------------- gather aggregation (fp16 input, fp32 accum, OT output) ----------------
template <int C8, typename OT>
__global__ __launch_bounds__(128) void agg_kernel_h(
    const __half* __restrict__ hs_, const float* __restrict__ bias_,
    OT* __restrict__ out_, int N)
{
    constexpr int NPB = 128 / C8;
    int node = blockIdx.x * NPB + threadIdx.x / C8;
    int c = threadIdx.x % C8;
    if (node >= N) return;
    const uint4* hs = (const uint4*)hs_;
    float dn = g_dis[node];
    int s0 = g_off[node], s1 = g_off[node + 1];

    float acc[8];
    {
        uint4 sv = hs[(size_t)node * C8 + c];
        const __half2* p = (const __half2*)&sv;
        #pragma unroll
        for (int q = 0; q < 4; q++) {
            float2 f = __half22float2(p[q]);
            acc[2 * q] = f.x; acc[2 * q + 1] = f.y;
        }
    }
    int j = s0;
    for (; j + 3 < s1; j += 4) {
        uint4 v0 = hs[(size_t)g_csr[j]     * C8 + c];
        uint4 v1 = hs[(size_t)g_csr[j + 1] * C8 + c];
        uint4 v2 = hs[(size_t)g_csr[j + 2] * C8 + c];
        uint4 v3 = hs[(size_t)g_csr[j + 3] * C8 + c];
        const __half2* p0 = (const __half2*)&v0;
        const __half2* p1 = (const __half2*)&v1;
        const __half2* p2 = (const __half2*)&v2;
        const __half2* p3 = (const __half2*)&v3;
        #pragma unroll
        for (int q = 0; q < 4; q++) {
            float2 f0 = __half22float2(p0[q]);
            float2 f1 = __half22float2(p1[q]);
            float2 f2 = __half22float2(p2[q]);
            float2 f3 = __half22float2(p3[q]);
            acc[2 * q]     += (f0.x + f1.x) + (f2.x + f3.x);
            acc[2 * q + 1] += (f0.y + f1.y) + (f2.y + f3.y);
        }
    }
    for (; j < s1; j++) {
        uint4 v = hs[(size_t)g_csr[j] * C8 + c];
        const __half2* p = (const __half2*)&v;
        #pragma unroll
        for (int q = 0; q < 4; q++) {
            float2 f = __half22float2(p[q]);
            acc[2 * q] += f.x; acc[2 * q + 1] += f.y;
        }
    }
    float4 b0 = ((const float4*)bias_)[c * 2];
    float4 b1 = ((const float4*)bias_)[c * 2 + 1];
    float o[8];
    o[0] = fmaxf(fmaf(acc[0], dn, b0.x), 0.f);
    o[1] = fmaxf(fmaf(acc[1], dn, b0.y), 0.f);
    o[2] = fmaxf(fmaf(acc[2], dn, b0.z), 0.f);
    o[3] = fmaxf(fmaf(acc[3], dn, b0.w), 0.f);
    o[4] = fmaxf(fmaf(acc[4], dn, b1.x), 0.f);
    o[5] = fmaxf(fmaf(acc[5], dn, b1.y), 0.f);
    o[6] = fmaxf(fmaf(acc[6], dn, b1.z), 0.f);
    o[7] = fmaxf(fmaf(acc[7], dn, b1.w), 0.f);
    if constexpr (sizeof(OT) == 2) {
        uint4 st;
        __half2* hp = (__half2*)&st;
        hp[0] = __floats2half2_rn(o[0], o[1]);
        hp[1] = __floats2half2_rn(o[2], o[3]);
        hp[2] = __floats2half2_rn(o[4], o[5]);
        hp[3] = __floats2half2_rn(o[6], o[7]);
        ((uint4*)out_)[(size_t)node * C8 + c] = st;
    } else {
        ((float4*)out_)[(size_t)node * C8 * 2 + c * 2]     = make_float4(o[0], o[1], o[2], o[3]);
        ((float4*)out_)[(size_t)node * C8 * 2 + c * 2 + 1] = make_float4(o[4], o[5], o[6], o[7]);
    }
}

// ---------------- global max pool per graph ----------------
__global__ void pool_kernel() {
    int g = blockIdx.x;
    int c = threadIdx.x;          // 0..127
    int a = g_gs[g], b = g_gs[g + 1];
    float m = -3.402823466e38f;
    int n = a;
    for (; n + 3 < b; n += 4) {
        float v0 = g_cx[(size_t)(n + 0) * HID2 + c];
        float v1 = g_cx[(size_t)(n + 1) * HID2 + c];
        float v2 = g_cx[(size_t)(n + 2) * HID2 + c];
        float v3 = g_cx[(size_t)(n + 3) * HID2 + c];
        m = fmaxf(m, fmaxf(fmaxf(v0, v1), fmaxf(v2, v3)));
    }
    for (; n < b; n++) m = fmaxf(m, g_cx[(size_t)n * HID2 + c]);
    g_px[g * HID2 + c] = m;
}

// ---------------- head ----------------
__global__ void head_kernel(const float* __restrict__ Wm, const float* __restrict__ bm,
                            float* __restrict__ out)
{
    int g = blockIdx.x;
    int d = threadIdx.x;          // 0..63
    float acc = bm[d];
    #pragma unroll 8
    for (int k = 0; k < HID2; k++)
        acc = fmaf(g_px[g * HID2 + k], Wm[k * N_DCS + d], acc);
    out[g * N_DCS + d] = acc;
}

// ---------------- launch ----------------
extern "C" void kernel_launch(void* const* d_in, const int* in_sizes, int n_in,
                              void* d_out, int out_size)
{
    const float* x     = (const float*)d_in[0];
    const int*   ei    = (const int*)  d_in[1];
    const int*   batch = (const int*)  d_in[2];
    const float* W1    = (const float*)d_in[3];
    const float* b1    = (const float*)d_in[4];
    const float* W2    = (const float*)d_in[5];
    const float* b2    = (const float*)d_in[6];
    const float* Wm    = (const float*)d_in[7];
    const float* bm    = (const float*)d_in[8];
    float* out = (float*)d_out;

    const int N = in_sizes[2];          // 50000
    const int E = in_sizes[1] / 2;      // 800000
    const int* src = ei;
    const int* dst = ei + E;

    __half *h1, *bx, *h2, *w1f, *w2f;
    float *cx;
    cudaGetSymbolAddress((void**)&h1, g_h1);
    cudaGetSymbolAddress((void**)&bx, g_bx);
    cudaGetSymbolAddress((void**)&h2, g_h2);
    cudaGetSymbolAddress((void**)&cx, g_cx);
    cudaGetSymbolAddress((void**)&w1f, g_w1f);
    cudaGetSymbolAddress((void**)&w2f, g_w2f);

    const int TB = 256;
    int gn = (N + TB - 1) / TB;
    int ge = (E + TB - 1) / TB;
    int nb = (N + 1023) / 1024;

    // GEMM1: CTA 64x256 (A read once), double-buffered chunk-32, 2 CTAs/SM
    const int SMEM1 = 2 * (64 * 64 + 256 * 64);    // 40960
    // GEMM2: CTA 64x128
    const int SMEM2 = 2 * (64 * 64 + 128 * 64);    // 24576
    cudaFuncSetAttribute((const void*)gemm_f16_kernel<HID, 64, float>,
                         cudaFuncAttributeMaxDynamicSharedMemorySize, SMEM1);
    cudaFuncSetAttribute((const void*)gemm_f16_kernel<HID2, 64, __half>,
                         cudaFuncAttributeMaxDynamicSharedMemorySize, SMEM2);

    // L1: prep (zero deg + pack weights fp16)
    prep_kernel<<<ZB + HID + HID2, 256>>>(W1, W2);
    // L2: degree histogram
    hist_kernel<<<ge, TB>>>(dst, E);
    // L3: block scan (+ dis fused)
    scan_block_kernel<<<nb, 1024>>>(N);
    // L4: layer-1 GEMM, fp16, full-N tile (profiled position)
    gemm_f16_kernel<HID, 64, float><<<(N + 63) / 64, 256, SMEM1>>>(x, w1f, h1, N);
    // L5-L7: CSR build (+ graph bounds fused into scan_add)
    scan_sums_kernel<<<1, 64>>>(nb, N);
    scan_add_kernel<<<gn, TB>>>(batch, N);
    scatter_kernel<<<ge, TB>>>(src, dst, E);
    // L8: layer-1 aggregation -> bx (fp16)
    agg_kernel_h<HID / 8, __half><<<(N * (HID / 8) + 127) / 128, 128>>>(h1, b1, bx, N);
    // L9: layer-2 GEMM (fp16, 64x128)
    gemm_f16_kernel<HID2, 64, __half><<<(N + 63) / 64, 256, SMEM2>>>(bx, w2f, h2, N);
    // L10: layer-2 aggregation -> cx (fp32)
    agg_kernel_h<HID2 / 8, float><<<(N * (HID2 / 8) + 127) / 128, 128>>>(h2, b2, cx, N);
    // L11-L12: pool + head
    pool_kernel<<<N_GRAPHS, HID2>>>();
    head_kernel<<<N_GRAPHS, N_DCS>>>(Wm, bm, out);
}

// round 17
// speedup vs baseline: 2.5125x; 1.1027x over previous
#include <cuda_runtime.h>
#include <cuda_fp16.h>
#include <cstdint>
#include <cstddef>

#define N_NODES 50000
#define N_EDGES 800000
#define N_GRAPHS 64
#define IN_C 256
#define HID 256
#define HID2 128
#define N_DCS 64

// ---------------- static device scratch ----------------
__device__ __half g_h1[(size_t)N_NODES * HID];          // (x@W1)*dis, fp16
__device__ __half g_bx[(size_t)N_NODES * HID];          // relu layer1 output fp16
__device__ __half g_h2[(size_t)N_NODES * HID2];         // (bx@W2)*dis, fp16
__device__ __half g_cx[(size_t)N_NODES * HID2];         // relu layer2 output fp16
__device__ __half g_w1f[HID * IN_C];                    // W1^T packed fp16
__device__ __half g_w2f[HID2 * HID];                    // W2^T packed fp16
__device__ float g_dis[N_NODES];
__device__ int   g_deg[N_NODES];
__device__ int   g_off[N_NODES + 1];
__device__ int   g_pos[N_NODES];
__device__ int   g_csr[N_EDGES];
__device__ int   g_bsum[64];
__device__ int   g_boff[64];
__device__ int   g_gs[N_GRAPHS + 1];

// ---------------- helpers ----------------
__device__ __forceinline__ uint32_t smem_u32(const void* p) {
    uint32_t a;
    asm("{ .reg .u64 t; cvta.to.shared.u64 t, %1; cvt.u32.u64 %0, t; }" : "=r"(a) : "l"(p));
    return a;
}
// SW64 swizzle for 64-byte rows
#define SWZ64(o) ((uint32_t)(o) ^ ((((uint32_t)(o)) >> 3) & 0x30u))

#define MMA_F16(d, a, b) \
    asm volatile("mma.sync.aligned.m16n8k16.row.col.f32.f16.f16.f32 " \
        "{%0,%1,%2,%3}, {%4,%5,%6,%7}, {%8,%9}, {%0,%1,%2,%3};" \
        : "+f"((d)[0]), "+f"((d)[1]), "+f"((d)[2]), "+f"((d)[3]) \
        : "r"((a)[0]), "r"((a)[1]), "r"((a)[2]), "r"((a)[3]), \
          "r"((b)[0]), "r"((b)[1]))

#define LDSM4(r, addr) \
    asm volatile("ldmatrix.sync.aligned.m8n8.x4.shared.b16 {%0,%1,%2,%3}, [%4];" \
        : "=r"((r)[0]), "=r"((r)[1]), "=r"((r)[2]), "=r"((r)[3]) : "r"(addr))

#define CPASYNC16(dst, src) \
    asm volatile("cp.async.cg.shared.global [%0], [%1], 16;" :: "r"(dst), "l"(src))
#define CPASYNC16Z(dst, src, sz) \
    asm volatile("cp.async.cg.shared.global [%0], [%1], 16, %2;" :: "r"(dst), "l"(src), "r"(sz))
#define CPCOMMIT() asm volatile("cp.async.commit_group;" ::: "memory")
#define CPWAIT0()  asm volatile("cp.async.wait_group 0;" ::: "memory")

// ---------------- fused prep: zero g_deg + pack W1/W2 transposed fp16 ----------------
#define ZB ((N_NODES + 255) / 256)
__global__ void prep_kernel(const float* __restrict__ W1, const float* __restrict__ W2) {
    int b = blockIdx.x;
    int t = threadIdx.x;                 // 256
    if (b < ZB) {
        int i = b * 256 + t;
        if (i < N_NODES) g_deg[i] = 0;
    } else if (b < ZB + HID) {
        int n = b - ZB;
        g_w1f[(size_t)n * 256 + t] = __float2half(W1[(size_t)t * HID + n]);
    } else {
        int n = b - ZB - HID;
        g_w2f[(size_t)n * 256 + t] = __float2half(W2[(size_t)t * HID2 + n]);
    }
}

// vectorized histogram: 4 edges per thread via int4
__global__ void hist_kernel(const int* __restrict__ dst, int e4, int e) {
    int i = blockIdx.x * blockDim.x + threadIdx.x;
    if (i < e4) {
        int4 d = ((const int4*)dst)[i];
        atomicAdd(&g_deg[d.x], 1);
        atomicAdd(&g_deg[d.y], 1);
        atomicAdd(&g_deg[d.z], 1);
        atomicAdd(&g_deg[d.w], 1);
    }
    if (i == 0) {
        for (int j = e4 * 4; j < e; j++) atomicAdd(&g_deg[dst[j]], 1);
    }
}

// stage 1: warp-shuffle scan + block sum; also computes dis = rsqrt(deg+1)
__global__ void scan_block_kernel(int n) {
    __shared__ int warpsum[32];
    int tid = threadIdx.x;               // 1024
    int i = blockIdx.x * 1024 + tid;
    int v = (i < n) ? g_deg[i] : 0;
    if (i < n) g_dis[i] = rsqrtf((float)v + 1.0f);
    int lane = tid & 31, w = tid >> 5;
    int s = v;
    #pragma unroll
    for (int d = 1; d < 32; d <<= 1) {
        int t = __shfl_up_sync(0xffffffffu, s, d);
        if (lane >= d) s += t;
    }
    if (lane == 31) warpsum[w] = s;
    __syncthreads();
    if (w == 0) {
        int ws = warpsum[lane];
        #pragma unroll
        for (int d = 1; d < 32; d <<= 1) {
            int t = __shfl_up_sync(0xffffffffu, ws, d);
            if (lane >= d) ws += t;
        }
        warpsum[lane] = ws;
    }
    __syncthreads();
    int base = (w > 0) ? warpsum[w - 1] : 0;
    int incl = base + s;
    if (i < n) g_off[i] = incl - v;       // exclusive
    if (tid == 1023) g_bsum[blockIdx.x] = incl;
}
__global__ void scan_sums_kernel(int nb, int n) {
    __shared__ int sh[64];
    int tid = threadIdx.x;
    int v = (tid < nb) ? g_bsum[tid] : 0;
    sh[tid] = v;
    __syncthreads();
    #pragma unroll
    for (int s = 1; s < 64; s <<= 1) {
        int t = (tid >= s) ? sh[tid - s] : 0;
        __syncthreads();
        sh[tid] += t;
        __syncthreads();
    }
    if (tid < nb) g_boff[tid] = sh[tid] - v;
    if (tid == nb - 1) g_off[n] = sh[tid];
}
// stage 3 + graph-bounds fused
__global__ void scan_add_kernel(const int* __restrict__ batch, int n) {
    int i = blockIdx.x * blockDim.x + threadIdx.x;
    if (i < n) {
        int o = g_off[i] + g_boff[i >> 10];
        g_off[i] = o;
        g_pos[i] = o;
        if (i == 0) {
            g_gs[N_GRAPHS] = n;
            g_gs[batch[0]] = 0;
        } else if (batch[i] != batch[i - 1]) {
            g_gs[batch[i]] = i;
        }
    }
}
// vectorized scatter: 4 edges per thread
__global__ void scatter_kernel(const int* __restrict__ src, const int* __restrict__ dst,
                               int e4, int e) {
    int i = blockIdx.x * blockDim.x + threadIdx.x;
    if (i < e4) {
        int4 s = ((const int4*)src)[i];
        int4 d = ((const int4*)dst)[i];
        g_csr[atomicAdd(&g_pos[d.x], 1)] = s.x;
        g_csr[atomicAdd(&g_pos[d.y], 1)] = s.y;
        g_csr[atomicAdd(&g_pos[d.z], 1)] = s.z;
        g_csr[atomicAdd(&g_pos[d.w], 1)] = s.w;
    }
    if (i == 0) {
        for (int j = e4 * 4; j < e; j++)
            g_csr[atomicAdd(&g_pos[dst[j]], 1)] = src[j];
    }
}

// ================ single-pass fp16 HMMA GEMM, full-N CTA tile, chunk-32 double buffer ================
// C[r][c] = (A[r,:]@B[c,:]^T) * g_dis[r], fp16 out.
// A [M,256] row-major: fp32 (LDG + convert + STS, register-staged) or fp16 (cp.async direct).
// Bf fp16 [NTOT,256] row-major (pre-transposed weights, cp.async; full NTOT per CTA -> A read once).
// CTA tile MTILE x NTOT, K=256 in 8 chunks of 32 (SW64-swizzled 64B SMEM rows).
// 8 warps (2 x 4); warp tile (MTILE/2) x (NTOT/4); m16n8k16; ldmatrix.x4 fragments.
template <int NTOT, int MTILE, typename AT>
__global__ __launch_bounds__(256, 2) void gemm_f16_kernel(
    const AT* __restrict__ A, const __half* __restrict__ Bf,
    __half* __restrict__ C, int M)
{
    constexpr int K = 256;
    constexpr int MI    = MTILE / 32;
    constexpr int NI    = NTOT / 32;
    constexpr int NB    = NI / 2;
    constexpr int ATERM = MTILE * 64;
    constexpr int BTERM = NTOT * 64;
    constexpr int BUF   = ATERM + BTERM;
    constexpr int TPR   = 256 / MTILE;
    constexpr int CPT   = 32 / TPR;

    extern __shared__ char sm[];
    const uint32_t sb = smem_u32(sm);

    const int tid = threadIdx.x;
    const int wid = tid >> 5;
    const int lane = tid & 31;
    const int wm = wid >> 2;
    const int wn = wid & 3;
    const int m0 = blockIdx.x * MTILE;

    uint32_t abase[MI], bbase[NB];
    {
        int arow = (lane & 7) + ((lane >> 3) & 1) * 8;
        int akb  = (lane >> 4) * 16;
        #pragma unroll
        for (int mi = 0; mi < MI; mi++)
            abase[mi] = (uint32_t)(wm * (MTILE / 2) + mi * 16 + arow) * 64 + akb;
        int brow = (lane & 7) + (lane >> 4) * 8;
        int bkb  = ((lane >> 3) & 1) * 16;
        #pragma unroll
        for (int p = 0; p < NB; p++)
            bbase[p] = (uint32_t)(wn * (NTOT / 4) + p * 16 + brow) * 64 + bkb;
    }

    float acc[MI][NI][4];
    #pragma unroll
    for (int i = 0; i < MI; i++)
        #pragma unroll
        for (int j = 0; j < NI; j++)
            #pragma unroll
            for (int q = 0; q < 4; q++) acc[i][j][q] = 0.f;

    const int arow_ld = tid / TPR;
    const int part = tid % TPR;
    const bool aok = (m0 + arow_ld) < M;
    float pfv[CPT];

    auto prefA = [&](int c) {
        if constexpr (sizeof(AT) == 4) {
            if (aok) {
                const float* ap = (const float*)A + (size_t)(m0 + arow_ld) * K + part * CPT;
                #pragma unroll
                for (int i = 0; i < CPT / 4; i++) {
                    float4 v = *(const float4*)(ap + c * 32 + i * 4);
                    pfv[4 * i] = v.x; pfv[4 * i + 1] = v.y;
                    pfv[4 * i + 2] = v.z; pfv[4 * i + 3] = v.w;
                }
            } else {
                #pragma unroll
                for (int i = 0; i < CPT; i++) pfv[i] = 0.f;
            }
        }
    };
    auto storeA = [&](int b) {
        if constexpr (sizeof(AT) == 4) {
            char* dst = sm + b * BUF;
            #pragma unroll
            for (int i = 0; i < CPT / 8; i++) {
                uint4 hv;
                __half2* hp = (__half2*)&hv;
                hp[0] = __floats2half2_rn(pfv[8 * i],     pfv[8 * i + 1]);
                hp[1] = __floats2half2_rn(pfv[8 * i + 2], pfv[8 * i + 3]);
                hp[2] = __floats2half2_rn(pfv[8 * i + 4], pfv[8 * i + 5]);
                hp[3] = __floats2half2_rn(pfv[8 * i + 6], pfv[8 * i + 7]);
                uint32_t so = SWZ64((uint32_t)(arow_ld * 64 + part * CPT * 2 + i * 16));
                *(uint4*)(dst + so) = hv;
            }
        }
    };
    auto cpA = [&](int c, int b) {
        if constexpr (sizeof(AT) == 2) {
            uint32_t d = sb + b * BUF;
            constexpr int NS = (MTILE * 4) / 256;
            #pragma unroll
            for (int i = 0; i < NS; i++) {
                int v = tid + 256 * i;
                int row = v >> 2, u = v & 3;
                uint32_t so = SWZ64((uint32_t)(row * 64 + u * 16));
                size_t gi = (size_t)(m0 + row) * K + c * 32 + u * 8;
                uint32_t sz = ((m0 + row) < M) ? 16u : 0u;
                CPASYNC16Z(d + so, (const __half*)A + gi, sz);
            }
        }
    };
    auto cpB = [&](int c, int b) {
        uint32_t d = sb + b * BUF + ATERM;
        constexpr int NS = (NTOT * 4) / 256;
        #pragma unroll
        for (int i = 0; i < NS; i++) {
            int v = tid + 256 * i;
            int row = v >> 2, u = v & 3;
            uint32_t so = SWZ64((uint32_t)(row * 64 + u * 16));
            size_t gi = (size_t)row * K + c * 32 + u * 8;
            CPASYNC16(d + so, Bf + gi);
        }
    };
    auto compute = [&](int b) {
        uint32_t sA = sb + b * BUF;
        uint32_t sB = sA + ATERM;
        #pragma unroll
        for (int ks = 0; ks < 2; ks++) {
            const uint32_t ko = (uint32_t)(ks * 32);
            uint32_t bf[NI * 2], af[MI * 4];
            #pragma unroll
            for (int p = 0; p < NB; p++)
                LDSM4(&bf[p * 4], sB + SWZ64(bbase[p] + ko));
            #pragma unroll
            for (int mi = 0; mi < MI; mi++)
                LDSM4(&af[mi * 4], sA + SWZ64(abase[mi] + ko));
            #pragma unroll
            for (int mi = 0; mi < MI; mi++)
                #pragma unroll
                for (int ni = 0; ni < NI; ni++)
                    MMA_F16(acc[mi][ni], &af[mi * 4], &bf[ni * 2]);
        }
    };

    prefA(0);
    cpA(0, 0);
    cpB(0, 0);
    CPCOMMIT();
    storeA(0);
    CPWAIT0();
    __syncthreads();

    #pragma unroll
    for (int c = 0; c < 8; c++) {
        int nb = (c + 1) & 1;
        if (c < 7) {
            cpA(c + 1, nb);
            cpB(c + 1, nb);
            CPCOMMIT();
            prefA(c + 1);
        }
        compute(c & 1);
        if (c < 7) {
            storeA(nb);
            CPWAIT0();
        }
        __syncthreads();
    }

    const int g = lane >> 2;
    const int t = lane & 3;
    #pragma unroll
    for (int mi = 0; mi < MI; mi++) {
        int r0 = m0 + wm * (MTILE / 2) + mi * 16 + g;
        int r1 = r0 + 8;
        float s0 = (r0 < M) ? g_dis[r0] : 0.f;
        float s1 = (r1 < M) ? g_dis[r1] : 0.f;
        #pragma unroll
        for (int ni = 0; ni < NI; ni++) {
            int col = wn * (NTOT / 4) + ni * 8 + t * 2;
            if (r0 < M)
                *(__half2*)(C + (size_t)r0 * NTOT + col) =
                    __floats2half2_rn(acc[mi][ni][0] * s0, acc[mi][ni][1] * s0);
            if (r1 < M)
                *(__half2*)(C + (size_t)r1 * NTOT + col) =
                    __floats2half2_rn(acc[mi][ni][2] * s1, acc[mi][ni][3] * s1);
        }
    }
}

// ---------------- gather aggregation (fp16 input, fp32 accum, OT output) ----------------
template <int C8, typename OT>
__global__ __launch_bounds__(128) void agg_kernel_h(
    const __half* __restrict__ hs_, const float* __restrict__ bias_,
    OT* __restrict__ out_, int N)
{
    constexpr int NPB = 128 / C8;
    int node = blockIdx.x * NPB + threadIdx.x / C8;
    int c = threadIdx.x % C8;
    if (node >= N) return;
    const uint4* hs = (const uint4*)hs_;
    float dn = g_dis[node];
    int s0 = g_off[node], s1 = g_off[node + 1];

    float acc[8];
    {
        uint4 sv = hs[(size_t)node * C8 + c];
        const __half2* p = (const __half2*)&sv;
        #pragma unroll
        for (int q = 0; q < 4; q++) {
            float2 f = __half22float2(p[q]);
            acc[2 * q] = f.x; acc[2 * q + 1] = f.y;
        }
    }
    int j = s0;
    for (; j + 3 < s1; j += 4) {
        uint4 v0 = hs[(size_t)g_csr[j]     * C8 + c];
        uint4 v1 = hs[(size_t)g_csr[j + 1] * C8 + c];
        uint4 v2 = hs[(size_t)g_csr[j + 2] * C8 + c];
        uint4 v3 = hs[(size_t)g_csr[j + 3] * C8 + c];
        const __half2* p0 = (const __half2*)&v0;
        const __half2* p1 = (const __half2*)&v1;
        const __half2* p2 = (const __half2*)&v2;
        const __half2* p3 = (const __half2*)&v3;
        #pragma unroll
        for (int q = 0; q < 4; q++) {
            float2 f0 = __half22float2(p0[q]);
            float2 f1 = __half22float2(p1[q]);
            float2 f2 = __half22float2(p2[q]);
            float2 f3 = __half22float2(p3[q]);
            acc[2 * q]     += (f0.x + f1.x) + (f2.x + f3.x);
            acc[2 * q + 1] += (f0.y + f1.y) + (f2.y + f3.y);
        }
    }
    for (; j < s1; j++) {
        uint4 v = hs[(size_t)g_csr[j] * C8 + c];
        const __half2* p = (const __half2*)&v;
        #pragma unroll
        for (int q = 0; q < 4; q++) {
            float2 f = __half22float2(p[q]);
            acc[2 * q] += f.x; acc[2 * q + 1] += f.y;
        }
    }
    float4 b0 = ((const float4*)bias_)[c * 2];
    float4 b1 = ((const float4*)bias_)[c * 2 + 1];
    float o[8];
    o[0] = fmaxf(fmaf(acc[0], dn, b0.x), 0.f);
    o[1] = fmaxf(fmaf(acc[1], dn, b0.y), 0.f);
    o[2] = fmaxf(fmaf(acc[2], dn, b0.z), 0.f);
    o[3] = fmaxf(fmaf(acc[3], dn, b0.w), 0.f);
    o[4] = fmaxf(fmaf(acc[4], dn, b1.x), 0.f);
    o[5] = fmaxf(fmaf(acc[5], dn, b1.y), 0.f);
    o[6] = fmaxf(fmaf(acc[6], dn, b1.z), 0.f);
    o[7] = fmaxf(fmaf(acc[7], dn, b1.w), 0.f);
    if constexpr (sizeof(OT) == 2) {
        uint4 st;
        __half2* hp = (__half2*)&st;
        hp[0] = __floats2half2_rn(o[0], o[1]);
        hp[1] = __floats2half2_rn(o[2], o[3]);
        hp[2] = __floats2half2_rn(o[4], o[5]);
        hp[3] = __floats2half2_rn(o[6], o[7]);
        ((uint4*)out_)[(size_t)node * C8 + c] = st;
    } else {
        ((float4*)out_)[(size_t)node * C8 * 2 + c * 2]     = make_float4(o[0], o[1], o[2], o[3]);
        ((float4*)out_)[(size_t)node * C8 * 2 + c * 2 + 1] = make_float4(o[4], o[5], o[6], o[7]);
    }
}

// ---------------- fused max-pool + head: one block per graph ----------------
// Pool reads cx fp16; px stays in SMEM; head GEMM computed in-block.
__global__ __launch_bounds__(128) void pool_head_kernel(
    const float* __restrict__ Wm, const float* __restrict__ bm, float* __restrict__ out)
{
    __shared__ float sred[8][HID2];      // per-group partial max
    __shared__ float spx[HID2];
    int g = blockIdx.x;
    int tid = threadIdx.x;               // 128
    int grp = tid >> 4;                  // 0..7
    int slot = tid & 15;                 // 0..15 (8 channels each)
    int a = g_gs[g], b = g_gs[g + 1];
    float m[8];
    #pragma unroll
    for (int q = 0; q < 8; q++) m[q] = -3.402823466e38f;
    const uint4* cx = (const uint4*)g_cx;          // 16 uint4-slots per row
    for (int n = a + grp; n < b; n += 8) {
        uint4 v = cx[(size_t)n * 16 + slot];
        const __half2* p = (const __half2*)&v;
        #pragma unroll
        for (int q = 0; q < 4; q++) {
            float2 f = __half22float2(p[q]);
            m[2 * q]     = fmaxf(m[2 * q], f.x);
            m[2 * q + 1] = fmaxf(m[2 * q + 1], f.y);
        }
    }
    #pragma unroll
    for (int q = 0; q < 8; q++) sred[grp][slot * 8 + q] = m[q];
    __syncthreads();
    float mx = sred[0][tid];
    #pragma unroll
    for (int r = 1; r < 8; r++) mx = fmaxf(mx, sred[r][tid]);
    spx[tid] = mx;
    __syncthreads();
    if (tid < N_DCS) {
        float acc = bm[tid];
        #pragma unroll 8
        for (int k = 0; k < HID2; k++)
            acc = fmaf(spx[k], Wm[k * N_DCS + tid], acc);
        out[g * N_DCS + tid] = acc;
    }
}

// ---------------- launch ----------------
extern "C" void kernel_launch(void* const* d_in, const int* in_sizes, int n_in,
                              void* d_out, int out_size)
{
    const float* x     = (const float*)d_in[0];
    const int*   ei    = (const int*)  d_in[1];
    const int*   batch = (const int*)  d_in[2];
    const float* W1    = (const float*)d_in[3];
    const float* b1    = (const float*)d_in[4];
    const float* W2    = (const float*)d_in[5];
    const float* b2    = (const float*)d_in[6];
    const float* Wm    = (const float*)d_in[7];
    const float* bm    = (const float*)d_in[8];
    float* out = (float*)d_out;

    const int N = in_sizes[2];          // 50000
    const int E = in_sizes[1] / 2;      // 800000
    const int* src = ei;
    const int* dst = ei + E;
    const int E4 = E / 4;

    __half *h1, *bx, *h2, *cx, *w1f, *w2f;
    cudaGetSymbolAddress((void**)&h1, g_h1);
    cudaGetSymbolAddress((void**)&bx, g_bx);
    cudaGetSymbolAddress((void**)&h2, g_h2);
    cudaGetSymbolAddress((void**)&cx, g_cx);
    cudaGetSymbolAddress((void**)&w1f, g_w1f);
    cudaGetSymbolAddress((void**)&w2f, g_w2f);

    const int TB = 256;
    int gn = (N + TB - 1) / TB;
    int ge4 = (E4 + TB - 1) / TB;
    int nb = (N + 1023) / 1024;

    // GEMM1: CTA 64x256 (A read once), double-buffered chunk-32, 2 CTAs/SM
    const int SMEM1 = 2 * (64 * 64 + 256 * 64);    // 40960
    // GEMM2: CTA 64x128
    const int SMEM2 = 2 * (64 * 64 + 128 * 64);    // 24576
    cudaFuncSetAttribute((const void*)gemm_f16_kernel<HID, 64, float>,
                         cudaFuncAttributeMaxDynamicSharedMemorySize, SMEM1);
    cudaFuncSetAttribute((const void*)gemm_f16_kernel<HID2, 64, __half>,
                         cudaFuncAttributeMaxDynamicSharedMemorySize, SMEM2);

    // L1: prep (zero deg + pack weights fp16)
    prep_kernel<<<ZB + HID + HID2, 256>>>(W1, W2);
    // L2: degree histogram (vectorized)
    hist_kernel<<<ge4, TB>>>(dst, E4, E);
    // L3: block scan (warp-shuffle, + dis fused)
    scan_block_kernel<<<nb, 1024>>>(N);
    // L4: layer-1 GEMM, fp16, full-N tile (profiled position)
    gemm_f16_kernel<HID, 64, float><<<(N + 63) / 64, 256, SMEM1>>>(x, w1f, h1, N);
    // L5-L7: CSR build (+ graph bounds fused into scan_add)
    scan_sums_kernel<<<1, 64>>>(nb, N);
    scan_add_kernel<<<gn, TB>>>(batch, N);
    scatter_kernel<<<ge4, TB>>>(src, dst, E4, E);
    // L8: layer-1 aggregation -> bx (fp16)
    agg_kernel_h<HID / 8, __half><<<(N * (HID / 8) + 127) / 128, 128>>>(h1, b1, bx, N);
    // L9: layer-2 GEMM (fp16, 64x128)
    gemm_f16_kernel<HID2, 64, __half><<<(N + 63) / 64, 256, SMEM2>>>(bx, w2f, h2, N);
    // L10: layer-2 aggregation -> cx (fp16)
    agg_kernel_h<HID2 / 8, __half><<<(N * (HID2 / 8) + 127) / 128, 128>>>(h2, b2, cx, N);
    // L11: fused pool + head
    pool_head_kernel<<<N_GRAPHS, 128>>>(Wm, bm, out);
}